// round 10
// baseline (speedup 1.0000x reference)
#include <cuda_runtime.h>
#include <cuda_fp16.h>
#include <cuda_bf16.h>
#include <math.h>

// Problem constants
#define Bq 2
#define Tq 2048
#define Cq 1024
#define Hq 16
#define Dq 64
#define NCHUNK 16
#define LCHUNK 128
#define BHq (Bq * Hq)       // 32
#define Mrows (Bq * Tq)     // 4096
#define EPSq 1e-6f

// ---------------- scratch (device globals: no allocs allowed) ----------------
__device__ float g_q[(size_t)BHq * Tq * Dq];
__device__ float g_k[(size_t)BHq * Tq * Dq];
__device__ float g_v[(size_t)BHq * Tq * Dq];
__device__ float g_Sc[(size_t)BHq * NCHUNK * Dq * Dq];
__device__ float g_Sp[(size_t)BHq * NCHUNK * Dq * Dq];
__device__ float g_zc[(size_t)BHq * NCHUNK * Dq];
__device__ float g_zp[(size_t)BHq * NCHUNK * Dq];

// fp16 buffers: A-side split hi/lo, B-side (weights) single fp16.
__device__ __align__(16) __half g_xh[(size_t)Mrows * Cq];
__device__ __align__(16) __half g_xl[(size_t)Mrows * Cq];
__device__ __align__(16) __half g_wa[(size_t)Cq * 3 * Cq];
__device__ __align__(16) __half g_wp[(size_t)Cq * Cq];
__device__ __align__(16) __half g_yh[(size_t)Mrows * Cq];
__device__ __align__(16) __half g_yl[(size_t)Mrows * Cq];

// ---------------- fp32 -> fp16 hi/lo split ------------------------------------
__global__ __launch_bounds__(256)
void split2_kernel(const float* __restrict__ in, __half* __restrict__ hi,
                   __half* __restrict__ lo, int n4)
{
    const int i = blockIdx.x * 256 + threadIdx.x;
    if (i >= n4) return;
    float4 v = ((const float4*)in)[i];
    __half h0 = __float2half(v.x), h1 = __float2half(v.y);
    __half h2 = __float2half(v.z), h3 = __float2half(v.w);
    __half l0 = __float2half(v.x - __half2float(h0));
    __half l1 = __float2half(v.y - __half2float(h1));
    __half l2 = __float2half(v.z - __half2float(h2));
    __half l3 = __float2half(v.w - __half2float(h3));
    uint2 uh, ul;
    uh.x = ((unsigned)__half_as_ushort(h1) << 16) | __half_as_ushort(h0);
    uh.y = ((unsigned)__half_as_ushort(h3) << 16) | __half_as_ushort(h2);
    ul.x = ((unsigned)__half_as_ushort(l1) << 16) | __half_as_ushort(l0);
    ul.y = ((unsigned)__half_as_ushort(l3) << 16) | __half_as_ushort(l2);
    ((uint2*)hi)[i] = uh;
    ((uint2*)lo)[i] = ul;
}

// ---------------- fp32 -> fp16 (hi only, for weights) -------------------------
__global__ __launch_bounds__(256)
void split1_kernel(const float* __restrict__ in, __half* __restrict__ hi, int n4)
{
    const int i = blockIdx.x * 256 + threadIdx.x;
    if (i >= n4) return;
    float4 v = ((const float4*)in)[i];
    __half h0 = __float2half(v.x), h1 = __float2half(v.y);
    __half h2 = __float2half(v.z), h3 = __float2half(v.w);
    uint2 uh;
    uh.x = ((unsigned)__half_as_ushort(h1) << 16) | __half_as_ushort(h0);
    uh.y = ((unsigned)__half_as_ushort(h3) << 16) | __half_as_ushort(h2);
    ((uint2*)hi)[i] = uh;
}

// ---------------- MMA helpers ------------------------------------------------
__device__ __forceinline__ void ldsm_x4(uint4& r, unsigned addr) {
    asm volatile("ldmatrix.sync.aligned.m8n8.x4.shared.b16 {%0,%1,%2,%3}, [%4];"
                 : "=r"(r.x), "=r"(r.y), "=r"(r.z), "=r"(r.w) : "r"(addr));
}
__device__ __forceinline__ void ldsm_x4t(uint4& r, unsigned addr) {
    asm volatile("ldmatrix.sync.aligned.m8n8.x4.trans.shared.b16 {%0,%1,%2,%3}, [%4];"
                 : "=r"(r.x), "=r"(r.y), "=r"(r.z), "=r"(r.w) : "r"(addr));
}
__device__ __forceinline__ void mma_fp16(float c[4], const uint4& a, unsigned b0, unsigned b1) {
    asm volatile("mma.sync.aligned.m16n8k16.row.col.f32.f16.f16.f32 "
                 "{%0,%1,%2,%3},{%4,%5,%6,%7},{%8,%9},{%0,%1,%2,%3};"
                 : "+f"(c[0]), "+f"(c[1]), "+f"(c[2]), "+f"(c[3])
                 : "r"(a.x), "r"(a.y), "r"(a.z), "r"(a.w), "r"(b0), "r"(b1));
}
__device__ __forceinline__ void cp16(unsigned s, const void* g) {
    asm volatile("cp.async.cg.shared.global [%0], [%1], 16;\n" :: "r"(s), "l"(g));
}

// ---------------- fp16-split tensor-core GEMM, 128x256 tile, K-step 64 -------
// C = (Ah+Al) @ B, fp32 accumulate. Warp tile 64x64 -> 96 B smem per MMA.
// Per stage: Ah 16K | Al 16K | B 32K = 64KB; 2 stages = 128KB.
#define STAGE_BYTES 65536
#define GEMM_SMEM   (2 * STAGE_BYTES)

template <int MODE>
__global__ __launch_bounds__(256, 1)
void mma_gemm(const __half* __restrict__ Ah, const __half* __restrict__ Al,
              const __half* __restrict__ Bm,
              float* __restrict__ Cout, int N)
{
    constexpr int K = 1024;
    constexpr int KSTEP = 64;
    constexpr int NITER = K / KSTEP;     // 16
    extern __shared__ char smem[];
    const unsigned sbase = (unsigned)__cvta_generic_to_shared(smem);

    const int tid = threadIdx.x;
    const int lane = tid & 31, wid = tid >> 5;
    const int warp_m = wid >> 2, warp_n = wid & 3;
    const int bm = blockIdx.y * 128, bn = blockIdx.x * 256;

    // ---- ldmatrix A read params: A tile 128 rows x 64 halves (8 granules/row)
    const int arow_l = warp_m * 64 + (lane & 15);
    const int aghalf = (lane >> 4) & 1;
    const unsigned aBase = (unsigned)(arow_l * 128);   // row*8 granules *16B
    const int arow7 = arow_l & 7;

    // ---- ldmatrix B read params: B tile 64 rows(k) x 256 halves (32 gran/row)
    const int bk_l = (lane & 7) + ((lane >> 3) & 1) * 8;
    const int gadd = lane >> 4;
    const int bk7 = bk_l & 7;
    int gsw[4];
#pragma unroll
    for (int jn = 0; jn < 4; jn++) {
        const int g = warp_n * 8 + jn * 2 + gadd;
        gsw[jn] = (g & 24) | ((g & 7) ^ bk7);
    }
    const unsigned bBase = (unsigned)(bk_l * 512);

    float acc[4][8][4];
#pragma unroll
    for (int mi = 0; mi < 4; mi++)
#pragma unroll
        for (int ni = 0; ni < 8; ni++)
#pragma unroll
            for (int r = 0; r < 4; r++) acc[mi][ni][r] = 0.f;

    auto issue = [&](int stage, int k0) {
        const unsigned st = sbase + stage * STAGE_BYTES;
#pragma unroll
        for (int j = 0; j < 4; j++) {
            const int f = tid + j * 256;           // 0..1023 A granules
            const int ar = f >> 3, ac = f & 7;
            const unsigned s = (unsigned)(ar * 8 + (ac ^ (ar & 7))) * 16;
            const size_t ao = (size_t)(bm + ar) * K + k0 + ac * 8;
            cp16(st + s,         Ah + ao);
            cp16(st + 16384 + s, Al + ao);
        }
#pragma unroll
        for (int j = 0; j < 8; j++) {
            const int f = tid + j * 256;           // 0..2047 B granules
            const int br = f >> 5, bg = f & 31;
            const unsigned s = (unsigned)(br * 32 + ((bg & 24) | ((bg & 7) ^ (br & 7)))) * 16;
            const size_t bo = (size_t)(k0 + br) * N + bn + bg * 8;
            cp16(st + 32768 + s, Bm + bo);
        }
        asm volatile("cp.async.commit_group;");
    };

    issue(0, 0);
    issue(1, KSTEP);

    for (int it = 0; it < NITER; it++) {
        asm volatile("cp.async.wait_group 1;");
        __syncthreads();
        const unsigned st = sbase + (it & 1) * STAGE_BYTES;
#pragma unroll
        for (int kx = 0; kx < 4; kx++) {
            uint4 Afh[4], Afl[4];
            const unsigned asw = (unsigned)(((kx * 2 + aghalf) ^ arow7) * 16);
#pragma unroll
            for (int mi = 0; mi < 4; mi++) {
                const unsigned a = st + aBase + mi * 2048 + asw;
                ldsm_x4(Afh[mi], a);
                ldsm_x4(Afl[mi], a + 16384);
            }
#pragma unroll
            for (int jn = 0; jn < 4; jn++) {
                uint4 Bf;
                ldsm_x4t(Bf, st + 32768 + bBase + kx * 8192 + (unsigned)(gsw[jn] * 16));
#pragma unroll
                for (int mi = 0; mi < 4; mi++) {
                    mma_fp16(acc[mi][2 * jn],     Afh[mi], Bf.x, Bf.y);
                    mma_fp16(acc[mi][2 * jn],     Afl[mi], Bf.x, Bf.y);
                    mma_fp16(acc[mi][2 * jn + 1], Afh[mi], Bf.z, Bf.w);
                    mma_fp16(acc[mi][2 * jn + 1], Afl[mi], Bf.z, Bf.w);
                }
            }
        }
        __syncthreads();
        if (it + 2 < NITER) issue(it & 1, (it + 2) * KSTEP);
        else asm volatile("cp.async.commit_group;");
    }

    // ---- epilogue
    const int rbase = bm + warp_m * 64 + (lane >> 2);
    const int cb = bn + warp_n * 64 + (lane & 3) * 2;
#pragma unroll
    for (int ni = 0; ni < 8; ni++) {
        const int c = cb + ni * 8;
        if (MODE == 2) {
#pragma unroll
            for (int mi = 0; mi < 4; mi++) {
#pragma unroll
                for (int half = 0; half < 2; half++) {
                    const int r = rbase + mi * 16 + half * 8;
                    *(float2*)&Cout[(size_t)r * N + c] =
                        make_float2(acc[mi][ni][half * 2], acc[mi][ni][half * 2 + 1]);
                }
            }
        } else {
            const int seg = c >> 10;
            const int cc = c & 1023;
            const int h = cc >> 6, d0 = cc & 63;
            float* dstb = (seg == 0) ? g_q : (seg == 1) ? g_k : g_v;
#pragma unroll
            for (int mi = 0; mi < 4; mi++) {
#pragma unroll
                for (int half = 0; half < 2; half++) {
                    const int r = rbase + mi * 16 + half * 8;
                    const int b = r >> 11, t = r & 2047;
                    float v0 = acc[mi][ni][half * 2], v1 = acc[mi][ni][half * 2 + 1];
                    if (seg < 2) {
                        v0 = (v0 > 0.f) ? (v0 + 1.f) : expf(v0);
                        v1 = (v1 > 0.f) ? (v1 + 1.f) : expf(v1);
                    }
                    const size_t idx = ((size_t)(b * Hq + h) * Tq + t) * Dq + d0;
                    *(float2*)&dstb[idx] = make_float2(v0, v1);
                }
            }
        }
    }
}

// ---------------- per-chunk K^T V sums + k sums ------------------------------
__global__ __launch_bounds__(256)
void chunk_sums_kernel()
{
    const int c  = blockIdx.x;
    const int bh = blockIdx.y;
    const int tid = threadIdx.x;
    const int i0 = (tid >> 4) << 2;
    const int j0 = (tid & 15) << 2;
    const bool zowner = ((tid & 15) == 0);

    const float* kb = g_k + ((size_t)bh * Tq + c * LCHUNK) * Dq;
    const float* vb = g_v + ((size_t)bh * Tq + c * LCHUNK) * Dq;

    __shared__ float ks[32][64];
    __shared__ float vs[32][64];

    float s[4][4];
#pragma unroll
    for (int a = 0; a < 4; a++)
#pragma unroll
        for (int b = 0; b < 4; b++) s[a][b] = 0.f;
    float z[4] = {0.f, 0.f, 0.f, 0.f};

    for (int t0 = 0; t0 < LCHUNK; t0 += 32) {
#pragma unroll
        for (int l = 0; l < 2; l++) {
            const int f = tid * 2 + l;
            const int rr = f >> 4, cc4 = (f & 15) << 2;
            *(float4*)&ks[rr][cc4] = *(const float4*)(kb + (size_t)(t0 + rr) * 64 + cc4);
            *(float4*)&vs[rr][cc4] = *(const float4*)(vb + (size_t)(t0 + rr) * 64 + cc4);
        }
        __syncthreads();
#pragma unroll 8
        for (int tt = 0; tt < 32; tt++) {
            float kr[4], vr[4];
            *(float4*)kr = *(const float4*)&ks[tt][i0];
            *(float4*)vr = *(const float4*)&vs[tt][j0];
#pragma unroll
            for (int a = 0; a < 4; a++)
#pragma unroll
                for (int b = 0; b < 4; b++)
                    s[a][b] = fmaf(kr[a], vr[b], s[a][b]);
            if (zowner) {
#pragma unroll
                for (int a = 0; a < 4; a++) z[a] += kr[a];
            }
        }
        __syncthreads();
    }

    float* Sp = g_Sc + ((size_t)bh * NCHUNK + c) * (Dq * Dq);
#pragma unroll
    for (int a = 0; a < 4; a++)
        *(float4*)&Sp[(i0 + a) * Dq + j0] = make_float4(s[a][0], s[a][1], s[a][2], s[a][3]);
    if (zowner) {
        float* zp = g_zc + ((size_t)bh * NCHUNK + c) * Dq;
#pragma unroll
        for (int a = 0; a < 4; a++) zp[i0 + a] = z[a];
    }
}

// ---------------- exclusive scan over chunks ---------------------------------
__global__ __launch_bounds__(256)
void scan_kernel()
{
    const int bh = blockIdx.x;
    const int tid = threadIdx.x;
    const size_t base = (size_t)bh * NCHUNK;

    float run[16];
#pragma unroll
    for (int l = 0; l < 16; l++) run[l] = 0.f;
    float zrun = 0.f;

    for (int c = 0; c < NCHUNK; c++) {
        float*       sp = g_Sp + (base + c) * (Dq * Dq) + tid * 16;
        const float* sc = g_Sc + (base + c) * (Dq * Dq) + tid * 16;
#pragma unroll
        for (int l = 0; l < 16; l++) {
            sp[l] = run[l];
            run[l] += sc[l];
        }
        if (tid < Dq) {
            g_zp[(base + c) * Dq + tid] = zrun;
            zrun += g_zc[(base + c) * Dq + tid];
        }
    }
}

// ---------------- per-chunk attention (half-chunk blocks) --------------------
#define AT_QS 0
#define AT_KS 4096
#define AT_A  12544
#define AT_S  20736
#define AT_Z  24832
#define AT_D  24896
#define AT_TOTAL 24960
#define AT_BYTES (AT_TOTAL * 4)   // 99840

__global__ __launch_bounds__(256)
void attn_kernel()
{
    extern __shared__ float sm[];
    float* Qs   = sm + AT_QS;
    float* Ks   = sm + AT_KS;
    float* Asm  = sm + AT_A;
    float* Ss   = sm + AT_S;
    float* zs   = sm + AT_Z;
    float* dens = sm + AT_D;

    const int c    = blockIdx.x >> 1;
    const int half = blockIdx.x & 1;
    const int bh   = blockIdx.y;
    const int tid  = threadIdx.x;
    const int r0   = half << 6;
    const int SEND = r0 + 64;
    const size_t coff = ((size_t)bh * Tq + c * LCHUNK) * Dq;
    const size_t qoff = coff + (size_t)r0 * Dq;
    const size_t soff = ((size_t)bh * NCHUNK + c) * (Dq * Dq);

    for (int f = tid; f < 1024; f += 256) {
        const int t = f >> 4, d4 = (f & 15) << 2;
        *(float4*)&Qs[t * 64 + d4] = *(const float4*)(g_q + qoff + (size_t)t * 64 + d4);
    }
    for (int f = tid; f < SEND * 16; f += 256) {
        const int d  = f & 63;
        const int t0 = (f >> 6) << 2;
        const float x0 = g_k[coff + (size_t)(t0 + 0) * 64 + d];
        const float x1 = g_k[coff + (size_t)(t0 + 1) * 64 + d];
        const float x2 = g_k[coff + (size_t)(t0 + 2) * 64 + d];
        const float x3 = g_k[coff + (size_t)(t0 + 3) * 64 + d];
        *(float4*)&Ks[d * 132 + t0] = make_float4(x0, x1, x2, x3);
    }
    for (int f = tid; f < 1024; f += 256)
        *(float4*)&Ss[f * 4] = *(const float4*)(g_Sp + soff + f * 4);
    if (tid < Dq) zs[tid] = g_zp[((size_t)bh * NCHUNK + c) * Dq + tid];
    __syncthreads();

    if (tid < 64) {
        float acc = EPSq;
#pragma unroll
        for (int d0 = 0; d0 < 64; d0 += 4) {
            float4 q4 = *(const float4*)&Qs[tid * 64 + d0];
            float4 z4 = *(const float4*)&zs[d0];
            acc += q4.x * z4.x + q4.y * z4.y + q4.z * z4.z + q4.w * z4.w;
        }
        dens[tid] = acc;
    }
    __syncthreads();

    const int trow = (tid >> 4) << 2;

    if (half) {
        const int tcol = (tid & 15) << 3;
        float a1[4][8];
#pragma unroll
        for (int i = 0; i < 4; i++)
#pragma unroll
            for (int j = 0; j < 8; j++) a1[i][j] = 0.f;
        for (int d0 = 0; d0 < 64; d0 += 4) {
            float kr[4][8];
#pragma unroll
            for (int l = 0; l < 4; l++) {
                *(float4*)(&kr[l][0]) = *(const float4*)&Ks[(d0 + l) * 132 + tcol];
                *(float4*)(&kr[l][4]) = *(const float4*)&Ks[(d0 + l) * 132 + tcol + 4];
            }
#pragma unroll
            for (int i = 0; i < 4; i++) {
                float4 q4 = *(const float4*)&Qs[(trow + i) * 64 + d0];
                const float qa[4] = {q4.x, q4.y, q4.z, q4.w};
#pragma unroll
                for (int l = 0; l < 4; l++)
#pragma unroll
                    for (int j = 0; j < 8; j++)
                        a1[i][j] = fmaf(qa[l], kr[l][j], a1[i][j]);
            }
        }
#pragma unroll
        for (int i = 0; i < 4; i++) {
            const int tl = trow + i;
            const int tg = r0 + tl;
            float rs = 0.f;
#pragma unroll
            for (int j = 0; j < 8; j++) {
                const int s = tcol + j;
                const float v = (s <= tg) ? a1[i][j] : 0.f;
                a1[i][j] = v;
                rs += v;
            }
            *(float4*)&Asm[tl * 128 + tcol]     = make_float4(a1[i][0], a1[i][1], a1[i][2], a1[i][3]);
            *(float4*)&Asm[tl * 128 + tcol + 4] = make_float4(a1[i][4], a1[i][5], a1[i][6], a1[i][7]);
            atomicAdd(&dens[tl], rs);
        }
    } else {
        const int tcol = (tid & 15) << 2;
        float a1[4][4];
#pragma unroll
        for (int i = 0; i < 4; i++)
#pragma unroll
            for (int j = 0; j < 4; j++) a1[i][j] = 0.f;
        for (int d0 = 0; d0 < 64; d0 += 4) {
            float kr[4][4];
#pragma unroll
            for (int l = 0; l < 4; l++)
                *(float4*)(&kr[l][0]) = *(const float4*)&Ks[(d0 + l) * 132 + tcol];
#pragma unroll
            for (int i = 0; i < 4; i++) {
                float4 q4 = *(const float4*)&Qs[(trow + i) * 64 + d0];
                const float qa[4] = {q4.x, q4.y, q4.z, q4.w};
#pragma unroll
                for (int l = 0; l < 4; l++)
#pragma unroll
                    for (int j = 0; j < 4; j++)
                        a1[i][j] = fmaf(qa[l], kr[l][j], a1[i][j]);
            }
        }
#pragma unroll
        for (int i = 0; i < 4; i++) {
            const int tl = trow + i;
            float rs = 0.f;
#pragma unroll
            for (int j = 0; j < 4; j++) {
                const int s = tcol + j;
                const float v = (s <= tl) ? a1[i][j] : 0.f;
                a1[i][j] = v;
                rs += v;
            }
            *(float4*)&Asm[tl * 128 + tcol] = make_float4(a1[i][0], a1[i][1], a1[i][2], a1[i][3]);
            atomicAdd(&dens[tl], rs);
        }
    }
    __syncthreads();

    for (int f = tid; f < SEND * 16; f += 256)
        *(float4*)&Ks[f * 4] = *(const float4*)(g_v + coff + f * 4);
    __syncthreads();

    const int jc = (tid & 15) << 2;
    float a2[4][4];
#pragma unroll
    for (int i = 0; i < 4; i++)
#pragma unroll
        for (int j = 0; j < 4; j++) a2[i][j] = 0.f;

    for (int s0 = 0; s0 < SEND; s0 += 4) {
        float vr[4][4];
#pragma unroll
        for (int l = 0; l < 4; l++)
            *(float4*)vr[l] = *(const float4*)&Ks[(s0 + l) * 64 + jc];
#pragma unroll
        for (int i = 0; i < 4; i++) {
            float4 av = *(const float4*)&Asm[(trow + i) * 128 + s0];
            const float aa[4] = {av.x, av.y, av.z, av.w};
#pragma unroll
            for (int l = 0; l < 4; l++)
#pragma unroll
                for (int j = 0; j < 4; j++)
                    a2[i][j] = fmaf(aa[l], vr[l][j], a2[i][j]);
        }
    }
    for (int d0 = 0; d0 < 64; d0 += 4) {
        float sr[4][4];
#pragma unroll
        for (int l = 0; l < 4; l++)
            *(float4*)sr[l] = *(const float4*)&Ss[(d0 + l) * 64 + jc];
#pragma unroll
        for (int i = 0; i < 4; i++) {
            float4 q4 = *(const float4*)&Qs[(trow + i) * 64 + d0];
            const float qa[4] = {q4.x, q4.y, q4.z, q4.w};
#pragma unroll
            for (int l = 0; l < 4; l++)
#pragma unroll
                for (int j = 0; j < 4; j++)
                    a2[i][j] = fmaf(qa[l], sr[l][j], a2[i][j]);
        }
    }

    const int b = bh >> 4, h = bh & 15;
#pragma unroll
    for (int i = 0; i < 4; i++) {
        const int tl = trow + i;
        const float inv = 1.0f / dens[tl];
        const size_t row = (size_t)b * Tq + c * LCHUNK + r0 + tl;
        const size_t idx = row * Cq + h * 64 + jc;
        float o0 = a2[i][0] * inv, o1 = a2[i][1] * inv;
        float o2 = a2[i][2] * inv, o3 = a2[i][3] * inv;
        __half h0 = __float2half(o0), h1 = __float2half(o1);
        __half h2 = __float2half(o2), h3 = __float2half(o3);
        __half l0 = __float2half(o0 - __half2float(h0));
        __half l1 = __float2half(o1 - __half2float(h1));
        __half l2 = __float2half(o2 - __half2float(h2));
        __half l3 = __float2half(o3 - __half2float(h3));
        uint2 uh, ul;
        uh.x = ((unsigned)__half_as_ushort(h1) << 16) | __half_as_ushort(h0);
        uh.y = ((unsigned)__half_as_ushort(h3) << 16) | __half_as_ushort(h2);
        ul.x = ((unsigned)__half_as_ushort(l1) << 16) | __half_as_ushort(l0);
        ul.y = ((unsigned)__half_as_ushort(l3) << 16) | __half_as_ushort(l2);
        *(uint2*)&g_yh[idx] = uh;
        *(uint2*)&g_yl[idx] = ul;
    }
}

// ---------------- launch -----------------------------------------------------
extern "C" void kernel_launch(void* const* d_in, const int* in_sizes, int n_in,
                              void* d_out, int out_size)
{
    const float* x      = (const float*)d_in[0];
    const float* w_attn = (const float*)d_in[1];
    const float* w_proj = (const float*)d_in[2];
    float* out = (float*)d_out;

    cudaFuncSetAttribute(attn_kernel, cudaFuncAttributeMaxDynamicSharedMemorySize, AT_BYTES);
    cudaFuncSetAttribute(mma_gemm<1>, cudaFuncAttributeMaxDynamicSharedMemorySize, GEMM_SMEM);
    cudaFuncSetAttribute(mma_gemm<2>, cudaFuncAttributeMaxDynamicSharedMemorySize, GEMM_SMEM);

    __half *xh, *xl, *wa, *wp, *yh, *yl;
    cudaGetSymbolAddress((void**)&xh, g_xh);
    cudaGetSymbolAddress((void**)&xl, g_xl);
    cudaGetSymbolAddress((void**)&wa, g_wa);
    cudaGetSymbolAddress((void**)&wp, g_wp);
    cudaGetSymbolAddress((void**)&yh, g_yh);
    cudaGetSymbolAddress((void**)&yl, g_yl);

    split2_kernel<<<(Mrows * Cq / 4 + 255) / 256, 256>>>(x, xh, xl, Mrows * Cq / 4);
    split1_kernel<<<(Cq * 3 * Cq / 4 + 255) / 256, 256>>>(w_attn, wa, Cq * 3 * Cq / 4);
    split1_kernel<<<(Cq * Cq / 4 + 255) / 256, 256>>>(w_proj, wp, Cq * Cq / 4);

    mma_gemm<1><<<dim3(3 * Cq / 256, Mrows / 128), 256, GEMM_SMEM>>>(
        xh, xl, wa, nullptr, 3 * Cq);
    chunk_sums_kernel<<<dim3(NCHUNK, BHq), 256>>>();
    scan_kernel<<<BHq, 256>>>();
    attn_kernel<<<dim3(2 * NCHUNK, BHq), 256, AT_BYTES>>>();
    mma_gemm<2><<<dim3(Cq / 256, Mrows / 128), 256, GEMM_SMEM>>>(
        yh, yl, wp, out, Cq);
}

// round 11
// speedup vs baseline: 1.5360x; 1.5360x over previous
#include <cuda_runtime.h>
#include <cuda_fp16.h>
#include <cuda_bf16.h>
#include <math.h>

// Problem constants
#define Bq 2
#define Tq 2048
#define Cq 1024
#define Hq 16
#define Dq 64
#define NCHUNK 16
#define LCHUNK 128
#define BHq (Bq * Hq)       // 32
#define Mrows (Bq * Tq)     // 4096
#define EPSq 1e-6f

// ---------------- scratch (device globals: no allocs allowed) ----------------
__device__ float g_q[(size_t)BHq * Tq * Dq];
__device__ float g_k[(size_t)BHq * Tq * Dq];
__device__ float g_v[(size_t)BHq * Tq * Dq];
__device__ float g_Sc[(size_t)BHq * NCHUNK * Dq * Dq];
__device__ float g_Sp[(size_t)BHq * NCHUNK * Dq * Dq];
__device__ float g_zc[(size_t)BHq * NCHUNK * Dq];
__device__ float g_zp[(size_t)BHq * NCHUNK * Dq];

// fp16 buffers: A-side split hi/lo, B-side (weights) single fp16.
__device__ __align__(16) __half g_xh[(size_t)Mrows * Cq];
__device__ __align__(16) __half g_xl[(size_t)Mrows * Cq];
__device__ __align__(16) __half g_wa[(size_t)Cq * 3 * Cq];
__device__ __align__(16) __half g_wp[(size_t)Cq * Cq];
__device__ __align__(16) __half g_yh[(size_t)Mrows * Cq];
__device__ __align__(16) __half g_yl[(size_t)Mrows * Cq];

// ---------------- fp32 -> fp16 hi/lo split ------------------------------------
__global__ __launch_bounds__(256)
void split2_kernel(const float* __restrict__ in, __half* __restrict__ hi,
                   __half* __restrict__ lo, int n4)
{
    const int i = blockIdx.x * 256 + threadIdx.x;
    if (i >= n4) return;
    float4 v = ((const float4*)in)[i];
    __half h0 = __float2half(v.x), h1 = __float2half(v.y);
    __half h2 = __float2half(v.z), h3 = __float2half(v.w);
    __half l0 = __float2half(v.x - __half2float(h0));
    __half l1 = __float2half(v.y - __half2float(h1));
    __half l2 = __float2half(v.z - __half2float(h2));
    __half l3 = __float2half(v.w - __half2float(h3));
    uint2 uh, ul;
    uh.x = ((unsigned)__half_as_ushort(h1) << 16) | __half_as_ushort(h0);
    uh.y = ((unsigned)__half_as_ushort(h3) << 16) | __half_as_ushort(h2);
    ul.x = ((unsigned)__half_as_ushort(l1) << 16) | __half_as_ushort(l0);
    ul.y = ((unsigned)__half_as_ushort(l3) << 16) | __half_as_ushort(l2);
    ((uint2*)hi)[i] = uh;
    ((uint2*)lo)[i] = ul;
}

// ---------------- fp32 -> fp16 (hi only, for weights) -------------------------
__global__ __launch_bounds__(256)
void split1_kernel(const float* __restrict__ in, __half* __restrict__ hi, int n4)
{
    const int i = blockIdx.x * 256 + threadIdx.x;
    if (i >= n4) return;
    float4 v = ((const float4*)in)[i];
    __half h0 = __float2half(v.x), h1 = __float2half(v.y);
    __half h2 = __float2half(v.z), h3 = __float2half(v.w);
    uint2 uh;
    uh.x = ((unsigned)__half_as_ushort(h1) << 16) | __half_as_ushort(h0);
    uh.y = ((unsigned)__half_as_ushort(h3) << 16) | __half_as_ushort(h2);
    ((uint2*)hi)[i] = uh;
}

// ---------------- MMA helpers ------------------------------------------------
__device__ __forceinline__ void ldsm_x4(uint4& r, unsigned addr) {
    asm volatile("ldmatrix.sync.aligned.m8n8.x4.shared.b16 {%0,%1,%2,%3}, [%4];"
                 : "=r"(r.x), "=r"(r.y), "=r"(r.z), "=r"(r.w) : "r"(addr));
}
__device__ __forceinline__ void ldsm_x4t(uint4& r, unsigned addr) {
    asm volatile("ldmatrix.sync.aligned.m8n8.x4.trans.shared.b16 {%0,%1,%2,%3}, [%4];"
                 : "=r"(r.x), "=r"(r.y), "=r"(r.z), "=r"(r.w) : "r"(addr));
}
__device__ __forceinline__ void mma_fp16(float c[4], const uint4& a, unsigned b0, unsigned b1) {
    asm volatile("mma.sync.aligned.m16n8k16.row.col.f32.f16.f16.f32 "
                 "{%0,%1,%2,%3},{%4,%5,%6,%7},{%8,%9},{%0,%1,%2,%3};"
                 : "+f"(c[0]), "+f"(c[1]), "+f"(c[2]), "+f"(c[3])
                 : "r"(a.x), "r"(a.y), "r"(a.z), "r"(a.w), "r"(b0), "r"(b1));
}
__device__ __forceinline__ void cp16(unsigned s, const void* g) {
    asm volatile("cp.async.cg.shared.global [%0], [%1], 16;\n" :: "r"(s), "l"(g));
}

// ---------------- fp16-split tensor-core GEMM, K-step 64 ---------------------
// C = (Ah+Al) @ B, fp32 accumulate. Block 128x128, warp tile 32x64 (4x2 warps)
// -> 128 B smem per MMA (vs 160 at 64x32), acc stays 64 regs (2 CTA/SM).
// Per stage: Ah 16K | Al 16K | B 16K = 48KB; 2 stages.
#define STAGE_BYTES 49152
#define GEMM_SMEM   (2 * STAGE_BYTES)

template <int MODE>
__global__ __launch_bounds__(256)
void mma_gemm(const __half* __restrict__ Ah, const __half* __restrict__ Al,
              const __half* __restrict__ Bm,
              float* __restrict__ Cout, int N)
{
    constexpr int K = 1024;
    constexpr int KSTEP = 64;
    constexpr int NITER = K / KSTEP;     // 16
    extern __shared__ char smem[];
    const unsigned sbase = (unsigned)__cvta_generic_to_shared(smem);

    const int tid = threadIdx.x;
    const int lane = tid & 31, wid = tid >> 5;
    const int warp_m = wid >> 1, warp_n = wid & 1;   // 4x2 warps, tile 32x64
    const int bm = blockIdx.y * 128, bn = blockIdx.x * 128;

    // A tile: 128 rows x 64 fp16 (8 granules/row), swizzle c ^ (row&7)
    // B tile:  64 rows x 128 fp16 (16 granules/row), swizzle (g&8)|((g&7)^(row&7))
    int sA[4], sB[4], gAr[4], gAc[4], gBr[4], gBc[4];
#pragma unroll
    for (int j = 0; j < 4; j++) {
        const int f = tid + j * 256;          // 0..1023
        const int ar = f >> 3, ac = f & 7;
        sA[j] = (ar * 8 + (ac ^ (ar & 7))) * 16;
        gAr[j] = ar; gAc[j] = ac * 8;
        const int br = f >> 4, bg = f & 15;
        sB[j] = (br * 16 + ((bg & 8) | ((bg & 7) ^ (br & 7)))) * 16;
        gBr[j] = br; gBc[j] = bg * 8;
    }

    // ---- ldmatrix A read offsets: rows warp_m*32 + mi*16
    const int arow_l = warp_m * 32 + (lane & 15);
    const int aghalf = (lane >> 4) & 1;
    int aOff[2][4];
#pragma unroll
    for (int mi = 0; mi < 2; mi++) {
        const int row = arow_l + mi * 16;
        const int rsw = row & 7;
#pragma unroll
        for (int kx = 0; kx < 4; kx++) {
            const int c = kx * 2 + aghalf;
            aOff[mi][kx] = (row * 8 + (c ^ rsw)) * 16;
        }
    }
    // ---- ldmatrix B read offsets: cols warp_n*64, 4 granule-pairs (jn)
    const int bk_l = (lane & 7) + ((lane >> 3) & 1) * 8;
    const int gadd = lane >> 4;
    const int klow = bk_l & 7;
    int bOff[4][4];
#pragma unroll
    for (int kx = 0; kx < 4; kx++) {
        const int k = kx * 16 + bk_l;
#pragma unroll
        for (int jn = 0; jn < 4; jn++) {
            const int g = warp_n * 8 + jn * 2 + gadd;
            bOff[kx][jn] = (k * 16 + ((g & 8) | ((g & 7) ^ klow))) * 16;
        }
    }

    float acc[2][8][4];
#pragma unroll
    for (int mi = 0; mi < 2; mi++)
#pragma unroll
        for (int ni = 0; ni < 8; ni++)
#pragma unroll
            for (int r = 0; r < 4; r++) acc[mi][ni][r] = 0.f;

    auto issue = [&](int stage, int k0) {
        const unsigned st = sbase + stage * STAGE_BYTES;
#pragma unroll
        for (int j = 0; j < 4; j++) {
            const size_t aoff = (size_t)(bm + gAr[j]) * K + k0 + gAc[j];
            const size_t boff = (size_t)(k0 + gBr[j]) * N + bn + gBc[j];
            cp16(st + sA[j],         Ah + aoff);
            cp16(st + 16384 + sA[j], Al + aoff);
            cp16(st + 32768 + sB[j], Bm + boff);
        }
        asm volatile("cp.async.commit_group;");
    };

    issue(0, 0);
    issue(1, KSTEP);

    for (int it = 0; it < NITER; it++) {
        asm volatile("cp.async.wait_group 1;");
        __syncthreads();
        const unsigned st = sbase + (it & 1) * STAGE_BYTES;
#pragma unroll
        for (int kx = 0; kx < 4; kx++) {
            uint4 Afh[2], Afl[2];
#pragma unroll
            for (int mi = 0; mi < 2; mi++) {
                ldsm_x4(Afh[mi], st + aOff[mi][kx]);
                ldsm_x4(Afl[mi], st + 16384 + aOff[mi][kx]);
            }
#pragma unroll
            for (int jn = 0; jn < 4; jn++) {
                uint4 Bf;
                ldsm_x4t(Bf, st + 32768 + bOff[kx][jn]);
#pragma unroll
                for (int mi = 0; mi < 2; mi++) {
                    mma_fp16(acc[mi][2 * jn],     Afh[mi], Bf.x, Bf.y);
                    mma_fp16(acc[mi][2 * jn],     Afl[mi], Bf.x, Bf.y);
                    mma_fp16(acc[mi][2 * jn + 1], Afh[mi], Bf.z, Bf.w);
                    mma_fp16(acc[mi][2 * jn + 1], Afl[mi], Bf.z, Bf.w);
                }
            }
        }
        __syncthreads();
        if (it + 2 < NITER) issue(it & 1, (it + 2) * KSTEP);
        else asm volatile("cp.async.commit_group;");
    }

    // ---- epilogue
    const int rbase = bm + warp_m * 32 + (lane >> 2);
    const int cb = bn + warp_n * 64 + (lane & 3) * 2;
#pragma unroll
    for (int ni = 0; ni < 8; ni++) {
        const int c = cb + ni * 8;
        if (MODE == 2) {
#pragma unroll
            for (int mi = 0; mi < 2; mi++) {
#pragma unroll
                for (int half = 0; half < 2; half++) {
                    const int r = rbase + mi * 16 + half * 8;
                    *(float2*)&Cout[(size_t)r * N + c] =
                        make_float2(acc[mi][ni][half * 2], acc[mi][ni][half * 2 + 1]);
                }
            }
        } else {
            const int seg = c >> 10;
            const int cc = c & 1023;
            const int h = cc >> 6, d0 = cc & 63;
            float* dstb = (seg == 0) ? g_q : (seg == 1) ? g_k : g_v;
#pragma unroll
            for (int mi = 0; mi < 2; mi++) {
#pragma unroll
                for (int half = 0; half < 2; half++) {
                    const int r = rbase + mi * 16 + half * 8;
                    const int b = r >> 11, t = r & 2047;
                    float v0 = acc[mi][ni][half * 2], v1 = acc[mi][ni][half * 2 + 1];
                    if (seg < 2) {
                        v0 = (v0 > 0.f) ? (v0 + 1.f) : expf(v0);
                        v1 = (v1 > 0.f) ? (v1 + 1.f) : expf(v1);
                    }
                    const size_t idx = ((size_t)(b * Hq + h) * Tq + t) * Dq + d0;
                    *(float2*)&dstb[idx] = make_float2(v0, v1);
                }
            }
        }
    }
}

// ---------------- per-chunk K^T V sums + k sums ------------------------------
__global__ __launch_bounds__(256)
void chunk_sums_kernel()
{
    const int c  = blockIdx.x;
    const int bh = blockIdx.y;
    const int tid = threadIdx.x;
    const int i0 = (tid >> 4) << 2;
    const int j0 = (tid & 15) << 2;
    const bool zowner = ((tid & 15) == 0);

    const float* kb = g_k + ((size_t)bh * Tq + c * LCHUNK) * Dq;
    const float* vb = g_v + ((size_t)bh * Tq + c * LCHUNK) * Dq;

    __shared__ float ks[32][64];
    __shared__ float vs[32][64];

    float s[4][4];
#pragma unroll
    for (int a = 0; a < 4; a++)
#pragma unroll
        for (int b = 0; b < 4; b++) s[a][b] = 0.f;
    float z[4] = {0.f, 0.f, 0.f, 0.f};

    for (int t0 = 0; t0 < LCHUNK; t0 += 32) {
#pragma unroll
        for (int l = 0; l < 2; l++) {
            const int f = tid * 2 + l;
            const int rr = f >> 4, cc4 = (f & 15) << 2;
            *(float4*)&ks[rr][cc4] = *(const float4*)(kb + (size_t)(t0 + rr) * 64 + cc4);
            *(float4*)&vs[rr][cc4] = *(const float4*)(vb + (size_t)(t0 + rr) * 64 + cc4);
        }
        __syncthreads();
#pragma unroll 8
        for (int tt = 0; tt < 32; tt++) {
            float kr[4], vr[4];
            *(float4*)kr = *(const float4*)&ks[tt][i0];
            *(float4*)vr = *(const float4*)&vs[tt][j0];
#pragma unroll
            for (int a = 0; a < 4; a++)
#pragma unroll
                for (int b = 0; b < 4; b++)
                    s[a][b] = fmaf(kr[a], vr[b], s[a][b]);
            if (zowner) {
#pragma unroll
                for (int a = 0; a < 4; a++) z[a] += kr[a];
            }
        }
        __syncthreads();
    }

    float* Sp = g_Sc + ((size_t)bh * NCHUNK + c) * (Dq * Dq);
#pragma unroll
    for (int a = 0; a < 4; a++)
        *(float4*)&Sp[(i0 + a) * Dq + j0] = make_float4(s[a][0], s[a][1], s[a][2], s[a][3]);
    if (zowner) {
        float* zp = g_zc + ((size_t)bh * NCHUNK + c) * Dq;
#pragma unroll
        for (int a = 0; a < 4; a++) zp[i0 + a] = z[a];
    }
}

// ---------------- exclusive scan over chunks ---------------------------------
__global__ __launch_bounds__(256)
void scan_kernel()
{
    const int bh = blockIdx.x;
    const int tid = threadIdx.x;
    const size_t base = (size_t)bh * NCHUNK;

    float run[16];
#pragma unroll
    for (int l = 0; l < 16; l++) run[l] = 0.f;
    float zrun = 0.f;

    for (int c = 0; c < NCHUNK; c++) {
        float*       sp = g_Sp + (base + c) * (Dq * Dq) + tid * 16;
        const float* sc = g_Sc + (base + c) * (Dq * Dq) + tid * 16;
#pragma unroll
        for (int l = 0; l < 16; l++) {
            sp[l] = run[l];
            run[l] += sc[l];
        }
        if (tid < Dq) {
            g_zp[(base + c) * Dq + tid] = zrun;
            zrun += g_zc[(base + c) * Dq + tid];
        }
    }
}

// ---------------- per-chunk attention (half-chunk blocks) --------------------
#define AT_QS 0
#define AT_KS 4096
#define AT_A  12544
#define AT_S  20736
#define AT_Z  24832
#define AT_D  24896
#define AT_TOTAL 24960
#define AT_BYTES (AT_TOTAL * 4)   // 99840

__global__ __launch_bounds__(256)
void attn_kernel()
{
    extern __shared__ float sm[];
    float* Qs   = sm + AT_QS;
    float* Ks   = sm + AT_KS;
    float* Asm  = sm + AT_A;
    float* Ss   = sm + AT_S;
    float* zs   = sm + AT_Z;
    float* dens = sm + AT_D;

    const int c    = blockIdx.x >> 1;
    const int half = blockIdx.x & 1;
    const int bh   = blockIdx.y;
    const int tid  = threadIdx.x;
    const int r0   = half << 6;
    const int SEND = r0 + 64;
    const size_t coff = ((size_t)bh * Tq + c * LCHUNK) * Dq;
    const size_t qoff = coff + (size_t)r0 * Dq;
    const size_t soff = ((size_t)bh * NCHUNK + c) * (Dq * Dq);

    for (int f = tid; f < 1024; f += 256) {
        const int t = f >> 4, d4 = (f & 15) << 2;
        *(float4*)&Qs[t * 64 + d4] = *(const float4*)(g_q + qoff + (size_t)t * 64 + d4);
    }
    for (int f = tid; f < SEND * 16; f += 256) {
        const int d  = f & 63;
        const int t0 = (f >> 6) << 2;
        const float x0 = g_k[coff + (size_t)(t0 + 0) * 64 + d];
        const float x1 = g_k[coff + (size_t)(t0 + 1) * 64 + d];
        const float x2 = g_k[coff + (size_t)(t0 + 2) * 64 + d];
        const float x3 = g_k[coff + (size_t)(t0 + 3) * 64 + d];
        *(float4*)&Ks[d * 132 + t0] = make_float4(x0, x1, x2, x3);
    }
    for (int f = tid; f < 1024; f += 256)
        *(float4*)&Ss[f * 4] = *(const float4*)(g_Sp + soff + f * 4);
    if (tid < Dq) zs[tid] = g_zp[((size_t)bh * NCHUNK + c) * Dq + tid];
    __syncthreads();

    if (tid < 64) {
        float acc = EPSq;
#pragma unroll
        for (int d0 = 0; d0 < 64; d0 += 4) {
            float4 q4 = *(const float4*)&Qs[tid * 64 + d0];
            float4 z4 = *(const float4*)&zs[d0];
            acc += q4.x * z4.x + q4.y * z4.y + q4.z * z4.z + q4.w * z4.w;
        }
        dens[tid] = acc;
    }
    __syncthreads();

    const int trow = (tid >> 4) << 2;

    if (half) {
        const int tcol = (tid & 15) << 3;
        float a1[4][8];
#pragma unroll
        for (int i = 0; i < 4; i++)
#pragma unroll
            for (int j = 0; j < 8; j++) a1[i][j] = 0.f;
        for (int d0 = 0; d0 < 64; d0 += 4) {
            float kr[4][8];
#pragma unroll
            for (int l = 0; l < 4; l++) {
                *(float4*)(&kr[l][0]) = *(const float4*)&Ks[(d0 + l) * 132 + tcol];
                *(float4*)(&kr[l][4]) = *(const float4*)&Ks[(d0 + l) * 132 + tcol + 4];
            }
#pragma unroll
            for (int i = 0; i < 4; i++) {
                float4 q4 = *(const float4*)&Qs[(trow + i) * 64 + d0];
                const float qa[4] = {q4.x, q4.y, q4.z, q4.w};
#pragma unroll
                for (int l = 0; l < 4; l++)
#pragma unroll
                    for (int j = 0; j < 8; j++)
                        a1[i][j] = fmaf(qa[l], kr[l][j], a1[i][j]);
            }
        }
#pragma unroll
        for (int i = 0; i < 4; i++) {
            const int tl = trow + i;
            const int tg = r0 + tl;
            float rs = 0.f;
#pragma unroll
            for (int j = 0; j < 8; j++) {
                const int s = tcol + j;
                const float v = (s <= tg) ? a1[i][j] : 0.f;
                a1[i][j] = v;
                rs += v;
            }
            *(float4*)&Asm[tl * 128 + tcol]     = make_float4(a1[i][0], a1[i][1], a1[i][2], a1[i][3]);
            *(float4*)&Asm[tl * 128 + tcol + 4] = make_float4(a1[i][4], a1[i][5], a1[i][6], a1[i][7]);
            atomicAdd(&dens[tl], rs);
        }
    } else {
        const int tcol = (tid & 15) << 2;
        float a1[4][4];
#pragma unroll
        for (int i = 0; i < 4; i++)
#pragma unroll
            for (int j = 0; j < 4; j++) a1[i][j] = 0.f;
        for (int d0 = 0; d0 < 64; d0 += 4) {
            float kr[4][4];
#pragma unroll
            for (int l = 0; l < 4; l++)
                *(float4*)(&kr[l][0]) = *(const float4*)&Ks[(d0 + l) * 132 + tcol];
#pragma unroll
            for (int i = 0; i < 4; i++) {
                float4 q4 = *(const float4*)&Qs[(trow + i) * 64 + d0];
                const float qa[4] = {q4.x, q4.y, q4.z, q4.w};
#pragma unroll
                for (int l = 0; l < 4; l++)
#pragma unroll
                    for (int j = 0; j < 4; j++)
                        a1[i][j] = fmaf(qa[l], kr[l][j], a1[i][j]);
            }
        }
#pragma unroll
        for (int i = 0; i < 4; i++) {
            const int tl = trow + i;
            float rs = 0.f;
#pragma unroll
            for (int j = 0; j < 4; j++) {
                const int s = tcol + j;
                const float v = (s <= tl) ? a1[i][j] : 0.f;
                a1[i][j] = v;
                rs += v;
            }
            *(float4*)&Asm[tl * 128 + tcol] = make_float4(a1[i][0], a1[i][1], a1[i][2], a1[i][3]);
            atomicAdd(&dens[tl], rs);
        }
    }
    __syncthreads();

    for (int f = tid; f < SEND * 16; f += 256)
        *(float4*)&Ks[f * 4] = *(const float4*)(g_v + coff + f * 4);
    __syncthreads();

    const int jc = (tid & 15) << 2;
    float a2[4][4];
#pragma unroll
    for (int i = 0; i < 4; i++)
#pragma unroll
        for (int j = 0; j < 4; j++) a2[i][j] = 0.f;

    for (int s0 = 0; s0 < SEND; s0 += 4) {
        float vr[4][4];
#pragma unroll
        for (int l = 0; l < 4; l++)
            *(float4*)vr[l] = *(const float4*)&Ks[(s0 + l) * 64 + jc];
#pragma unroll
        for (int i = 0; i < 4; i++) {
            float4 av = *(const float4*)&Asm[(trow + i) * 128 + s0];
            const float aa[4] = {av.x, av.y, av.z, av.w};
#pragma unroll
            for (int l = 0; l < 4; l++)
#pragma unroll
                for (int j = 0; j < 4; j++)
                    a2[i][j] = fmaf(aa[l], vr[l][j], a2[i][j]);
        }
    }
    for (int d0 = 0; d0 < 64; d0 += 4) {
        float sr[4][4];
#pragma unroll
        for (int l = 0; l < 4; l++)
            *(float4*)sr[l] = *(const float4*)&Ss[(d0 + l) * 64 + jc];
#pragma unroll
        for (int i = 0; i < 4; i++) {
            float4 q4 = *(const float4*)&Qs[(trow + i) * 64 + d0];
            const float qa[4] = {q4.x, q4.y, q4.z, q4.w};
#pragma unroll
            for (int l = 0; l < 4; l++)
#pragma unroll
                for (int j = 0; j < 4; j++)
                    a2[i][j] = fmaf(qa[l], sr[l][j], a2[i][j]);
        }
    }

    const int b = bh >> 4, h = bh & 15;
#pragma unroll
    for (int i = 0; i < 4; i++) {
        const int tl = trow + i;
        const float inv = 1.0f / dens[tl];
        const size_t row = (size_t)b * Tq + c * LCHUNK + r0 + tl;
        const size_t idx = row * Cq + h * 64 + jc;
        float o0 = a2[i][0] * inv, o1 = a2[i][1] * inv;
        float o2 = a2[i][2] * inv, o3 = a2[i][3] * inv;
        __half h0 = __float2half(o0), h1 = __float2half(o1);
        __half h2 = __float2half(o2), h3 = __float2half(o3);
        __half l0 = __float2half(o0 - __half2float(h0));
        __half l1 = __float2half(o1 - __half2float(h1));
        __half l2 = __float2half(o2 - __half2float(h2));
        __half l3 = __float2half(o3 - __half2float(h3));
        uint2 uh, ul;
        uh.x = ((unsigned)__half_as_ushort(h1) << 16) | __half_as_ushort(h0);
        uh.y = ((unsigned)__half_as_ushort(h3) << 16) | __half_as_ushort(h2);
        ul.x = ((unsigned)__half_as_ushort(l1) << 16) | __half_as_ushort(l0);
        ul.y = ((unsigned)__half_as_ushort(l3) << 16) | __half_as_ushort(l2);
        *(uint2*)&g_yh[idx] = uh;
        *(uint2*)&g_yl[idx] = ul;
    }
}

// ---------------- launch -----------------------------------------------------
extern "C" void kernel_launch(void* const* d_in, const int* in_sizes, int n_in,
                              void* d_out, int out_size)
{
    const float* x      = (const float*)d_in[0];
    const float* w_attn = (const float*)d_in[1];
    const float* w_proj = (const float*)d_in[2];
    float* out = (float*)d_out;

    cudaFuncSetAttribute(attn_kernel, cudaFuncAttributeMaxDynamicSharedMemorySize, AT_BYTES);
    cudaFuncSetAttribute(mma_gemm<1>, cudaFuncAttributeMaxDynamicSharedMemorySize, GEMM_SMEM);
    cudaFuncSetAttribute(mma_gemm<2>, cudaFuncAttributeMaxDynamicSharedMemorySize, GEMM_SMEM);

    __half *xh, *xl, *wa, *wp, *yh, *yl;
    cudaGetSymbolAddress((void**)&xh, g_xh);
    cudaGetSymbolAddress((void**)&xl, g_xl);
    cudaGetSymbolAddress((void**)&wa, g_wa);
    cudaGetSymbolAddress((void**)&wp, g_wp);
    cudaGetSymbolAddress((void**)&yh, g_yh);
    cudaGetSymbolAddress((void**)&yl, g_yl);

    split2_kernel<<<(Mrows * Cq / 4 + 255) / 256, 256>>>(x, xh, xl, Mrows * Cq / 4);
    split1_kernel<<<(Cq * 3 * Cq / 4 + 255) / 256, 256>>>(w_attn, wa, Cq * 3 * Cq / 4);
    split1_kernel<<<(Cq * Cq / 4 + 255) / 256, 256>>>(w_proj, wp, Cq * Cq / 4);

    mma_gemm<1><<<dim3(3 * Cq / 128, Mrows / 128), 256, GEMM_SMEM>>>(
        xh, xl, wa, nullptr, 3 * Cq);
    chunk_sums_kernel<<<dim3(NCHUNK, BHq), 256>>>();
    scan_kernel<<<BHq, 256>>>();
    attn_kernel<<<dim3(2 * NCHUNK, BHq), 256, AT_BYTES>>>();
    mma_gemm<2><<<dim3(Cq / 128, Mrows / 128), 256, GEMM_SMEM>>>(
        yh, yl, wp, out, Cq);
}

// round 12
// speedup vs baseline: 1.6416x; 1.0688x over previous
#include <cuda_runtime.h>
#include <cuda_fp16.h>
#include <cuda_bf16.h>
#include <math.h>

// Problem constants
#define Bq 2
#define Tq 2048
#define Cq 1024
#define Hq 16
#define Dq 64
#define NCHUNK 16
#define LCHUNK 128
#define BHq (Bq * Hq)       // 32
#define Mrows (Bq * Tq)     // 4096
#define EPSq 1e-6f

// ---------------- scratch (device globals: no allocs allowed) ----------------
__device__ float g_q[(size_t)BHq * Tq * Dq];
__device__ float g_k[(size_t)BHq * Tq * Dq];
__device__ float g_v[(size_t)BHq * Tq * Dq];
__device__ float g_Sc[(size_t)BHq * NCHUNK * Dq * Dq];
__device__ float g_Sp[(size_t)BHq * NCHUNK * Dq * Dq];
__device__ float g_zc[(size_t)BHq * NCHUNK * Dq];
__device__ float g_zp[(size_t)BHq * NCHUNK * Dq];

// fp16 buffers: A-side split hi/lo, B-side (weights) single fp16.
__device__ __align__(16) __half g_xh[(size_t)Mrows * Cq];
__device__ __align__(16) __half g_xl[(size_t)Mrows * Cq];
__device__ __align__(16) __half g_wa[(size_t)Cq * 3 * Cq];
__device__ __align__(16) __half g_wp[(size_t)Cq * Cq];
__device__ __align__(16) __half g_yh[(size_t)Mrows * Cq];
__device__ __align__(16) __half g_yl[(size_t)Mrows * Cq];

// ---------------- fused prep: x hi/lo split + wa/wp fp16 casts ---------------
// Region sizes in float4 units.
#define N4_X  (Mrows * Cq / 4)            // 1048576
#define N4_WA (Cq * 3 * Cq / 4)           // 786432
#define N4_WP (Cq * Cq / 4)               // 262144
#define N4_TOTAL (N4_X + N4_WA + N4_WP)   // 2097152

__global__ __launch_bounds__(256)
void prep_kernel(const float* __restrict__ x, const float* __restrict__ wa,
                 const float* __restrict__ wp)
{
    const int i = blockIdx.x * 256 + threadIdx.x;
    if (i < N4_X) {
        float4 v = ((const float4*)x)[i];
        __half h0 = __float2half(v.x), h1 = __float2half(v.y);
        __half h2 = __float2half(v.z), h3 = __float2half(v.w);
        __half l0 = __float2half(v.x - __half2float(h0));
        __half l1 = __float2half(v.y - __half2float(h1));
        __half l2 = __float2half(v.z - __half2float(h2));
        __half l3 = __float2half(v.w - __half2float(h3));
        uint2 uh, ul;
        uh.x = ((unsigned)__half_as_ushort(h1) << 16) | __half_as_ushort(h0);
        uh.y = ((unsigned)__half_as_ushort(h3) << 16) | __half_as_ushort(h2);
        ul.x = ((unsigned)__half_as_ushort(l1) << 16) | __half_as_ushort(l0);
        ul.y = ((unsigned)__half_as_ushort(l3) << 16) | __half_as_ushort(l2);
        ((uint2*)g_xh)[i] = uh;
        ((uint2*)g_xl)[i] = ul;
    } else if (i < N4_X + N4_WA) {
        const int j = i - N4_X;
        float4 v = ((const float4*)wa)[j];
        __half h0 = __float2half(v.x), h1 = __float2half(v.y);
        __half h2 = __float2half(v.z), h3 = __float2half(v.w);
        uint2 uh;
        uh.x = ((unsigned)__half_as_ushort(h1) << 16) | __half_as_ushort(h0);
        uh.y = ((unsigned)__half_as_ushort(h3) << 16) | __half_as_ushort(h2);
        ((uint2*)g_wa)[j] = uh;
    } else if (i < N4_TOTAL) {
        const int j = i - N4_X - N4_WA;
        float4 v = ((const float4*)wp)[j];
        __half h0 = __float2half(v.x), h1 = __float2half(v.y);
        __half h2 = __float2half(v.z), h3 = __float2half(v.w);
        uint2 uh;
        uh.x = ((unsigned)__half_as_ushort(h1) << 16) | __half_as_ushort(h0);
        uh.y = ((unsigned)__half_as_ushort(h3) << 16) | __half_as_ushort(h2);
        ((uint2*)g_wp)[j] = uh;
    }
}

// ---------------- MMA helpers ------------------------------------------------
__device__ __forceinline__ void ldsm_x4(uint4& r, unsigned addr) {
    asm volatile("ldmatrix.sync.aligned.m8n8.x4.shared.b16 {%0,%1,%2,%3}, [%4];"
                 : "=r"(r.x), "=r"(r.y), "=r"(r.z), "=r"(r.w) : "r"(addr));
}
__device__ __forceinline__ void ldsm_x4t(uint4& r, unsigned addr) {
    asm volatile("ldmatrix.sync.aligned.m8n8.x4.trans.shared.b16 {%0,%1,%2,%3}, [%4];"
                 : "=r"(r.x), "=r"(r.y), "=r"(r.z), "=r"(r.w) : "r"(addr));
}
__device__ __forceinline__ void mma_fp16(float c[4], const uint4& a, unsigned b0, unsigned b1) {
    asm volatile("mma.sync.aligned.m16n8k16.row.col.f32.f16.f16.f32 "
                 "{%0,%1,%2,%3},{%4,%5,%6,%7},{%8,%9},{%0,%1,%2,%3};"
                 : "+f"(c[0]), "+f"(c[1]), "+f"(c[2]), "+f"(c[3])
                 : "r"(a.x), "r"(a.y), "r"(a.z), "r"(a.w), "r"(b0), "r"(b1));
}
__device__ __forceinline__ void cp16(unsigned s, const void* g) {
    asm volatile("cp.async.cg.shared.global [%0], [%1], 16;\n" :: "r"(s), "l"(g));
}

// ---------------- fp16-split tensor-core GEMM, K-step 64 (round-9 proven) ----
// C = (Ah+Al) @ B, fp32 accumulate. Block 128x128, warp tile 64x32 (2x4 warps).
// Per stage: Ah 16K | Al 16K | B 16K = 48KB; 2 stages.
#define STAGE_BYTES 49152
#define GEMM_SMEM   (2 * STAGE_BYTES)

template <int MODE>
__global__ __launch_bounds__(256)
void mma_gemm(const __half* __restrict__ Ah, const __half* __restrict__ Al,
              const __half* __restrict__ Bm,
              float* __restrict__ Cout, int N)
{
    constexpr int K = 1024;
    constexpr int KSTEP = 64;
    constexpr int NITER = K / KSTEP;     // 16
    extern __shared__ char smem[];
    const unsigned sbase = (unsigned)__cvta_generic_to_shared(smem);

    const int tid = threadIdx.x;
    const int lane = tid & 31, wid = tid >> 5;
    const int warp_m = wid >> 2, warp_n = wid & 3;
    const int bm = blockIdx.y * 128, bn = blockIdx.x * 128;

    // A tile: 128 rows x 64 fp16 (8 granules/row), swizzle c ^ (row&7)
    // B tile:  64 rows x 128 fp16 (16 granules/row), swizzle (g&8)|((g&7)^(row&7))
    int sA[4], sB[4], gAr[4], gAc[4], gBr[4], gBc[4];
#pragma unroll
    for (int j = 0; j < 4; j++) {
        const int f = tid + j * 256;          // 0..1023
        const int ar = f >> 3, ac = f & 7;
        sA[j] = (ar * 8 + (ac ^ (ar & 7))) * 16;
        gAr[j] = ar; gAc[j] = ac * 8;
        const int br = f >> 4, bg = f & 15;
        sB[j] = (br * 16 + ((bg & 8) | ((bg & 7) ^ (br & 7)))) * 16;
        gBr[j] = br; gBc[j] = bg * 8;
    }

    const int arow_l = warp_m * 64 + (lane & 15);
    const int aghalf = (lane >> 4) & 1;
    int aOff[4][4];
#pragma unroll
    for (int mi = 0; mi < 4; mi++) {
        const int row = arow_l + mi * 16;
        const int rsw = row & 7;
#pragma unroll
        for (int kx = 0; kx < 4; kx++) {
            const int c = kx * 2 + aghalf;
            aOff[mi][kx] = (row * 8 + (c ^ rsw)) * 16;
        }
    }
    const int bk_l = (lane & 7) + ((lane >> 3) & 1) * 8;
    const int gadd = lane >> 4;
    const int klow = bk_l & 7;
    int bOff[4][2];
#pragma unroll
    for (int kx = 0; kx < 4; kx++) {
        const int k = kx * 16 + bk_l;
#pragma unroll
        for (int np = 0; np < 2; np++) {
            const int g = warp_n * 4 + np * 2 + gadd;
            bOff[kx][np] = (k * 16 + ((g & 8) | ((g & 7) ^ klow))) * 16;
        }
    }

    float acc[4][4][4];
#pragma unroll
    for (int mi = 0; mi < 4; mi++)
#pragma unroll
        for (int ni = 0; ni < 4; ni++)
#pragma unroll
            for (int r = 0; r < 4; r++) acc[mi][ni][r] = 0.f;

    auto issue = [&](int stage, int k0) {
        const unsigned st = sbase + stage * STAGE_BYTES;
#pragma unroll
        for (int j = 0; j < 4; j++) {
            const size_t aoff = (size_t)(bm + gAr[j]) * K + k0 + gAc[j];
            const size_t boff = (size_t)(k0 + gBr[j]) * N + bn + gBc[j];
            cp16(st + sA[j],         Ah + aoff);
            cp16(st + 16384 + sA[j], Al + aoff);
            cp16(st + 32768 + sB[j], Bm + boff);
        }
        asm volatile("cp.async.commit_group;");
    };

    issue(0, 0);
    issue(1, KSTEP);

    for (int it = 0; it < NITER; it++) {
        asm volatile("cp.async.wait_group 1;");
        __syncthreads();
        const unsigned st = sbase + (it & 1) * STAGE_BYTES;
#pragma unroll
        for (int kx = 0; kx < 4; kx++) {
            uint4 Afh[4], Afl[4], Bf[2];
#pragma unroll
            for (int mi = 0; mi < 4; mi++) {
                ldsm_x4(Afh[mi], st + aOff[mi][kx]);
                ldsm_x4(Afl[mi], st + 16384 + aOff[mi][kx]);
            }
#pragma unroll
            for (int np = 0; np < 2; np++)
                ldsm_x4t(Bf[np], st + 32768 + bOff[kx][np]);
#pragma unroll
            for (int mi = 0; mi < 4; mi++)
#pragma unroll
                for (int ni = 0; ni < 4; ni++) {
                    const int np = ni >> 1;
                    const unsigned b0 = (ni & 1) ? Bf[np].z : Bf[np].x;
                    const unsigned b1 = (ni & 1) ? Bf[np].w : Bf[np].y;
                    mma_fp16(acc[mi][ni], Afh[mi], b0, b1);
                    mma_fp16(acc[mi][ni], Afl[mi], b0, b1);
                }
        }
        __syncthreads();
        if (it + 2 < NITER) issue(it & 1, (it + 2) * KSTEP);
        else asm volatile("cp.async.commit_group;");
    }

    const int rbase = bm + warp_m * 64 + (lane >> 2);
    const int cbase = bn + warp_n * 32 + (lane & 3) * 2;
#pragma unroll
    for (int ni = 0; ni < 4; ni++) {
        const int c = cbase + ni * 8;
        if (MODE == 2) {
#pragma unroll
            for (int mi = 0; mi < 4; mi++) {
#pragma unroll
                for (int half = 0; half < 2; half++) {
                    const int r = rbase + mi * 16 + half * 8;
                    *(float2*)&Cout[(size_t)r * N + c] =
                        make_float2(acc[mi][ni][half * 2], acc[mi][ni][half * 2 + 1]);
                }
            }
        } else {
            const int seg = c >> 10;
            const int cc = c & 1023;
            const int h = cc >> 6, d0 = cc & 63;
            float* dstb = (seg == 0) ? g_q : (seg == 1) ? g_k : g_v;
#pragma unroll
            for (int mi = 0; mi < 4; mi++) {
#pragma unroll
                for (int half = 0; half < 2; half++) {
                    const int r = rbase + mi * 16 + half * 8;
                    const int b = r >> 11, t = r & 2047;
                    float v0 = acc[mi][ni][half * 2], v1 = acc[mi][ni][half * 2 + 1];
                    if (seg < 2) {
                        v0 = (v0 > 0.f) ? (v0 + 1.f) : expf(v0);
                        v1 = (v1 > 0.f) ? (v1 + 1.f) : expf(v1);
                    }
                    const size_t idx = ((size_t)(b * Hq + h) * Tq + t) * Dq + d0;
                    *(float2*)&dstb[idx] = make_float2(v0, v1);
                }
            }
        }
    }
}

// ---------------- per-chunk K^T V sums + k sums ------------------------------
__global__ __launch_bounds__(256)
void chunk_sums_kernel()
{
    const int c  = blockIdx.x;
    const int bh = blockIdx.y;
    const int tid = threadIdx.x;
    const int i0 = (tid >> 4) << 2;
    const int j0 = (tid & 15) << 2;
    const bool zowner = ((tid & 15) == 0);

    const float* kb = g_k + ((size_t)bh * Tq + c * LCHUNK) * Dq;
    const float* vb = g_v + ((size_t)bh * Tq + c * LCHUNK) * Dq;

    __shared__ float ks[32][64];
    __shared__ float vs[32][64];

    float s[4][4];
#pragma unroll
    for (int a = 0; a < 4; a++)
#pragma unroll
        for (int b = 0; b < 4; b++) s[a][b] = 0.f;
    float z[4] = {0.f, 0.f, 0.f, 0.f};

    for (int t0 = 0; t0 < LCHUNK; t0 += 32) {
#pragma unroll
        for (int l = 0; l < 2; l++) {
            const int f = tid * 2 + l;
            const int rr = f >> 4, cc4 = (f & 15) << 2;
            *(float4*)&ks[rr][cc4] = *(const float4*)(kb + (size_t)(t0 + rr) * 64 + cc4);
            *(float4*)&vs[rr][cc4] = *(const float4*)(vb + (size_t)(t0 + rr) * 64 + cc4);
        }
        __syncthreads();
#pragma unroll 8
        for (int tt = 0; tt < 32; tt++) {
            float kr[4], vr[4];
            *(float4*)kr = *(const float4*)&ks[tt][i0];
            *(float4*)vr = *(const float4*)&vs[tt][j0];
#pragma unroll
            for (int a = 0; a < 4; a++)
#pragma unroll
                for (int b = 0; b < 4; b++)
                    s[a][b] = fmaf(kr[a], vr[b], s[a][b]);
            if (zowner) {
#pragma unroll
                for (int a = 0; a < 4; a++) z[a] += kr[a];
            }
        }
        __syncthreads();
    }

    float* Sp = g_Sc + ((size_t)bh * NCHUNK + c) * (Dq * Dq);
#pragma unroll
    for (int a = 0; a < 4; a++)
        *(float4*)&Sp[(i0 + a) * Dq + j0] = make_float4(s[a][0], s[a][1], s[a][2], s[a][3]);
    if (zowner) {
        float* zp = g_zc + ((size_t)bh * NCHUNK + c) * Dq;
#pragma unroll
        for (int a = 0; a < 4; a++) zp[i0 + a] = z[a];
    }
}

// ---------------- exclusive scan over chunks ---------------------------------
__global__ __launch_bounds__(256)
void scan_kernel()
{
    const int bh = blockIdx.x;
    const int tid = threadIdx.x;
    const size_t base = (size_t)bh * NCHUNK;

    float run[16];
#pragma unroll
    for (int l = 0; l < 16; l++) run[l] = 0.f;
    float zrun = 0.f;

    for (int c = 0; c < NCHUNK; c++) {
        float*       sp = g_Sp + (base + c) * (Dq * Dq) + tid * 16;
        const float* sc = g_Sc + (base + c) * (Dq * Dq) + tid * 16;
#pragma unroll
        for (int l = 0; l < 16; l++) {
            sp[l] = run[l];
            run[l] += sc[l];
        }
        if (tid < Dq) {
            g_zp[(base + c) * Dq + tid] = zrun;
            zrun += g_zc[(base + c) * Dq + tid];
        }
    }
}

// ---------------- per-chunk attention (half-chunk blocks) --------------------
#define AT_QS 0
#define AT_KS 4096
#define AT_A  12544
#define AT_S  20736
#define AT_Z  24832
#define AT_D  24896
#define AT_TOTAL 24960
#define AT_BYTES (AT_TOTAL * 4)   // 99840

__global__ __launch_bounds__(256)
void attn_kernel()
{
    extern __shared__ float sm[];
    float* Qs   = sm + AT_QS;
    float* Ks   = sm + AT_KS;
    float* Asm  = sm + AT_A;
    float* Ss   = sm + AT_S;
    float* zs   = sm + AT_Z;
    float* dens = sm + AT_D;

    const int c    = blockIdx.x >> 1;
    const int half = blockIdx.x & 1;
    const int bh   = blockIdx.y;
    const int tid  = threadIdx.x;
    const int r0   = half << 6;
    const int SEND = r0 + 64;
    const size_t coff = ((size_t)bh * Tq + c * LCHUNK) * Dq;
    const size_t qoff = coff + (size_t)r0 * Dq;
    const size_t soff = ((size_t)bh * NCHUNK + c) * (Dq * Dq);

    for (int f = tid; f < 1024; f += 256) {
        const int t = f >> 4, d4 = (f & 15) << 2;
        *(float4*)&Qs[t * 64 + d4] = *(const float4*)(g_q + qoff + (size_t)t * 64 + d4);
    }
    for (int f = tid; f < SEND * 16; f += 256) {
        const int d  = f & 63;
        const int t0 = (f >> 6) << 2;
        const float x0 = g_k[coff + (size_t)(t0 + 0) * 64 + d];
        const float x1 = g_k[coff + (size_t)(t0 + 1) * 64 + d];
        const float x2 = g_k[coff + (size_t)(t0 + 2) * 64 + d];
        const float x3 = g_k[coff + (size_t)(t0 + 3) * 64 + d];
        *(float4*)&Ks[d * 132 + t0] = make_float4(x0, x1, x2, x3);
    }
    for (int f = tid; f < 1024; f += 256)
        *(float4*)&Ss[f * 4] = *(const float4*)(g_Sp + soff + f * 4);
    if (tid < Dq) zs[tid] = g_zp[((size_t)bh * NCHUNK + c) * Dq + tid];
    __syncthreads();

    if (tid < 64) {
        float acc = EPSq;
#pragma unroll
        for (int d0 = 0; d0 < 64; d0 += 4) {
            float4 q4 = *(const float4*)&Qs[tid * 64 + d0];
            float4 z4 = *(const float4*)&zs[d0];
            acc += q4.x * z4.x + q4.y * z4.y + q4.z * z4.z + q4.w * z4.w;
        }
        dens[tid] = acc;
    }
    __syncthreads();

    const int trow = (tid >> 4) << 2;

    if (half) {
        const int tcol = (tid & 15) << 3;
        float a1[4][8];
#pragma unroll
        for (int i = 0; i < 4; i++)
#pragma unroll
            for (int j = 0; j < 8; j++) a1[i][j] = 0.f;
        for (int d0 = 0; d0 < 64; d0 += 4) {
            float kr[4][8];
#pragma unroll
            for (int l = 0; l < 4; l++) {
                *(float4*)(&kr[l][0]) = *(const float4*)&Ks[(d0 + l) * 132 + tcol];
                *(float4*)(&kr[l][4]) = *(const float4*)&Ks[(d0 + l) * 132 + tcol + 4];
            }
#pragma unroll
            for (int i = 0; i < 4; i++) {
                float4 q4 = *(const float4*)&Qs[(trow + i) * 64 + d0];
                const float qa[4] = {q4.x, q4.y, q4.z, q4.w};
#pragma unroll
                for (int l = 0; l < 4; l++)
#pragma unroll
                    for (int j = 0; j < 8; j++)
                        a1[i][j] = fmaf(qa[l], kr[l][j], a1[i][j]);
            }
        }
#pragma unroll
        for (int i = 0; i < 4; i++) {
            const int tl = trow + i;
            const int tg = r0 + tl;
            float rs = 0.f;
#pragma unroll
            for (int j = 0; j < 8; j++) {
                const int s = tcol + j;
                const float v = (s <= tg) ? a1[i][j] : 0.f;
                a1[i][j] = v;
                rs += v;
            }
            *(float4*)&Asm[tl * 128 + tcol]     = make_float4(a1[i][0], a1[i][1], a1[i][2], a1[i][3]);
            *(float4*)&Asm[tl * 128 + tcol + 4] = make_float4(a1[i][4], a1[i][5], a1[i][6], a1[i][7]);
            atomicAdd(&dens[tl], rs);
        }
    } else {
        const int tcol = (tid & 15) << 2;
        float a1[4][4];
#pragma unroll
        for (int i = 0; i < 4; i++)
#pragma unroll
            for (int j = 0; j < 4; j++) a1[i][j] = 0.f;
        for (int d0 = 0; d0 < 64; d0 += 4) {
            float kr[4][4];
#pragma unroll
            for (int l = 0; l < 4; l++)
                *(float4*)(&kr[l][0]) = *(const float4*)&Ks[(d0 + l) * 132 + tcol];
#pragma unroll
            for (int i = 0; i < 4; i++) {
                float4 q4 = *(const float4*)&Qs[(trow + i) * 64 + d0];
                const float qa[4] = {q4.x, q4.y, q4.z, q4.w};
#pragma unroll
                for (int l = 0; l < 4; l++)
#pragma unroll
                    for (int j = 0; j < 4; j++)
                        a1[i][j] = fmaf(qa[l], kr[l][j], a1[i][j]);
            }
        }
#pragma unroll
        for (int i = 0; i < 4; i++) {
            const int tl = trow + i;
            float rs = 0.f;
#pragma unroll
            for (int j = 0; j < 4; j++) {
                const int s = tcol + j;
                const float v = (s <= tl) ? a1[i][j] : 0.f;
                a1[i][j] = v;
                rs += v;
            }
            *(float4*)&Asm[tl * 128 + tcol] = make_float4(a1[i][0], a1[i][1], a1[i][2], a1[i][3]);
            atomicAdd(&dens[tl], rs);
        }
    }
    __syncthreads();

    for (int f = tid; f < SEND * 16; f += 256)
        *(float4*)&Ks[f * 4] = *(const float4*)(g_v + coff + f * 4);
    __syncthreads();

    const int jc = (tid & 15) << 2;
    float a2[4][4];
#pragma unroll
    for (int i = 0; i < 4; i++)
#pragma unroll
        for (int j = 0; j < 4; j++) a2[i][j] = 0.f;

    for (int s0 = 0; s0 < SEND; s0 += 4) {
        float vr[4][4];
#pragma unroll
        for (int l = 0; l < 4; l++)
            *(float4*)vr[l] = *(const float4*)&Ks[(s0 + l) * 64 + jc];
#pragma unroll
        for (int i = 0; i < 4; i++) {
            float4 av = *(const float4*)&Asm[(trow + i) * 128 + s0];
            const float aa[4] = {av.x, av.y, av.z, av.w};
#pragma unroll
            for (int l = 0; l < 4; l++)
#pragma unroll
                for (int j = 0; j < 4; j++)
                    a2[i][j] = fmaf(aa[l], vr[l][j], a2[i][j]);
        }
    }
    for (int d0 = 0; d0 < 64; d0 += 4) {
        float sr[4][4];
#pragma unroll
        for (int l = 0; l < 4; l++)
            *(float4*)sr[l] = *(const float4*)&Ss[(d0 + l) * 64 + jc];
#pragma unroll
        for (int i = 0; i < 4; i++) {
            float4 q4 = *(const float4*)&Qs[(trow + i) * 64 + d0];
            const float qa[4] = {q4.x, q4.y, q4.z, q4.w};
#pragma unroll
            for (int l = 0; l < 4; l++)
#pragma unroll
                for (int j = 0; j < 4; j++)
                    a2[i][j] = fmaf(qa[l], sr[l][j], a2[i][j]);
        }
    }

    const int b = bh >> 4, h = bh & 15;
#pragma unroll
    for (int i = 0; i < 4; i++) {
        const int tl = trow + i;
        const float inv = 1.0f / dens[tl];
        const size_t row = (size_t)b * Tq + c * LCHUNK + r0 + tl;
        const size_t idx = row * Cq + h * 64 + jc;
        float o0 = a2[i][0] * inv, o1 = a2[i][1] * inv;
        float o2 = a2[i][2] * inv, o3 = a2[i][3] * inv;
        __half h0 = __float2half(o0), h1 = __float2half(o1);
        __half h2 = __float2half(o2), h3 = __float2half(o3);
        __half l0 = __float2half(o0 - __half2float(h0));
        __half l1 = __float2half(o1 - __half2float(h1));
        __half l2 = __float2half(o2 - __half2float(h2));
        __half l3 = __float2half(o3 - __half2float(h3));
        uint2 uh, ul;
        uh.x = ((unsigned)__half_as_ushort(h1) << 16) | __half_as_ushort(h0);
        uh.y = ((unsigned)__half_as_ushort(h3) << 16) | __half_as_ushort(h2);
        ul.x = ((unsigned)__half_as_ushort(l1) << 16) | __half_as_ushort(l0);
        ul.y = ((unsigned)__half_as_ushort(l3) << 16) | __half_as_ushort(l2);
        *(uint2*)&g_yh[idx] = uh;
        *(uint2*)&g_yl[idx] = ul;
    }
}

// ---------------- launch -----------------------------------------------------
extern "C" void kernel_launch(void* const* d_in, const int* in_sizes, int n_in,
                              void* d_out, int out_size)
{
    const float* x      = (const float*)d_in[0];
    const float* w_attn = (const float*)d_in[1];
    const float* w_proj = (const float*)d_in[2];
    float* out = (float*)d_out;

    cudaFuncSetAttribute(attn_kernel, cudaFuncAttributeMaxDynamicSharedMemorySize, AT_BYTES);
    cudaFuncSetAttribute(mma_gemm<1>, cudaFuncAttributeMaxDynamicSharedMemorySize, GEMM_SMEM);
    cudaFuncSetAttribute(mma_gemm<2>, cudaFuncAttributeMaxDynamicSharedMemorySize, GEMM_SMEM);

    __half *xh, *xl, *wa, *wp, *yh, *yl;
    cudaGetSymbolAddress((void**)&xh, g_xh);
    cudaGetSymbolAddress((void**)&xl, g_xl);
    cudaGetSymbolAddress((void**)&wa, g_wa);
    cudaGetSymbolAddress((void**)&wp, g_wp);
    cudaGetSymbolAddress((void**)&yh, g_yh);
    cudaGetSymbolAddress((void**)&yl, g_yl);

    prep_kernel<<<N4_TOTAL / 256, 256>>>(x, w_attn, w_proj);

    mma_gemm<1><<<dim3(3 * Cq / 128, Mrows / 128), 256, GEMM_SMEM>>>(
        xh, xl, wa, nullptr, 3 * Cq);
    chunk_sums_kernel<<<dim3(NCHUNK, BHq), 256>>>();
    scan_kernel<<<BHq, 256>>>();
    attn_kernel<<<dim3(2 * NCHUNK, BHq), 256, AT_BYTES>>>();
    mma_gemm<2><<<dim3(Cq / 128, Mrows / 128), 256, GEMM_SMEM>>>(
        yh, yl, wp, out, Cq);
}

// round 13
// speedup vs baseline: 1.8453x; 1.1241x over previous
#include <cuda_runtime.h>
#include <cuda_fp16.h>
#include <cuda_bf16.h>
#include <math.h>

// Problem constants
#define Bq 2
#define Tq 2048
#define Cq 1024
#define Hq 16
#define Dq 64
#define NCHUNK 16
#define LCHUNK 128
#define BHq (Bq * Hq)       // 32
#define Mrows (Bq * Tq)     // 4096
#define EPSq 1e-6f

// ---------------- scratch (device globals: no allocs allowed) ----------------
__device__ float g_q[(size_t)BHq * Tq * Dq];
__device__ float g_k[(size_t)BHq * Tq * Dq];
__device__ float g_v[(size_t)BHq * Tq * Dq];
__device__ float g_Sc[(size_t)BHq * NCHUNK * Dq * Dq];
__device__ float g_Sp[(size_t)BHq * NCHUNK * Dq * Dq];
__device__ float g_zc[(size_t)BHq * NCHUNK * Dq];
__device__ float g_zp[(size_t)BHq * NCHUNK * Dq];

// fp16 buffers: A-side split hi/lo, B-side (weights) single fp16.
__device__ __align__(16) __half g_xh[(size_t)Mrows * Cq];
__device__ __align__(16) __half g_xl[(size_t)Mrows * Cq];
__device__ __align__(16) __half g_wa[(size_t)Cq * 3 * Cq];
__device__ __align__(16) __half g_wp[(size_t)Cq * Cq];
__device__ __align__(16) __half g_yh[(size_t)Mrows * Cq];
__device__ __align__(16) __half g_yl[(size_t)Mrows * Cq];

// ---------------- fused prep: x hi/lo split + wa/wp fp16 casts ---------------
#define N4_X  (Mrows * Cq / 4)            // 1048576
#define N4_WA (Cq * 3 * Cq / 4)           // 786432
#define N4_WP (Cq * Cq / 4)               // 262144
#define N4_TOTAL (N4_X + N4_WA + N4_WP)   // 2097152

__global__ __launch_bounds__(256)
void prep_kernel(const float* __restrict__ x, const float* __restrict__ wa,
                 const float* __restrict__ wp)
{
    const int i = blockIdx.x * 256 + threadIdx.x;
    if (i < N4_X) {
        float4 v = ((const float4*)x)[i];
        __half h0 = __float2half(v.x), h1 = __float2half(v.y);
        __half h2 = __float2half(v.z), h3 = __float2half(v.w);
        __half l0 = __float2half(v.x - __half2float(h0));
        __half l1 = __float2half(v.y - __half2float(h1));
        __half l2 = __float2half(v.z - __half2float(h2));
        __half l3 = __float2half(v.w - __half2float(h3));
        uint2 uh, ul;
        uh.x = ((unsigned)__half_as_ushort(h1) << 16) | __half_as_ushort(h0);
        uh.y = ((unsigned)__half_as_ushort(h3) << 16) | __half_as_ushort(h2);
        ul.x = ((unsigned)__half_as_ushort(l1) << 16) | __half_as_ushort(l0);
        ul.y = ((unsigned)__half_as_ushort(l3) << 16) | __half_as_ushort(l2);
        ((uint2*)g_xh)[i] = uh;
        ((uint2*)g_xl)[i] = ul;
    } else if (i < N4_X + N4_WA) {
        const int j = i - N4_X;
        float4 v = ((const float4*)wa)[j];
        __half h0 = __float2half(v.x), h1 = __float2half(v.y);
        __half h2 = __float2half(v.z), h3 = __float2half(v.w);
        uint2 uh;
        uh.x = ((unsigned)__half_as_ushort(h1) << 16) | __half_as_ushort(h0);
        uh.y = ((unsigned)__half_as_ushort(h3) << 16) | __half_as_ushort(h2);
        ((uint2*)g_wa)[j] = uh;
    } else if (i < N4_TOTAL) {
        const int j = i - N4_X - N4_WA;
        float4 v = ((const float4*)wp)[j];
        __half h0 = __float2half(v.x), h1 = __float2half(v.y);
        __half h2 = __float2half(v.z), h3 = __float2half(v.w);
        uint2 uh;
        uh.x = ((unsigned)__half_as_ushort(h1) << 16) | __half_as_ushort(h0);
        uh.y = ((unsigned)__half_as_ushort(h3) << 16) | __half_as_ushort(h2);
        ((uint2*)g_wp)[j] = uh;
    }
}

// ---------------- MMA helpers ------------------------------------------------
__device__ __forceinline__ void ldsm_x4(uint4& r, unsigned addr) {
    asm volatile("ldmatrix.sync.aligned.m8n8.x4.shared.b16 {%0,%1,%2,%3}, [%4];"
                 : "=r"(r.x), "=r"(r.y), "=r"(r.z), "=r"(r.w) : "r"(addr));
}
__device__ __forceinline__ void ldsm_x4t(uint4& r, unsigned addr) {
    asm volatile("ldmatrix.sync.aligned.m8n8.x4.trans.shared.b16 {%0,%1,%2,%3}, [%4];"
                 : "=r"(r.x), "=r"(r.y), "=r"(r.z), "=r"(r.w) : "r"(addr));
}
__device__ __forceinline__ void mma_fp16(float c[4], const uint4& a, unsigned b0, unsigned b1) {
    asm volatile("mma.sync.aligned.m16n8k16.row.col.f32.f16.f16.f32 "
                 "{%0,%1,%2,%3},{%4,%5,%6,%7},{%8,%9},{%0,%1,%2,%3};"
                 : "+f"(c[0]), "+f"(c[1]), "+f"(c[2]), "+f"(c[3])
                 : "r"(a.x), "r"(a.y), "r"(a.z), "r"(a.w), "r"(b0), "r"(b1));
}
__device__ __forceinline__ void cp16(unsigned s, const void* g) {
    asm volatile("cp.async.cg.shared.global [%0], [%1], 16;\n" :: "r"(s), "l"(g));
}

// ---------------- fp16-split tensor-core GEMM, K-step 64 (round-9 proven) ----
#define STAGE_BYTES 49152
#define GEMM_SMEM   (2 * STAGE_BYTES)

template <int MODE>
__global__ __launch_bounds__(256)
void mma_gemm(const __half* __restrict__ Ah, const __half* __restrict__ Al,
              const __half* __restrict__ Bm,
              float* __restrict__ Cout, int N)
{
    constexpr int K = 1024;
    constexpr int KSTEP = 64;
    constexpr int NITER = K / KSTEP;     // 16
    extern __shared__ char smem[];
    const unsigned sbase = (unsigned)__cvta_generic_to_shared(smem);

    const int tid = threadIdx.x;
    const int lane = tid & 31, wid = tid >> 5;
    const int warp_m = wid >> 2, warp_n = wid & 3;
    const int bm = blockIdx.y * 128, bn = blockIdx.x * 128;

    int sA[4], sB[4], gAr[4], gAc[4], gBr[4], gBc[4];
#pragma unroll
    for (int j = 0; j < 4; j++) {
        const int f = tid + j * 256;          // 0..1023
        const int ar = f >> 3, ac = f & 7;
        sA[j] = (ar * 8 + (ac ^ (ar & 7))) * 16;
        gAr[j] = ar; gAc[j] = ac * 8;
        const int br = f >> 4, bg = f & 15;
        sB[j] = (br * 16 + ((bg & 8) | ((bg & 7) ^ (br & 7)))) * 16;
        gBr[j] = br; gBc[j] = bg * 8;
    }

    const int arow_l = warp_m * 64 + (lane & 15);
    const int aghalf = (lane >> 4) & 1;
    int aOff[4][4];
#pragma unroll
    for (int mi = 0; mi < 4; mi++) {
        const int row = arow_l + mi * 16;
        const int rsw = row & 7;
#pragma unroll
        for (int kx = 0; kx < 4; kx++) {
            const int c = kx * 2 + aghalf;
            aOff[mi][kx] = (row * 8 + (c ^ rsw)) * 16;
        }
    }
    const int bk_l = (lane & 7) + ((lane >> 3) & 1) * 8;
    const int gadd = lane >> 4;
    const int klow = bk_l & 7;
    int bOff[4][2];
#pragma unroll
    for (int kx = 0; kx < 4; kx++) {
        const int k = kx * 16 + bk_l;
#pragma unroll
        for (int np = 0; np < 2; np++) {
            const int g = warp_n * 4 + np * 2 + gadd;
            bOff[kx][np] = (k * 16 + ((g & 8) | ((g & 7) ^ klow))) * 16;
        }
    }

    float acc[4][4][4];
#pragma unroll
    for (int mi = 0; mi < 4; mi++)
#pragma unroll
        for (int ni = 0; ni < 4; ni++)
#pragma unroll
            for (int r = 0; r < 4; r++) acc[mi][ni][r] = 0.f;

    auto issue = [&](int stage, int k0) {
        const unsigned st = sbase + stage * STAGE_BYTES;
#pragma unroll
        for (int j = 0; j < 4; j++) {
            const size_t aoff = (size_t)(bm + gAr[j]) * K + k0 + gAc[j];
            const size_t boff = (size_t)(k0 + gBr[j]) * N + bn + gBc[j];
            cp16(st + sA[j],         Ah + aoff);
            cp16(st + 16384 + sA[j], Al + aoff);
            cp16(st + 32768 + sB[j], Bm + boff);
        }
        asm volatile("cp.async.commit_group;");
    };

    issue(0, 0);
    issue(1, KSTEP);

    for (int it = 0; it < NITER; it++) {
        asm volatile("cp.async.wait_group 1;");
        __syncthreads();
        const unsigned st = sbase + (it & 1) * STAGE_BYTES;
#pragma unroll
        for (int kx = 0; kx < 4; kx++) {
            uint4 Afh[4], Afl[4], Bf[2];
#pragma unroll
            for (int mi = 0; mi < 4; mi++) {
                ldsm_x4(Afh[mi], st + aOff[mi][kx]);
                ldsm_x4(Afl[mi], st + 16384 + aOff[mi][kx]);
            }
#pragma unroll
            for (int np = 0; np < 2; np++)
                ldsm_x4t(Bf[np], st + 32768 + bOff[kx][np]);
#pragma unroll
            for (int mi = 0; mi < 4; mi++)
#pragma unroll
                for (int ni = 0; ni < 4; ni++) {
                    const int np = ni >> 1;
                    const unsigned b0 = (ni & 1) ? Bf[np].z : Bf[np].x;
                    const unsigned b1 = (ni & 1) ? Bf[np].w : Bf[np].y;
                    mma_fp16(acc[mi][ni], Afh[mi], b0, b1);
                    mma_fp16(acc[mi][ni], Afl[mi], b0, b1);
                }
        }
        __syncthreads();
        if (it + 2 < NITER) issue(it & 1, (it + 2) * KSTEP);
        else asm volatile("cp.async.commit_group;");
    }

    const int rbase = bm + warp_m * 64 + (lane >> 2);
    const int cbase = bn + warp_n * 32 + (lane & 3) * 2;
#pragma unroll
    for (int ni = 0; ni < 4; ni++) {
        const int c = cbase + ni * 8;
        if (MODE == 2) {
#pragma unroll
            for (int mi = 0; mi < 4; mi++) {
#pragma unroll
                for (int half = 0; half < 2; half++) {
                    const int r = rbase + mi * 16 + half * 8;
                    *(float2*)&Cout[(size_t)r * N + c] =
                        make_float2(acc[mi][ni][half * 2], acc[mi][ni][half * 2 + 1]);
                }
            }
        } else {
            const int seg = c >> 10;
            const int cc = c & 1023;
            const int h = cc >> 6, d0 = cc & 63;
            float* dstb = (seg == 0) ? g_q : (seg == 1) ? g_k : g_v;
#pragma unroll
            for (int mi = 0; mi < 4; mi++) {
#pragma unroll
                for (int half = 0; half < 2; half++) {
                    const int r = rbase + mi * 16 + half * 8;
                    const int b = r >> 11, t = r & 2047;
                    float v0 = acc[mi][ni][half * 2], v1 = acc[mi][ni][half * 2 + 1];
                    if (seg < 2) {
                        v0 = (v0 > 0.f) ? (v0 + 1.f) : expf(v0);
                        v1 = (v1 > 0.f) ? (v1 + 1.f) : expf(v1);
                    }
                    const size_t idx = ((size_t)(b * Hq + h) * Tq + t) * Dq + d0;
                    *(float2*)&dstb[idx] = make_float2(v0, v1);
                }
            }
        }
    }
}

// ---------------- per-chunk K^T V sums + k sums ------------------------------
__global__ __launch_bounds__(256)
void chunk_sums_kernel()
{
    const int c  = blockIdx.x;
    const int bh = blockIdx.y;
    const int tid = threadIdx.x;
    const int i0 = (tid >> 4) << 2;
    const int j0 = (tid & 15) << 2;
    const bool zowner = ((tid & 15) == 0);

    const float* kb = g_k + ((size_t)bh * Tq + c * LCHUNK) * Dq;
    const float* vb = g_v + ((size_t)bh * Tq + c * LCHUNK) * Dq;

    __shared__ float ks[32][64];
    __shared__ float vs[32][64];

    float s[4][4];
#pragma unroll
    for (int a = 0; a < 4; a++)
#pragma unroll
        for (int b = 0; b < 4; b++) s[a][b] = 0.f;
    float z[4] = {0.f, 0.f, 0.f, 0.f};

    for (int t0 = 0; t0 < LCHUNK; t0 += 32) {
#pragma unroll
        for (int l = 0; l < 2; l++) {
            const int f = tid * 2 + l;
            const int rr = f >> 4, cc4 = (f & 15) << 2;
            *(float4*)&ks[rr][cc4] = *(const float4*)(kb + (size_t)(t0 + rr) * 64 + cc4);
            *(float4*)&vs[rr][cc4] = *(const float4*)(vb + (size_t)(t0 + rr) * 64 + cc4);
        }
        __syncthreads();
#pragma unroll 8
        for (int tt = 0; tt < 32; tt++) {
            float kr[4], vr[4];
            *(float4*)kr = *(const float4*)&ks[tt][i0];
            *(float4*)vr = *(const float4*)&vs[tt][j0];
#pragma unroll
            for (int a = 0; a < 4; a++)
#pragma unroll
                for (int b = 0; b < 4; b++)
                    s[a][b] = fmaf(kr[a], vr[b], s[a][b]);
            if (zowner) {
#pragma unroll
                for (int a = 0; a < 4; a++) z[a] += kr[a];
            }
        }
        __syncthreads();
    }

    float* Sp = g_Sc + ((size_t)bh * NCHUNK + c) * (Dq * Dq);
#pragma unroll
    for (int a = 0; a < 4; a++)
        *(float4*)&Sp[(i0 + a) * Dq + j0] = make_float4(s[a][0], s[a][1], s[a][2], s[a][3]);
    if (zowner) {
        float* zp = g_zc + ((size_t)bh * NCHUNK + c) * Dq;
#pragma unroll
        for (int a = 0; a < 4; a++) zp[i0 + a] = z[a];
    }
}

// ---------------- exclusive scan over chunks (element-parallel) --------------
// grid (BHq, 4), 256 threads; each thread owns one float4 of the 64x64 state.
// The 16-chunk loop fully unrolls; all 16 loads issue independently (MLP=16).
__global__ __launch_bounds__(256)
void scan_kernel()
{
    const int bh = blockIdx.x;
    const int e4 = blockIdx.y * 256 + threadIdx.x;    // 0..1023 float4 groups
    const size_t base = (size_t)bh * NCHUNK * (Dq * Dq) + (size_t)e4 * 4;

    float4 run = make_float4(0.f, 0.f, 0.f, 0.f);
#pragma unroll
    for (int c = 0; c < NCHUNK; c++) {
        const size_t off = base + (size_t)c * (Dq * Dq);
        float4 sc = *(const float4*)&g_Sc[off];
        *(float4*)&g_Sp[off] = run;
        run.x += sc.x; run.y += sc.y; run.z += sc.z; run.w += sc.w;
    }

    // z prefix: slab 0, first 64 threads per bh
    if (blockIdx.y == 0 && threadIdx.x < Dq) {
        const size_t zb = (size_t)bh * NCHUNK * Dq + threadIdx.x;
        float zrun = 0.f;
#pragma unroll
        for (int c = 0; c < NCHUNK; c++) {
            const size_t off = zb + (size_t)c * Dq;
            float zc = g_zc[off];
            g_zp[off] = zrun;
            zrun += zc;
        }
    }
}

// ---------------- per-chunk attention (half-chunk blocks) --------------------
#define AT_QS 0
#define AT_KS 4096
#define AT_A  12544
#define AT_S  20736
#define AT_Z  24832
#define AT_D  24896
#define AT_TOTAL 24960
#define AT_BYTES (AT_TOTAL * 4)   // 99840

__global__ __launch_bounds__(256)
void attn_kernel()
{
    extern __shared__ float sm[];
    float* Qs   = sm + AT_QS;
    float* Ks   = sm + AT_KS;
    float* Asm  = sm + AT_A;
    float* Ss   = sm + AT_S;
    float* zs   = sm + AT_Z;
    float* dens = sm + AT_D;

    const int c    = blockIdx.x >> 1;
    const int half = blockIdx.x & 1;
    const int bh   = blockIdx.y;
    const int tid  = threadIdx.x;
    const int r0   = half << 6;
    const int SEND = r0 + 64;
    const size_t coff = ((size_t)bh * Tq + c * LCHUNK) * Dq;
    const size_t qoff = coff + (size_t)r0 * Dq;
    const size_t soff = ((size_t)bh * NCHUNK + c) * (Dq * Dq);

    for (int f = tid; f < 1024; f += 256) {
        const int t = f >> 4, d4 = (f & 15) << 2;
        *(float4*)&Qs[t * 64 + d4] = *(const float4*)(g_q + qoff + (size_t)t * 64 + d4);
    }
    for (int f = tid; f < SEND * 16; f += 256) {
        const int d  = f & 63;
        const int t0 = (f >> 6) << 2;
        const float x0 = g_k[coff + (size_t)(t0 + 0) * 64 + d];
        const float x1 = g_k[coff + (size_t)(t0 + 1) * 64 + d];
        const float x2 = g_k[coff + (size_t)(t0 + 2) * 64 + d];
        const float x3 = g_k[coff + (size_t)(t0 + 3) * 64 + d];
        *(float4*)&Ks[d * 132 + t0] = make_float4(x0, x1, x2, x3);
    }
    for (int f = tid; f < 1024; f += 256)
        *(float4*)&Ss[f * 4] = *(const float4*)(g_Sp + soff + f * 4);
    if (tid < Dq) zs[tid] = g_zp[((size_t)bh * NCHUNK + c) * Dq + tid];
    __syncthreads();

    if (tid < 64) {
        float acc = EPSq;
#pragma unroll
        for (int d0 = 0; d0 < 64; d0 += 4) {
            float4 q4 = *(const float4*)&Qs[tid * 64 + d0];
            float4 z4 = *(const float4*)&zs[d0];
            acc += q4.x * z4.x + q4.y * z4.y + q4.z * z4.z + q4.w * z4.w;
        }
        dens[tid] = acc;
    }
    __syncthreads();

    const int trow = (tid >> 4) << 2;

    if (half) {
        const int tcol = (tid & 15) << 3;
        float a1[4][8];
#pragma unroll
        for (int i = 0; i < 4; i++)
#pragma unroll
            for (int j = 0; j < 8; j++) a1[i][j] = 0.f;
        for (int d0 = 0; d0 < 64; d0 += 4) {
            float kr[4][8];
#pragma unroll
            for (int l = 0; l < 4; l++) {
                *(float4*)(&kr[l][0]) = *(const float4*)&Ks[(d0 + l) * 132 + tcol];
                *(float4*)(&kr[l][4]) = *(const float4*)&Ks[(d0 + l) * 132 + tcol + 4];
            }
#pragma unroll
            for (int i = 0; i < 4; i++) {
                float4 q4 = *(const float4*)&Qs[(trow + i) * 64 + d0];
                const float qa[4] = {q4.x, q4.y, q4.z, q4.w};
#pragma unroll
                for (int l = 0; l < 4; l++)
#pragma unroll
                    for (int j = 0; j < 8; j++)
                        a1[i][j] = fmaf(qa[l], kr[l][j], a1[i][j]);
            }
        }
#pragma unroll
        for (int i = 0; i < 4; i++) {
            const int tl = trow + i;
            const int tg = r0 + tl;
            float rs = 0.f;
#pragma unroll
            for (int j = 0; j < 8; j++) {
                const int s = tcol + j;
                const float v = (s <= tg) ? a1[i][j] : 0.f;
                a1[i][j] = v;
                rs += v;
            }
            *(float4*)&Asm[tl * 128 + tcol]     = make_float4(a1[i][0], a1[i][1], a1[i][2], a1[i][3]);
            *(float4*)&Asm[tl * 128 + tcol + 4] = make_float4(a1[i][4], a1[i][5], a1[i][6], a1[i][7]);
            atomicAdd(&dens[tl], rs);
        }
    } else {
        const int tcol = (tid & 15) << 2;
        float a1[4][4];
#pragma unroll
        for (int i = 0; i < 4; i++)
#pragma unroll
            for (int j = 0; j < 4; j++) a1[i][j] = 0.f;
        for (int d0 = 0; d0 < 64; d0 += 4) {
            float kr[4][4];
#pragma unroll
            for (int l = 0; l < 4; l++)
                *(float4*)(&kr[l][0]) = *(const float4*)&Ks[(d0 + l) * 132 + tcol];
#pragma unroll
            for (int i = 0; i < 4; i++) {
                float4 q4 = *(const float4*)&Qs[(trow + i) * 64 + d0];
                const float qa[4] = {q4.x, q4.y, q4.z, q4.w};
#pragma unroll
                for (int l = 0; l < 4; l++)
#pragma unroll
                    for (int j = 0; j < 4; j++)
                        a1[i][j] = fmaf(qa[l], kr[l][j], a1[i][j]);
            }
        }
#pragma unroll
        for (int i = 0; i < 4; i++) {
            const int tl = trow + i;
            float rs = 0.f;
#pragma unroll
            for (int j = 0; j < 4; j++) {
                const int s = tcol + j;
                const float v = (s <= tl) ? a1[i][j] : 0.f;
                a1[i][j] = v;
                rs += v;
            }
            *(float4*)&Asm[tl * 128 + tcol] = make_float4(a1[i][0], a1[i][1], a1[i][2], a1[i][3]);
            atomicAdd(&dens[tl], rs);
        }
    }
    __syncthreads();

    for (int f = tid; f < SEND * 16; f += 256)
        *(float4*)&Ks[f * 4] = *(const float4*)(g_v + coff + f * 4);
    __syncthreads();

    const int jc = (tid & 15) << 2;
    float a2[4][4];
#pragma unroll
    for (int i = 0; i < 4; i++)
#pragma unroll
        for (int j = 0; j < 4; j++) a2[i][j] = 0.f;

    for (int s0 = 0; s0 < SEND; s0 += 4) {
        float vr[4][4];
#pragma unroll
        for (int l = 0; l < 4; l++)
            *(float4*)vr[l] = *(const float4*)&Ks[(s0 + l) * 64 + jc];
#pragma unroll
        for (int i = 0; i < 4; i++) {
            float4 av = *(const float4*)&Asm[(trow + i) * 128 + s0];
            const float aa[4] = {av.x, av.y, av.z, av.w};
#pragma unroll
            for (int l = 0; l < 4; l++)
#pragma unroll
                for (int j = 0; j < 4; j++)
                    a2[i][j] = fmaf(aa[l], vr[l][j], a2[i][j]);
        }
    }
    for (int d0 = 0; d0 < 64; d0 += 4) {
        float sr[4][4];
#pragma unroll
        for (int l = 0; l < 4; l++)
            *(float4*)sr[l] = *(const float4*)&Ss[(d0 + l) * 64 + jc];
#pragma unroll
        for (int i = 0; i < 4; i++) {
            float4 q4 = *(const float4*)&Qs[(trow + i) * 64 + d0];
            const float qa[4] = {q4.x, q4.y, q4.z, q4.w};
#pragma unroll
            for (int l = 0; l < 4; l++)
#pragma unroll
                for (int j = 0; j < 4; j++)
                    a2[i][j] = fmaf(qa[l], sr[l][j], a2[i][j]);
        }
    }

    const int b = bh >> 4, h = bh & 15;
#pragma unroll
    for (int i = 0; i < 4; i++) {
        const int tl = trow + i;
        const float inv = 1.0f / dens[tl];
        const size_t row = (size_t)b * Tq + c * LCHUNK + r0 + tl;
        const size_t idx = row * Cq + h * 64 + jc;
        float o0 = a2[i][0] * inv, o1 = a2[i][1] * inv;
        float o2 = a2[i][2] * inv, o3 = a2[i][3] * inv;
        __half h0 = __float2half(o0), h1 = __float2half(o1);
        __half h2 = __float2half(o2), h3 = __float2half(o3);
        __half l0 = __float2half(o0 - __half2float(h0));
        __half l1 = __float2half(o1 - __half2float(h1));
        __half l2 = __float2half(o2 - __half2float(h2));
        __half l3 = __float2half(o3 - __half2float(h3));
        uint2 uh, ul;
        uh.x = ((unsigned)__half_as_ushort(h1) << 16) | __half_as_ushort(h0);
        uh.y = ((unsigned)__half_as_ushort(h3) << 16) | __half_as_ushort(h2);
        ul.x = ((unsigned)__half_as_ushort(l1) << 16) | __half_as_ushort(l0);
        ul.y = ((unsigned)__half_as_ushort(l3) << 16) | __half_as_ushort(l2);
        *(uint2*)&g_yh[idx] = uh;
        *(uint2*)&g_yl[idx] = ul;
    }
}

// ---------------- launch -----------------------------------------------------
extern "C" void kernel_launch(void* const* d_in, const int* in_sizes, int n_in,
                              void* d_out, int out_size)
{
    const float* x      = (const float*)d_in[0];
    const float* w_attn = (const float*)d_in[1];
    const float* w_proj = (const float*)d_in[2];
    float* out = (float*)d_out;

    cudaFuncSetAttribute(attn_kernel, cudaFuncAttributeMaxDynamicSharedMemorySize, AT_BYTES);
    cudaFuncSetAttribute(mma_gemm<1>, cudaFuncAttributeMaxDynamicSharedMemorySize, GEMM_SMEM);
    cudaFuncSetAttribute(mma_gemm<2>, cudaFuncAttributeMaxDynamicSharedMemorySize, GEMM_SMEM);

    __half *xh, *xl, *wa, *wp, *yh, *yl;
    cudaGetSymbolAddress((void**)&xh, g_xh);
    cudaGetSymbolAddress((void**)&xl, g_xl);
    cudaGetSymbolAddress((void**)&wa, g_wa);
    cudaGetSymbolAddress((void**)&wp, g_wp);
    cudaGetSymbolAddress((void**)&yh, g_yh);
    cudaGetSymbolAddress((void**)&yl, g_yl);

    prep_kernel<<<N4_TOTAL / 256, 256>>>(x, w_attn, w_proj);

    mma_gemm<1><<<dim3(3 * Cq / 128, Mrows / 128), 256, GEMM_SMEM>>>(
        xh, xl, wa, nullptr, 3 * Cq);
    chunk_sums_kernel<<<dim3(NCHUNK, BHq), 256>>>();
    scan_kernel<<<dim3(BHq, 4), 256>>>();
    attn_kernel<<<dim3(2 * NCHUNK, BHq), 256, AT_BYTES>>>();
    mma_gemm<2><<<dim3(Cq / 128, Mrows / 128), 256, GEMM_SMEM>>>(
        yh, yl, wp, out, Cq);
}

// round 14
// speedup vs baseline: 2.3165x; 1.2553x over previous
#include <cuda_runtime.h>
#include <cuda_fp16.h>
#include <cuda_bf16.h>
#include <math.h>

// Problem constants
#define Bq 2
#define Tq 2048
#define Cq 1024
#define Hq 16
#define Dq 64
#define NCHUNK 16
#define LCHUNK 128
#define BHq (Bq * Hq)       // 32
#define Mrows (Bq * Tq)     // 4096
#define EPSq 1e-6f

// ---------------- scratch (device globals: no allocs allowed) ----------------
__device__ float g_q[(size_t)BHq * Tq * Dq];
__device__ float g_k[(size_t)BHq * Tq * Dq];
__device__ float g_v[(size_t)BHq * Tq * Dq];
__device__ float g_Sc[(size_t)BHq * NCHUNK * Dq * Dq];
__device__ float g_Sp[(size_t)BHq * NCHUNK * Dq * Dq];
__device__ float g_zc[(size_t)BHq * NCHUNK * Dq];
__device__ float g_zp[(size_t)BHq * NCHUNK * Dq];

// fp16 buffers: A-side split hi/lo, B-side (weights) single fp16.
__device__ __align__(16) __half g_xh[(size_t)Mrows * Cq];
__device__ __align__(16) __half g_xl[(size_t)Mrows * Cq];
__device__ __align__(16) __half g_wa[(size_t)Cq * 3 * Cq];
__device__ __align__(16) __half g_wp[(size_t)Cq * Cq];
__device__ __align__(16) __half g_yh[(size_t)Mrows * Cq];
__device__ __align__(16) __half g_yl[(size_t)Mrows * Cq];

// ---------------- fused prep: x hi/lo split + wa/wp fp16 casts ---------------
#define N4_X  (Mrows * Cq / 4)            // 1048576
#define N4_WA (Cq * 3 * Cq / 4)           // 786432
#define N4_WP (Cq * Cq / 4)               // 262144
#define N4_TOTAL (N4_X + N4_WA + N4_WP)   // 2097152

__global__ __launch_bounds__(256)
void prep_kernel(const float* __restrict__ x, const float* __restrict__ wa,
                 const float* __restrict__ wp)
{
    const int i = blockIdx.x * 256 + threadIdx.x;
    if (i < N4_X) {
        float4 v = ((const float4*)x)[i];
        __half h0 = __float2half(v.x), h1 = __float2half(v.y);
        __half h2 = __float2half(v.z), h3 = __float2half(v.w);
        __half l0 = __float2half(v.x - __half2float(h0));
        __half l1 = __float2half(v.y - __half2float(h1));
        __half l2 = __float2half(v.z - __half2float(h2));
        __half l3 = __float2half(v.w - __half2float(h3));
        uint2 uh, ul;
        uh.x = ((unsigned)__half_as_ushort(h1) << 16) | __half_as_ushort(h0);
        uh.y = ((unsigned)__half_as_ushort(h3) << 16) | __half_as_ushort(h2);
        ul.x = ((unsigned)__half_as_ushort(l1) << 16) | __half_as_ushort(l0);
        ul.y = ((unsigned)__half_as_ushort(l3) << 16) | __half_as_ushort(l2);
        ((uint2*)g_xh)[i] = uh;
        ((uint2*)g_xl)[i] = ul;
    } else if (i < N4_X + N4_WA) {
        const int j = i - N4_X;
        float4 v = ((const float4*)wa)[j];
        __half h0 = __float2half(v.x), h1 = __float2half(v.y);
        __half h2 = __float2half(v.z), h3 = __float2half(v.w);
        uint2 uh;
        uh.x = ((unsigned)__half_as_ushort(h1) << 16) | __half_as_ushort(h0);
        uh.y = ((unsigned)__half_as_ushort(h3) << 16) | __half_as_ushort(h2);
        ((uint2*)g_wa)[j] = uh;
    } else if (i < N4_TOTAL) {
        const int j = i - N4_X - N4_WA;
        float4 v = ((const float4*)wp)[j];
        __half h0 = __float2half(v.x), h1 = __float2half(v.y);
        __half h2 = __float2half(v.z), h3 = __float2half(v.w);
        uint2 uh;
        uh.x = ((unsigned)__half_as_ushort(h1) << 16) | __half_as_ushort(h0);
        uh.y = ((unsigned)__half_as_ushort(h3) << 16) | __half_as_ushort(h2);
        ((uint2*)g_wp)[j] = uh;
    }
}

// ---------------- MMA helpers ------------------------------------------------
__device__ __forceinline__ void ldsm_x4(uint4& r, unsigned addr) {
    asm volatile("ldmatrix.sync.aligned.m8n8.x4.shared.b16 {%0,%1,%2,%3}, [%4];"
                 : "=r"(r.x), "=r"(r.y), "=r"(r.z), "=r"(r.w) : "r"(addr));
}
__device__ __forceinline__ void ldsm_x4t(uint4& r, unsigned addr) {
    asm volatile("ldmatrix.sync.aligned.m8n8.x4.trans.shared.b16 {%0,%1,%2,%3}, [%4];"
                 : "=r"(r.x), "=r"(r.y), "=r"(r.z), "=r"(r.w) : "r"(addr));
}
__device__ __forceinline__ void mma_fp16(float c[4], const uint4& a, unsigned b0, unsigned b1) {
    asm volatile("mma.sync.aligned.m16n8k16.row.col.f32.f16.f16.f32 "
                 "{%0,%1,%2,%3},{%4,%5,%6,%7},{%8,%9},{%0,%1,%2,%3};"
                 : "+f"(c[0]), "+f"(c[1]), "+f"(c[2]), "+f"(c[3])
                 : "r"(a.x), "r"(a.y), "r"(a.z), "r"(a.w), "r"(b0), "r"(b1));
}
__device__ __forceinline__ void cp16(unsigned s, const void* g) {
    asm volatile("cp.async.cg.shared.global [%0], [%1], 16;\n" :: "r"(s), "l"(g));
}
__device__ __forceinline__ unsigned pack2h(float a, float b) {
    return ((unsigned)__half_as_ushort(__float2half(b)) << 16)
         | (unsigned)__half_as_ushort(__float2half(a));
}

// ---------------- fp16-split tensor-core GEMM, K-step 64 (round-9 proven) ----
#define STAGE_BYTES 49152
#define GEMM_SMEM   (2 * STAGE_BYTES)

template <int MODE>
__global__ __launch_bounds__(256)
void mma_gemm(const __half* __restrict__ Ah, const __half* __restrict__ Al,
              const __half* __restrict__ Bm,
              float* __restrict__ Cout, int N)
{
    constexpr int K = 1024;
    constexpr int KSTEP = 64;
    constexpr int NITER = K / KSTEP;     // 16
    extern __shared__ char smem[];
    const unsigned sbase = (unsigned)__cvta_generic_to_shared(smem);

    const int tid = threadIdx.x;
    const int lane = tid & 31, wid = tid >> 5;
    const int warp_m = wid >> 2, warp_n = wid & 3;
    const int bm = blockIdx.y * 128, bn = blockIdx.x * 128;

    int sA[4], sB[4], gAr[4], gAc[4], gBr[4], gBc[4];
#pragma unroll
    for (int j = 0; j < 4; j++) {
        const int f = tid + j * 256;          // 0..1023
        const int ar = f >> 3, ac = f & 7;
        sA[j] = (ar * 8 + (ac ^ (ar & 7))) * 16;
        gAr[j] = ar; gAc[j] = ac * 8;
        const int br = f >> 4, bg = f & 15;
        sB[j] = (br * 16 + ((bg & 8) | ((bg & 7) ^ (br & 7)))) * 16;
        gBr[j] = br; gBc[j] = bg * 8;
    }

    const int arow_l = warp_m * 64 + (lane & 15);
    const int aghalf = (lane >> 4) & 1;
    int aOff[4][4];
#pragma unroll
    for (int mi = 0; mi < 4; mi++) {
        const int row = arow_l + mi * 16;
        const int rsw = row & 7;
#pragma unroll
        for (int kx = 0; kx < 4; kx++) {
            const int c = kx * 2 + aghalf;
            aOff[mi][kx] = (row * 8 + (c ^ rsw)) * 16;
        }
    }
    const int bk_l = (lane & 7) + ((lane >> 3) & 1) * 8;
    const int gadd = lane >> 4;
    const int klow = bk_l & 7;
    int bOff[4][2];
#pragma unroll
    for (int kx = 0; kx < 4; kx++) {
        const int k = kx * 16 + bk_l;
#pragma unroll
        for (int np = 0; np < 2; np++) {
            const int g = warp_n * 4 + np * 2 + gadd;
            bOff[kx][np] = (k * 16 + ((g & 8) | ((g & 7) ^ klow))) * 16;
        }
    }

    float acc[4][4][4];
#pragma unroll
    for (int mi = 0; mi < 4; mi++)
#pragma unroll
        for (int ni = 0; ni < 4; ni++)
#pragma unroll
            for (int r = 0; r < 4; r++) acc[mi][ni][r] = 0.f;

    auto issue = [&](int stage, int k0) {
        const unsigned st = sbase + stage * STAGE_BYTES;
#pragma unroll
        for (int j = 0; j < 4; j++) {
            const size_t aoff = (size_t)(bm + gAr[j]) * K + k0 + gAc[j];
            const size_t boff = (size_t)(k0 + gBr[j]) * N + bn + gBc[j];
            cp16(st + sA[j],         Ah + aoff);
            cp16(st + 16384 + sA[j], Al + aoff);
            cp16(st + 32768 + sB[j], Bm + boff);
        }
        asm volatile("cp.async.commit_group;");
    };

    issue(0, 0);
    issue(1, KSTEP);

    for (int it = 0; it < NITER; it++) {
        asm volatile("cp.async.wait_group 1;");
        __syncthreads();
        const unsigned st = sbase + (it & 1) * STAGE_BYTES;
#pragma unroll
        for (int kx = 0; kx < 4; kx++) {
            uint4 Afh[4], Afl[4], Bf[2];
#pragma unroll
            for (int mi = 0; mi < 4; mi++) {
                ldsm_x4(Afh[mi], st + aOff[mi][kx]);
                ldsm_x4(Afl[mi], st + 16384 + aOff[mi][kx]);
            }
#pragma unroll
            for (int np = 0; np < 2; np++)
                ldsm_x4t(Bf[np], st + 32768 + bOff[kx][np]);
#pragma unroll
            for (int mi = 0; mi < 4; mi++)
#pragma unroll
                for (int ni = 0; ni < 4; ni++) {
                    const int np = ni >> 1;
                    const unsigned b0 = (ni & 1) ? Bf[np].z : Bf[np].x;
                    const unsigned b1 = (ni & 1) ? Bf[np].w : Bf[np].y;
                    mma_fp16(acc[mi][ni], Afh[mi], b0, b1);
                    mma_fp16(acc[mi][ni], Afl[mi], b0, b1);
                }
        }
        __syncthreads();
        if (it + 2 < NITER) issue(it & 1, (it + 2) * KSTEP);
        else asm volatile("cp.async.commit_group;");
    }

    const int rbase = bm + warp_m * 64 + (lane >> 2);
    const int cbase = bn + warp_n * 32 + (lane & 3) * 2;
#pragma unroll
    for (int ni = 0; ni < 4; ni++) {
        const int c = cbase + ni * 8;
        if (MODE == 2) {
#pragma unroll
            for (int mi = 0; mi < 4; mi++) {
#pragma unroll
                for (int half = 0; half < 2; half++) {
                    const int r = rbase + mi * 16 + half * 8;
                    *(float2*)&Cout[(size_t)r * N + c] =
                        make_float2(acc[mi][ni][half * 2], acc[mi][ni][half * 2 + 1]);
                }
            }
        } else {
            const int seg = c >> 10;
            const int cc = c & 1023;
            const int h = cc >> 6, d0 = cc & 63;
            float* dstb = (seg == 0) ? g_q : (seg == 1) ? g_k : g_v;
#pragma unroll
            for (int mi = 0; mi < 4; mi++) {
#pragma unroll
                for (int half = 0; half < 2; half++) {
                    const int r = rbase + mi * 16 + half * 8;
                    const int b = r >> 11, t = r & 2047;
                    float v0 = acc[mi][ni][half * 2], v1 = acc[mi][ni][half * 2 + 1];
                    if (seg < 2) {
                        v0 = (v0 > 0.f) ? (v0 + 1.f) : expf(v0);
                        v1 = (v1 > 0.f) ? (v1 + 1.f) : expf(v1);
                    }
                    const size_t idx = ((size_t)(b * Hq + h) * Tq + t) * Dq + d0;
                    *(float2*)&dstb[idx] = make_float2(v0, v1);
                }
            }
        }
    }
}

// ---------------- per-chunk K^T V sums + k sums ------------------------------
__global__ __launch_bounds__(256)
void chunk_sums_kernel()
{
    const int c  = blockIdx.x;
    const int bh = blockIdx.y;
    const int tid = threadIdx.x;
    const int i0 = (tid >> 4) << 2;
    const int j0 = (tid & 15) << 2;
    const bool zowner = ((tid & 15) == 0);

    const float* kb = g_k + ((size_t)bh * Tq + c * LCHUNK) * Dq;
    const float* vb = g_v + ((size_t)bh * Tq + c * LCHUNK) * Dq;

    __shared__ float ks[32][64];
    __shared__ float vs[32][64];

    float s[4][4];
#pragma unroll
    for (int a = 0; a < 4; a++)
#pragma unroll
        for (int b = 0; b < 4; b++) s[a][b] = 0.f;
    float z[4] = {0.f, 0.f, 0.f, 0.f};

    for (int t0 = 0; t0 < LCHUNK; t0 += 32) {
#pragma unroll
        for (int l = 0; l < 2; l++) {
            const int f = tid * 2 + l;
            const int rr = f >> 4, cc4 = (f & 15) << 2;
            *(float4*)&ks[rr][cc4] = *(const float4*)(kb + (size_t)(t0 + rr) * 64 + cc4);
            *(float4*)&vs[rr][cc4] = *(const float4*)(vb + (size_t)(t0 + rr) * 64 + cc4);
        }
        __syncthreads();
#pragma unroll 8
        for (int tt = 0; tt < 32; tt++) {
            float kr[4], vr[4];
            *(float4*)kr = *(const float4*)&ks[tt][i0];
            *(float4*)vr = *(const float4*)&vs[tt][j0];
#pragma unroll
            for (int a = 0; a < 4; a++)
#pragma unroll
                for (int b = 0; b < 4; b++)
                    s[a][b] = fmaf(kr[a], vr[b], s[a][b]);
            if (zowner) {
#pragma unroll
                for (int a = 0; a < 4; a++) z[a] += kr[a];
            }
        }
        __syncthreads();
    }

    float* Sp = g_Sc + ((size_t)bh * NCHUNK + c) * (Dq * Dq);
#pragma unroll
    for (int a = 0; a < 4; a++)
        *(float4*)&Sp[(i0 + a) * Dq + j0] = make_float4(s[a][0], s[a][1], s[a][2], s[a][3]);
    if (zowner) {
        float* zp = g_zc + ((size_t)bh * NCHUNK + c) * Dq;
#pragma unroll
        for (int a = 0; a < 4; a++) zp[i0 + a] = z[a];
    }
}

// ---------------- exclusive scan over chunks (element-parallel) --------------
__global__ __launch_bounds__(256)
void scan_kernel()
{
    const int bh = blockIdx.x;
    const int e4 = blockIdx.y * 256 + threadIdx.x;    // 0..1023 float4 groups
    const size_t base = (size_t)bh * NCHUNK * (Dq * Dq) + (size_t)e4 * 4;

    float4 run = make_float4(0.f, 0.f, 0.f, 0.f);
#pragma unroll
    for (int c = 0; c < NCHUNK; c++) {
        const size_t off = base + (size_t)c * (Dq * Dq);
        float4 sc = *(const float4*)&g_Sc[off];
        *(float4*)&g_Sp[off] = run;
        run.x += sc.x; run.y += sc.y; run.z += sc.z; run.w += sc.w;
    }

    if (blockIdx.y == 0 && threadIdx.x < Dq) {
        const size_t zb = (size_t)bh * NCHUNK * Dq + threadIdx.x;
        float zrun = 0.f;
#pragma unroll
        for (int c = 0; c < NCHUNK; c++) {
            const size_t off = zb + (size_t)c * Dq;
            float zc = g_zc[off];
            g_zp[off] = zrun;
            zrun += zc;
        }
    }
}

// ---------------- per-chunk attention: fp16 MMA version ----------------------
// grid (2*NCHUNK, BH), 256 threads (8 warps as 2x4). 64 q-rows per block.
// Stage1: A[64x128] = (Qh+Ql) @ K^T (K native [s][d], non-trans ldsm B path),
// causal mask + rowsum->dens, A stored fp16. Stage2: y = A@V + (Qh+Ql)@S.
#define AK_QH 0
#define AK_QL 8192
#define AK_KS 16384
#define AK_VS 32768
#define AK_AS 49152
#define AK_SS 65536
#define AK_ZS 73728
#define AK_DN 73984
#define AK_BYTES 74240

__global__ __launch_bounds__(256)
void attn_kernel()
{
    extern __shared__ char smc[];
    const unsigned sb = (unsigned)__cvta_generic_to_shared(smc);
    float* zs   = (float*)(smc + AK_ZS);
    float* dens = (float*)(smc + AK_DN);

    const int c    = blockIdx.x >> 1;
    const int half = blockIdx.x & 1;
    const int bh   = blockIdx.y;
    const int tid  = threadIdx.x;
    const int lane = tid & 31, wid = tid >> 5;
    const int warp_m = wid >> 2, warp_n = wid & 3;   // 2 x 4
    const int r0   = half << 6;
    const size_t coff = ((size_t)bh * Tq + c * LCHUNK) * Dq;
    const size_t qoff = coff + (size_t)r0 * Dq;
    const size_t soff = ((size_t)bh * NCHUNK + c) * (Dq * Dq);

    // ---- load/convert phase --------------------------------------------------
    // Q: 512 granules (8 halves each), hi+lo
#pragma unroll
    for (int j = 0; j < 2; j++) {
        const int gi = tid + j * 256, row = gi >> 3, g = gi & 7;
        const float* s = g_q + qoff + row * 64 + g * 8;
        float4 f0 = *(const float4*)s, f1 = *(const float4*)(s + 4);
        float fs[8] = {f0.x, f0.y, f0.z, f0.w, f1.x, f1.y, f1.z, f1.w};
        unsigned hw[4], lw[4];
#pragma unroll
        for (int p = 0; p < 4; p++) {
            __half ha = __float2half(fs[2*p]), hb = __float2half(fs[2*p+1]);
            float la = fs[2*p] - __half2float(ha);
            float lb = fs[2*p+1] - __half2float(hb);
            hw[p] = ((unsigned)__half_as_ushort(hb) << 16) | __half_as_ushort(ha);
            lw[p] = pack2h(la, lb);
        }
        const unsigned off = row * 128 + ((g ^ (row & 7)) * 16);
        *(uint4*)(smc + AK_QH + off) = make_uint4(hw[0], hw[1], hw[2], hw[3]);
        *(uint4*)(smc + AK_QL + off) = make_uint4(lw[0], lw[1], lw[2], lw[3]);
    }
    // K: 1024 granules (full chunk rows 0..127), hi only
#pragma unroll
    for (int j = 0; j < 4; j++) {
        const int gi = tid + j * 256, row = gi >> 3, g = gi & 7;
        const float* s = g_k + coff + row * 64 + g * 8;
        float4 f0 = *(const float4*)s, f1 = *(const float4*)(s + 4);
        unsigned hw0 = pack2h(f0.x, f0.y), hw1 = pack2h(f0.z, f0.w);
        unsigned hw2 = pack2h(f1.x, f1.y), hw3 = pack2h(f1.z, f1.w);
        *(uint4*)(smc + AK_KS + row * 128 + ((g ^ (row & 7)) * 16)) =
            make_uint4(hw0, hw1, hw2, hw3);
    }
    // V: 1024 granules
#pragma unroll
    for (int j = 0; j < 4; j++) {
        const int gi = tid + j * 256, row = gi >> 3, g = gi & 7;
        const float* s = g_v + coff + row * 64 + g * 8;
        float4 f0 = *(const float4*)s, f1 = *(const float4*)(s + 4);
        unsigned hw0 = pack2h(f0.x, f0.y), hw1 = pack2h(f0.z, f0.w);
        unsigned hw2 = pack2h(f1.x, f1.y), hw3 = pack2h(f1.z, f1.w);
        *(uint4*)(smc + AK_VS + row * 128 + ((g ^ (row & 7)) * 16)) =
            make_uint4(hw0, hw1, hw2, hw3);
    }
    // S: 512 granules
#pragma unroll
    for (int j = 0; j < 2; j++) {
        const int gi = tid + j * 256, row = gi >> 3, g = gi & 7;
        const float* s = g_Sp + soff + row * 64 + g * 8;
        float4 f0 = *(const float4*)s, f1 = *(const float4*)(s + 4);
        unsigned hw0 = pack2h(f0.x, f0.y), hw1 = pack2h(f0.z, f0.w);
        unsigned hw2 = pack2h(f1.x, f1.y), hw3 = pack2h(f1.z, f1.w);
        *(uint4*)(smc + AK_SS + row * 128 + ((g ^ (row & 7)) * 16)) =
            make_uint4(hw0, hw1, hw2, hw3);
    }
    if (tid < Dq) {
        zs[tid] = g_zp[((size_t)bh * NCHUNK + c) * Dq + tid];
        dens[tid] = EPSq;
    }
    __syncthreads();

    // ---- dens init: eps + q . z (q = hi+lo, near-exact) ----------------------
    {
        const int row = tid >> 2, part = tid & 3;
        float s = 0.f;
#pragma unroll
        for (int d = part * 16; d < part * 16 + 16; d++) {
            const unsigned off = row * 128 + (((d >> 3) ^ (row & 7)) * 16) + (d & 7) * 2;
            float qv = __half2float(*(__half*)(smc + AK_QH + off))
                     + __half2float(*(__half*)(smc + AK_QL + off));
            s += qv * zs[d];
        }
        atomicAdd(&dens[row], s);
    }

    // ---- stage 1: A = Q @ K^T ------------------------------------------------
    const int lrow = lane & 15, lhalf = lane >> 4;
    float acc[2][4][4];
#pragma unroll
    for (int mi = 0; mi < 2; mi++)
#pragma unroll
        for (int ni = 0; ni < 4; ni++)
#pragma unroll
            for (int r = 0; r < 4; r++) acc[mi][ni][r] = 0.f;

#pragma unroll
    for (int kx = 0; kx < 4; kx++) {
        uint4 Ahf[2], Alf[2], Bs2[2];
#pragma unroll
        for (int mi = 0; mi < 2; mi++) {
            const int row = warp_m * 32 + mi * 16 + lrow;
            const unsigned ga = (unsigned)((kx * 2 + lhalf) ^ (row & 7));
            ldsm_x4(Ahf[mi], sb + AK_QH + row * 128 + ga * 16);
            ldsm_x4(Alf[mi], sb + AK_QL + row * 128 + ga * 16);
        }
#pragma unroll
        for (int jn = 0; jn < 2; jn++) {
            const int srow = warp_n * 32 + jn * 16 + lrow;
            const unsigned gb = (unsigned)((kx * 2 + lhalf) ^ (srow & 7));
            ldsm_x4(Bs2[jn], sb + AK_KS + srow * 128 + gb * 16);
        }
#pragma unroll
        for (int mi = 0; mi < 2; mi++)
#pragma unroll
            for (int ni = 0; ni < 4; ni++) {
                const int jn = ni >> 1;
                const unsigned b0 = (ni & 1) ? Bs2[jn].y : Bs2[jn].x;
                const unsigned b1 = (ni & 1) ? Bs2[jn].w : Bs2[jn].z;
                mma_fp16(acc[mi][ni], Ahf[mi], b0, b1);
                mma_fp16(acc[mi][ni], Alf[mi], b0, b1);
            }
    }

    // ---- mask + rowsum + store A (fp16) --------------------------------------
#pragma unroll
    for (int mi = 0; mi < 2; mi++) {
        const int ra = warp_m * 32 + mi * 16 + (lane >> 2);
        const int rb = ra + 8;
        float rs0 = 0.f, rs1 = 0.f;
#pragma unroll
        for (int ni = 0; ni < 4; ni++) {
            const int c0 = warp_n * 32 + ni * 8 + (lane & 3) * 2;
            const float v0 = (c0     <= r0 + ra) ? acc[mi][ni][0] : 0.f;
            const float v1 = (c0 + 1 <= r0 + ra) ? acc[mi][ni][1] : 0.f;
            const float v2 = (c0     <= r0 + rb) ? acc[mi][ni][2] : 0.f;
            const float v3 = (c0 + 1 <= r0 + rb) ? acc[mi][ni][3] : 0.f;
            rs0 += v0 + v1; rs1 += v2 + v3;
            const unsigned g = (unsigned)(c0 >> 3), go = (unsigned)((c0 & 7) * 2);
            const unsigned sw0 = (g & 8) | ((g & 7) ^ (ra & 7));
            const unsigned sw1 = (g & 8) | ((g & 7) ^ (rb & 7));
            *(unsigned*)(smc + AK_AS + ra * 256 + sw0 * 16 + go) = pack2h(v0, v1);
            *(unsigned*)(smc + AK_AS + rb * 256 + sw1 * 16 + go) = pack2h(v2, v3);
        }
        atomicAdd(&dens[ra], rs0);
        atomicAdd(&dens[rb], rs1);
    }
    __syncthreads();

    // ---- stage 2: y = A @ V + Q @ S ------------------------------------------
    const int bk_l = (lane & 7) + ((lane >> 3) & 1) * 8;
    float a2[2][2][4];
#pragma unroll
    for (int mi = 0; mi < 2; mi++)
#pragma unroll
        for (int ni = 0; ni < 2; ni++)
#pragma unroll
            for (int r = 0; r < 4; r++) a2[mi][ni][r] = 0.f;

#pragma unroll
    for (int kx = 0; kx < 8; kx++) {
        uint4 Af[2], Bv;
#pragma unroll
        for (int mi = 0; mi < 2; mi++) {
            const int row = warp_m * 32 + mi * 16 + lrow;
            const unsigned g = (unsigned)(kx * 2 + lhalf);
            const unsigned gs = (g & 8) | ((g & 7) ^ (row & 7));
            ldsm_x4(Af[mi], sb + AK_AS + row * 256 + gs * 16);
        }
        const int srow = kx * 16 + bk_l;
        const unsigned gv = (unsigned)((warp_n * 2 + lhalf) ^ (srow & 7));
        ldsm_x4t(Bv, sb + AK_VS + srow * 128 + gv * 16);
#pragma unroll
        for (int mi = 0; mi < 2; mi++)
#pragma unroll
            for (int ni = 0; ni < 2; ni++) {
                const unsigned b0 = ni ? Bv.z : Bv.x;
                const unsigned b1 = ni ? Bv.w : Bv.y;
                mma_fp16(a2[mi][ni], Af[mi], b0, b1);
            }
    }
#pragma unroll
    for (int kx = 0; kx < 4; kx++) {
        uint4 Qhf[2], Qlf[2], Bss;
#pragma unroll
        for (int mi = 0; mi < 2; mi++) {
            const int row = warp_m * 32 + mi * 16 + lrow;
            const unsigned ga = (unsigned)((kx * 2 + lhalf) ^ (row & 7));
            ldsm_x4(Qhf[mi], sb + AK_QH + row * 128 + ga * 16);
            ldsm_x4(Qlf[mi], sb + AK_QL + row * 128 + ga * 16);
        }
        const int srow = kx * 16 + bk_l;
        const unsigned gs2 = (unsigned)((warp_n * 2 + lhalf) ^ (srow & 7));
        ldsm_x4t(Bss, sb + AK_SS + srow * 128 + gs2 * 16);
#pragma unroll
        for (int mi = 0; mi < 2; mi++)
#pragma unroll
            for (int ni = 0; ni < 2; ni++) {
                const unsigned b0 = ni ? Bss.z : Bss.x;
                const unsigned b1 = ni ? Bss.w : Bss.y;
                mma_fp16(a2[mi][ni], Qhf[mi], b0, b1);
                mma_fp16(a2[mi][ni], Qlf[mi], b0, b1);
            }
    }

    // ---- epilogue: divide by dens, hi/lo split, store ------------------------
    const int b = bh >> 4, h = bh & 15;
#pragma unroll
    for (int mi = 0; mi < 2; mi++) {
#pragma unroll
        for (int ni = 0; ni < 2; ni++) {
            const int col = warp_n * 16 + ni * 8 + (lane & 3) * 2;
#pragma unroll
            for (int hf = 0; hf < 2; hf++) {
                const int rl = warp_m * 32 + mi * 16 + (lane >> 2) + hf * 8;
                const float inv = 1.0f / dens[rl];
                const float o0 = a2[mi][ni][hf * 2] * inv;
                const float o1 = a2[mi][ni][hf * 2 + 1] * inv;
                const __half h0 = __float2half(o0), h1 = __float2half(o1);
                const float l0 = o0 - __half2float(h0);
                const float l1 = o1 - __half2float(h1);
                const size_t row_g = (size_t)b * Tq + c * LCHUNK + r0 + rl;
                const size_t idx = row_g * Cq + h * 64 + col;
                *(unsigned*)&g_yh[idx] =
                    ((unsigned)__half_as_ushort(h1) << 16) | __half_as_ushort(h0);
                *(unsigned*)&g_yl[idx] = pack2h(l0, l1);
            }
        }
    }
}

// ---------------- launch -----------------------------------------------------
extern "C" void kernel_launch(void* const* d_in, const int* in_sizes, int n_in,
                              void* d_out, int out_size)
{
    const float* x      = (const float*)d_in[0];
    const float* w_attn = (const float*)d_in[1];
    const float* w_proj = (const float*)d_in[2];
    float* out = (float*)d_out;

    cudaFuncSetAttribute(attn_kernel, cudaFuncAttributeMaxDynamicSharedMemorySize, AK_BYTES);
    cudaFuncSetAttribute(mma_gemm<1>, cudaFuncAttributeMaxDynamicSharedMemorySize, GEMM_SMEM);
    cudaFuncSetAttribute(mma_gemm<2>, cudaFuncAttributeMaxDynamicSharedMemorySize, GEMM_SMEM);

    __half *xh, *xl, *wa, *wp, *yh, *yl;
    cudaGetSymbolAddress((void**)&xh, g_xh);
    cudaGetSymbolAddress((void**)&xl, g_xl);
    cudaGetSymbolAddress((void**)&wa, g_wa);
    cudaGetSymbolAddress((void**)&wp, g_wp);
    cudaGetSymbolAddress((void**)&yh, g_yh);
    cudaGetSymbolAddress((void**)&yl, g_yl);

    prep_kernel<<<N4_TOTAL / 256, 256>>>(x, w_attn, w_proj);

    mma_gemm<1><<<dim3(3 * Cq / 128, Mrows / 128), 256, GEMM_SMEM>>>(
        xh, xl, wa, nullptr, 3 * Cq);
    chunk_sums_kernel<<<dim3(NCHUNK, BHq), 256>>>();
    scan_kernel<<<dim3(BHq, 4), 256>>>();
    attn_kernel<<<dim3(2 * NCHUNK, BHq), 256, AK_BYTES>>>();
    mma_gemm<2><<<dim3(Cq / 128, Mrows / 128), 256, GEMM_SMEM>>>(
        yh, yl, wp, out, Cq);
}

// round 15
// speedup vs baseline: 3.4386x; 1.4844x over previous
#include <cuda_runtime.h>
#include <cuda_fp16.h>
#include <cuda_bf16.h>
#include <math.h>

// Problem constants
#define Bq 2
#define Tq 2048
#define Cq 1024
#define Hq 16
#define Dq 64
#define NCHUNK 16
#define LCHUNK 128
#define BHq (Bq * Hq)       // 32
#define Mrows (Bq * Tq)     // 4096
#define EPSq 1e-6f

// ---------------- scratch (device globals: no allocs allowed) ----------------
__device__ float g_q[(size_t)BHq * Tq * Dq];
__device__ float g_k[(size_t)BHq * Tq * Dq];
__device__ float g_v[(size_t)BHq * Tq * Dq];
__device__ float g_Sc[(size_t)BHq * NCHUNK * Dq * Dq];
__device__ float g_Sp[(size_t)BHq * NCHUNK * Dq * Dq];
__device__ float g_zc[(size_t)BHq * NCHUNK * Dq];
__device__ float g_zp[(size_t)BHq * NCHUNK * Dq];

// fp16 buffers (single precision fp16 operands; fp32 accumulate in MMA).
__device__ __align__(16) __half g_xf[(size_t)Mrows * Cq];
__device__ __align__(16) __half g_wa[(size_t)Cq * 3 * Cq];
__device__ __align__(16) __half g_wp[(size_t)Cq * Cq];
__device__ __align__(16) __half g_yf[(size_t)Mrows * Cq];

// ---------------- fused prep: fp32 -> fp16 casts ------------------------------
#define N4_X  (Mrows * Cq / 4)            // 1048576
#define N4_WA (Cq * 3 * Cq / 4)           // 786432
#define N4_WP (Cq * Cq / 4)               // 262144
#define N4_TOTAL (N4_X + N4_WA + N4_WP)   // 2097152

__global__ __launch_bounds__(256)
void prep_kernel(const float* __restrict__ x, const float* __restrict__ wa,
                 const float* __restrict__ wp)
{
    const int i = blockIdx.x * 256 + threadIdx.x;
    const float4* src;
    __half* dst;
    int j;
    if (i < N4_X) { src = (const float4*)x; dst = g_xf; j = i; }
    else if (i < N4_X + N4_WA) { src = (const float4*)wa; dst = g_wa; j = i - N4_X; }
    else if (i < N4_TOTAL) { src = (const float4*)wp; dst = g_wp; j = i - N4_X - N4_WA; }
    else return;
    float4 v = src[j];
    __half h0 = __float2half(v.x), h1 = __float2half(v.y);
    __half h2 = __float2half(v.z), h3 = __float2half(v.w);
    uint2 uh;
    uh.x = ((unsigned)__half_as_ushort(h1) << 16) | __half_as_ushort(h0);
    uh.y = ((unsigned)__half_as_ushort(h3) << 16) | __half_as_ushort(h2);
    ((uint2*)dst)[j] = uh;
}

// ---------------- MMA helpers ------------------------------------------------
__device__ __forceinline__ void ldsm_x4(uint4& r, unsigned addr) {
    asm volatile("ldmatrix.sync.aligned.m8n8.x4.shared.b16 {%0,%1,%2,%3}, [%4];"
                 : "=r"(r.x), "=r"(r.y), "=r"(r.z), "=r"(r.w) : "r"(addr));
}
__device__ __forceinline__ void ldsm_x4t(uint4& r, unsigned addr) {
    asm volatile("ldmatrix.sync.aligned.m8n8.x4.trans.shared.b16 {%0,%1,%2,%3}, [%4];"
                 : "=r"(r.x), "=r"(r.y), "=r"(r.z), "=r"(r.w) : "r"(addr));
}
__device__ __forceinline__ void mma_fp16(float c[4], const uint4& a, unsigned b0, unsigned b1) {
    asm volatile("mma.sync.aligned.m16n8k16.row.col.f32.f16.f16.f32 "
                 "{%0,%1,%2,%3},{%4,%5,%6,%7},{%8,%9},{%0,%1,%2,%3};"
                 : "+f"(c[0]), "+f"(c[1]), "+f"(c[2]), "+f"(c[3])
                 : "r"(a.x), "r"(a.y), "r"(a.z), "r"(a.w), "r"(b0), "r"(b1));
}
__device__ __forceinline__ void cp16(unsigned s, const void* g) {
    asm volatile("cp.async.cg.shared.global [%0], [%1], 16;\n" :: "r"(s), "l"(g));
}
__device__ __forceinline__ unsigned pack2h(float a, float b) {
    return ((unsigned)__half_as_ushort(__float2half(b)) << 16)
         | (unsigned)__half_as_ushort(__float2half(a));
}

// ---------------- fp16 tensor-core GEMM, K-step 64 ---------------------------
// C = A @ B, both fp16, fp32 accumulate. Block 128x128, warp tile 64x32.
// Per stage: A 16K | B 16K = 32KB; 2 stages = 64KB.
#define STAGE_BYTES 32768
#define GEMM_SMEM   (2 * STAGE_BYTES)

template <int MODE>
__global__ __launch_bounds__(256)
void mma_gemm(const __half* __restrict__ Am, const __half* __restrict__ Bm,
              float* __restrict__ Cout, int N)
{
    constexpr int K = 1024;
    constexpr int KSTEP = 64;
    constexpr int NITER = K / KSTEP;     // 16
    extern __shared__ char smem[];
    const unsigned sbase = (unsigned)__cvta_generic_to_shared(smem);

    const int tid = threadIdx.x;
    const int lane = tid & 31, wid = tid >> 5;
    const int warp_m = wid >> 2, warp_n = wid & 3;
    const int bm = blockIdx.y * 128, bn = blockIdx.x * 128;

    int sA[4], sB[4], gAr[4], gAc[4], gBr[4], gBc[4];
#pragma unroll
    for (int j = 0; j < 4; j++) {
        const int f = tid + j * 256;          // 0..1023
        const int ar = f >> 3, ac = f & 7;
        sA[j] = (ar * 8 + (ac ^ (ar & 7))) * 16;
        gAr[j] = ar; gAc[j] = ac * 8;
        const int br = f >> 4, bg = f & 15;
        sB[j] = (br * 16 + ((bg & 8) | ((bg & 7) ^ (br & 7)))) * 16;
        gBr[j] = br; gBc[j] = bg * 8;
    }

    const int arow_l = warp_m * 64 + (lane & 15);
    const int aghalf = (lane >> 4) & 1;
    int aOff[4][4];
#pragma unroll
    for (int mi = 0; mi < 4; mi++) {
        const int row = arow_l + mi * 16;
        const int rsw = row & 7;
#pragma unroll
        for (int kx = 0; kx < 4; kx++) {
            const int c = kx * 2 + aghalf;
            aOff[mi][kx] = (row * 8 + (c ^ rsw)) * 16;
        }
    }
    const int bk_l = (lane & 7) + ((lane >> 3) & 1) * 8;
    const int gadd = lane >> 4;
    const int klow = bk_l & 7;
    int bOff[4][2];
#pragma unroll
    for (int kx = 0; kx < 4; kx++) {
        const int k = kx * 16 + bk_l;
#pragma unroll
        for (int np = 0; np < 2; np++) {
            const int g = warp_n * 4 + np * 2 + gadd;
            bOff[kx][np] = (k * 16 + ((g & 8) | ((g & 7) ^ klow))) * 16;
        }
    }

    float acc[4][4][4];
#pragma unroll
    for (int mi = 0; mi < 4; mi++)
#pragma unroll
        for (int ni = 0; ni < 4; ni++)
#pragma unroll
            for (int r = 0; r < 4; r++) acc[mi][ni][r] = 0.f;

    auto issue = [&](int stage, int k0) {
        const unsigned st = sbase + stage * STAGE_BYTES;
#pragma unroll
        for (int j = 0; j < 4; j++) {
            const size_t aoff = (size_t)(bm + gAr[j]) * K + k0 + gAc[j];
            const size_t boff = (size_t)(k0 + gBr[j]) * N + bn + gBc[j];
            cp16(st + sA[j],         Am + aoff);
            cp16(st + 16384 + sB[j], Bm + boff);
        }
        asm volatile("cp.async.commit_group;");
    };

    issue(0, 0);
    issue(1, KSTEP);

    for (int it = 0; it < NITER; it++) {
        asm volatile("cp.async.wait_group 1;");
        __syncthreads();
        const unsigned st = sbase + (it & 1) * STAGE_BYTES;
#pragma unroll
        for (int kx = 0; kx < 4; kx++) {
            uint4 Af[4], Bf[2];
#pragma unroll
            for (int mi = 0; mi < 4; mi++)
                ldsm_x4(Af[mi], st + aOff[mi][kx]);
#pragma unroll
            for (int np = 0; np < 2; np++)
                ldsm_x4t(Bf[np], st + 16384 + bOff[kx][np]);
#pragma unroll
            for (int mi = 0; mi < 4; mi++)
#pragma unroll
                for (int ni = 0; ni < 4; ni++) {
                    const int np = ni >> 1;
                    const unsigned b0 = (ni & 1) ? Bf[np].z : Bf[np].x;
                    const unsigned b1 = (ni & 1) ? Bf[np].w : Bf[np].y;
                    mma_fp16(acc[mi][ni], Af[mi], b0, b1);
                }
        }
        __syncthreads();
        if (it + 2 < NITER) issue(it & 1, (it + 2) * KSTEP);
        else asm volatile("cp.async.commit_group;");
    }

    const int rbase = bm + warp_m * 64 + (lane >> 2);
    const int cbase = bn + warp_n * 32 + (lane & 3) * 2;
#pragma unroll
    for (int ni = 0; ni < 4; ni++) {
        const int c = cbase + ni * 8;
        if (MODE == 2) {
#pragma unroll
            for (int mi = 0; mi < 4; mi++) {
#pragma unroll
                for (int half = 0; half < 2; half++) {
                    const int r = rbase + mi * 16 + half * 8;
                    *(float2*)&Cout[(size_t)r * N + c] =
                        make_float2(acc[mi][ni][half * 2], acc[mi][ni][half * 2 + 1]);
                }
            }
        } else {
            const int seg = c >> 10;
            const int cc = c & 1023;
            const int h = cc >> 6, d0 = cc & 63;
            float* dstb = (seg == 0) ? g_q : (seg == 1) ? g_k : g_v;
#pragma unroll
            for (int mi = 0; mi < 4; mi++) {
#pragma unroll
                for (int half = 0; half < 2; half++) {
                    const int r = rbase + mi * 16 + half * 8;
                    const int b = r >> 11, t = r & 2047;
                    float v0 = acc[mi][ni][half * 2], v1 = acc[mi][ni][half * 2 + 1];
                    if (seg < 2) {
                        v0 = (v0 > 0.f) ? (v0 + 1.f) : expf(v0);
                        v1 = (v1 > 0.f) ? (v1 + 1.f) : expf(v1);
                    }
                    const size_t idx = ((size_t)(b * Hq + h) * Tq + t) * Dq + d0;
                    *(float2*)&dstb[idx] = make_float2(v0, v1);
                }
            }
        }
    }
}

// ---------------- per-chunk K^T V sums + k sums ------------------------------
__global__ __launch_bounds__(256)
void chunk_sums_kernel()
{
    const int c  = blockIdx.x;
    const int bh = blockIdx.y;
    const int tid = threadIdx.x;
    const int i0 = (tid >> 4) << 2;
    const int j0 = (tid & 15) << 2;
    const bool zowner = ((tid & 15) == 0);

    const float* kb = g_k + ((size_t)bh * Tq + c * LCHUNK) * Dq;
    const float* vb = g_v + ((size_t)bh * Tq + c * LCHUNK) * Dq;

    __shared__ float ks[32][64];
    __shared__ float vs[32][64];

    float s[4][4];
#pragma unroll
    for (int a = 0; a < 4; a++)
#pragma unroll
        for (int b = 0; b < 4; b++) s[a][b] = 0.f;
    float z[4] = {0.f, 0.f, 0.f, 0.f};

    for (int t0 = 0; t0 < LCHUNK; t0 += 32) {
#pragma unroll
        for (int l = 0; l < 2; l++) {
            const int f = tid * 2 + l;
            const int rr = f >> 4, cc4 = (f & 15) << 2;
            *(float4*)&ks[rr][cc4] = *(const float4*)(kb + (size_t)(t0 + rr) * 64 + cc4);
            *(float4*)&vs[rr][cc4] = *(const float4*)(vb + (size_t)(t0 + rr) * 64 + cc4);
        }
        __syncthreads();
#pragma unroll 8
        for (int tt = 0; tt < 32; tt++) {
            float kr[4], vr[4];
            *(float4*)kr = *(const float4*)&ks[tt][i0];
            *(float4*)vr = *(const float4*)&vs[tt][j0];
#pragma unroll
            for (int a = 0; a < 4; a++)
#pragma unroll
                for (int b = 0; b < 4; b++)
                    s[a][b] = fmaf(kr[a], vr[b], s[a][b]);
            if (zowner) {
#pragma unroll
                for (int a = 0; a < 4; a++) z[a] += kr[a];
            }
        }
        __syncthreads();
    }

    float* Sp = g_Sc + ((size_t)bh * NCHUNK + c) * (Dq * Dq);
#pragma unroll
    for (int a = 0; a < 4; a++)
        *(float4*)&Sp[(i0 + a) * Dq + j0] = make_float4(s[a][0], s[a][1], s[a][2], s[a][3]);
    if (zowner) {
        float* zp = g_zc + ((size_t)bh * NCHUNK + c) * Dq;
#pragma unroll
        for (int a = 0; a < 4; a++) zp[i0 + a] = z[a];
    }
}

// ---------------- exclusive scan over chunks (element-parallel) --------------
__global__ __launch_bounds__(256)
void scan_kernel()
{
    const int bh = blockIdx.x;
    const int e4 = blockIdx.y * 256 + threadIdx.x;    // 0..1023 float4 groups
    const size_t base = (size_t)bh * NCHUNK * (Dq * Dq) + (size_t)e4 * 4;

    float4 run = make_float4(0.f, 0.f, 0.f, 0.f);
#pragma unroll
    for (int c = 0; c < NCHUNK; c++) {
        const size_t off = base + (size_t)c * (Dq * Dq);
        float4 sc = *(const float4*)&g_Sc[off];
        *(float4*)&g_Sp[off] = run;
        run.x += sc.x; run.y += sc.y; run.z += sc.z; run.w += sc.w;
    }

    if (blockIdx.y == 0 && threadIdx.x < Dq) {
        const size_t zb = (size_t)bh * NCHUNK * Dq + threadIdx.x;
        float zrun = 0.f;
#pragma unroll
        for (int c = 0; c < NCHUNK; c++) {
            const size_t off = zb + (size_t)c * Dq;
            float zc = g_zc[off];
            g_zp[off] = zrun;
            zrun += zc;
        }
    }
}

// ---------------- per-chunk attention: fp16 MMA version ----------------------
#define AK_QH 0
#define AK_QL 8192
#define AK_KS 16384
#define AK_VS 32768
#define AK_AS 49152
#define AK_SS 65536
#define AK_ZS 73728
#define AK_DN 73984
#define AK_BYTES 74240

__global__ __launch_bounds__(256)
void attn_kernel()
{
    extern __shared__ char smc[];
    const unsigned sb = (unsigned)__cvta_generic_to_shared(smc);
    float* zs   = (float*)(smc + AK_ZS);
    float* dens = (float*)(smc + AK_DN);

    const int c    = blockIdx.x >> 1;
    const int half = blockIdx.x & 1;
    const int bh   = blockIdx.y;
    const int tid  = threadIdx.x;
    const int lane = tid & 31, wid = tid >> 5;
    const int warp_m = wid >> 2, warp_n = wid & 3;   // 2 x 4
    const int r0   = half << 6;
    const size_t coff = ((size_t)bh * Tq + c * LCHUNK) * Dq;
    const size_t qoff = coff + (size_t)r0 * Dq;
    const size_t soff = ((size_t)bh * NCHUNK + c) * (Dq * Dq);

    // ---- load/convert phase --------------------------------------------------
#pragma unroll
    for (int j = 0; j < 2; j++) {
        const int gi = tid + j * 256, row = gi >> 3, g = gi & 7;
        const float* s = g_q + qoff + row * 64 + g * 8;
        float4 f0 = *(const float4*)s, f1 = *(const float4*)(s + 4);
        float fs[8] = {f0.x, f0.y, f0.z, f0.w, f1.x, f1.y, f1.z, f1.w};
        unsigned hw[4], lw[4];
#pragma unroll
        for (int p = 0; p < 4; p++) {
            __half ha = __float2half(fs[2*p]), hb = __float2half(fs[2*p+1]);
            float la = fs[2*p] - __half2float(ha);
            float lb = fs[2*p+1] - __half2float(hb);
            hw[p] = ((unsigned)__half_as_ushort(hb) << 16) | __half_as_ushort(ha);
            lw[p] = pack2h(la, lb);
        }
        const unsigned off = row * 128 + ((g ^ (row & 7)) * 16);
        *(uint4*)(smc + AK_QH + off) = make_uint4(hw[0], hw[1], hw[2], hw[3]);
        *(uint4*)(smc + AK_QL + off) = make_uint4(lw[0], lw[1], lw[2], lw[3]);
    }
#pragma unroll
    for (int j = 0; j < 4; j++) {
        const int gi = tid + j * 256, row = gi >> 3, g = gi & 7;
        const float* s = g_k + coff + row * 64 + g * 8;
        float4 f0 = *(const float4*)s, f1 = *(const float4*)(s + 4);
        unsigned hw0 = pack2h(f0.x, f0.y), hw1 = pack2h(f0.z, f0.w);
        unsigned hw2 = pack2h(f1.x, f1.y), hw3 = pack2h(f1.z, f1.w);
        *(uint4*)(smc + AK_KS + row * 128 + ((g ^ (row & 7)) * 16)) =
            make_uint4(hw0, hw1, hw2, hw3);
    }
#pragma unroll
    for (int j = 0; j < 4; j++) {
        const int gi = tid + j * 256, row = gi >> 3, g = gi & 7;
        const float* s = g_v + coff + row * 64 + g * 8;
        float4 f0 = *(const float4*)s, f1 = *(const float4*)(s + 4);
        unsigned hw0 = pack2h(f0.x, f0.y), hw1 = pack2h(f0.z, f0.w);
        unsigned hw2 = pack2h(f1.x, f1.y), hw3 = pack2h(f1.z, f1.w);
        *(uint4*)(smc + AK_VS + row * 128 + ((g ^ (row & 7)) * 16)) =
            make_uint4(hw0, hw1, hw2, hw3);
    }
#pragma unroll
    for (int j = 0; j < 2; j++) {
        const int gi = tid + j * 256, row = gi >> 3, g = gi & 7;
        const float* s = g_Sp + soff + row * 64 + g * 8;
        float4 f0 = *(const float4*)s, f1 = *(const float4*)(s + 4);
        unsigned hw0 = pack2h(f0.x, f0.y), hw1 = pack2h(f0.z, f0.w);
        unsigned hw2 = pack2h(f1.x, f1.y), hw3 = pack2h(f1.z, f1.w);
        *(uint4*)(smc + AK_SS + row * 128 + ((g ^ (row & 7)) * 16)) =
            make_uint4(hw0, hw1, hw2, hw3);
    }
    if (tid < Dq) {
        zs[tid] = g_zp[((size_t)bh * NCHUNK + c) * Dq + tid];
        dens[tid] = EPSq;
    }
    __syncthreads();

    // ---- dens init: eps + q . z ----------------------------------------------
    {
        const int row = tid >> 2, part = tid & 3;
        float s = 0.f;
#pragma unroll
        for (int d = part * 16; d < part * 16 + 16; d++) {
            const unsigned off = row * 128 + (((d >> 3) ^ (row & 7)) * 16) + (d & 7) * 2;
            float qv = __half2float(*(__half*)(smc + AK_QH + off))
                     + __half2float(*(__half*)(smc + AK_QL + off));
            s += qv * zs[d];
        }
        atomicAdd(&dens[row], s);
    }

    // ---- stage 1: A = Q @ K^T ------------------------------------------------
    const int lrow = lane & 15, lhalf = lane >> 4;
    float acc[2][4][4];
#pragma unroll
    for (int mi = 0; mi < 2; mi++)
#pragma unroll
        for (int ni = 0; ni < 4; ni++)
#pragma unroll
            for (int r = 0; r < 4; r++) acc[mi][ni][r] = 0.f;

#pragma unroll
    for (int kx = 0; kx < 4; kx++) {
        uint4 Ahf[2], Alf[2], Bs2[2];
#pragma unroll
        for (int mi = 0; mi < 2; mi++) {
            const int row = warp_m * 32 + mi * 16 + lrow;
            const unsigned ga = (unsigned)((kx * 2 + lhalf) ^ (row & 7));
            ldsm_x4(Ahf[mi], sb + AK_QH + row * 128 + ga * 16);
            ldsm_x4(Alf[mi], sb + AK_QL + row * 128 + ga * 16);
        }
#pragma unroll
        for (int jn = 0; jn < 2; jn++) {
            const int srow = warp_n * 32 + jn * 16 + lrow;
            const unsigned gb = (unsigned)((kx * 2 + lhalf) ^ (srow & 7));
            ldsm_x4(Bs2[jn], sb + AK_KS + srow * 128 + gb * 16);
        }
#pragma unroll
        for (int mi = 0; mi < 2; mi++)
#pragma unroll
            for (int ni = 0; ni < 4; ni++) {
                const int jn = ni >> 1;
                const unsigned b0 = (ni & 1) ? Bs2[jn].y : Bs2[jn].x;
                const unsigned b1 = (ni & 1) ? Bs2[jn].w : Bs2[jn].z;
                mma_fp16(acc[mi][ni], Ahf[mi], b0, b1);
                mma_fp16(acc[mi][ni], Alf[mi], b0, b1);
            }
    }

    // ---- mask + rowsum + store A (fp16) --------------------------------------
#pragma unroll
    for (int mi = 0; mi < 2; mi++) {
        const int ra = warp_m * 32 + mi * 16 + (lane >> 2);
        const int rb = ra + 8;
        float rs0 = 0.f, rs1 = 0.f;
#pragma unroll
        for (int ni = 0; ni < 4; ni++) {
            const int c0 = warp_n * 32 + ni * 8 + (lane & 3) * 2;
            const float v0 = (c0     <= r0 + ra) ? acc[mi][ni][0] : 0.f;
            const float v1 = (c0 + 1 <= r0 + ra) ? acc[mi][ni][1] : 0.f;
            const float v2 = (c0     <= r0 + rb) ? acc[mi][ni][2] : 0.f;
            const float v3 = (c0 + 1 <= r0 + rb) ? acc[mi][ni][3] : 0.f;
            rs0 += v0 + v1; rs1 += v2 + v3;
            const unsigned g = (unsigned)(c0 >> 3), go = (unsigned)((c0 & 7) * 2);
            const unsigned sw0 = (g & 8) | ((g & 7) ^ (ra & 7));
            const unsigned sw1 = (g & 8) | ((g & 7) ^ (rb & 7));
            *(unsigned*)(smc + AK_AS + ra * 256 + sw0 * 16 + go) = pack2h(v0, v1);
            *(unsigned*)(smc + AK_AS + rb * 256 + sw1 * 16 + go) = pack2h(v2, v3);
        }
        atomicAdd(&dens[ra], rs0);
        atomicAdd(&dens[rb], rs1);
    }
    __syncthreads();

    // ---- stage 2: y = A @ V + Q @ S ------------------------------------------
    const int bk_l = (lane & 7) + ((lane >> 3) & 1) * 8;
    float a2[2][2][4];
#pragma unroll
    for (int mi = 0; mi < 2; mi++)
#pragma unroll
        for (int ni = 0; ni < 2; ni++)
#pragma unroll
            for (int r = 0; r < 4; r++) a2[mi][ni][r] = 0.f;

#pragma unroll
    for (int kx = 0; kx < 8; kx++) {
        uint4 Af[2], Bv;
#pragma unroll
        for (int mi = 0; mi < 2; mi++) {
            const int row = warp_m * 32 + mi * 16 + lrow;
            const unsigned g = (unsigned)(kx * 2 + lhalf);
            const unsigned gs = (g & 8) | ((g & 7) ^ (row & 7));
            ldsm_x4(Af[mi], sb + AK_AS + row * 256 + gs * 16);
        }
        const int srow = kx * 16 + bk_l;
        const unsigned gv = (unsigned)((warp_n * 2 + lhalf) ^ (srow & 7));
        ldsm_x4t(Bv, sb + AK_VS + srow * 128 + gv * 16);
#pragma unroll
        for (int mi = 0; mi < 2; mi++)
#pragma unroll
            for (int ni = 0; ni < 2; ni++) {
                const unsigned b0 = ni ? Bv.z : Bv.x;
                const unsigned b1 = ni ? Bv.w : Bv.y;
                mma_fp16(a2[mi][ni], Af[mi], b0, b1);
            }
    }
#pragma unroll
    for (int kx = 0; kx < 4; kx++) {
        uint4 Qhf[2], Qlf[2], Bss;
#pragma unroll
        for (int mi = 0; mi < 2; mi++) {
            const int row = warp_m * 32 + mi * 16 + lrow;
            const unsigned ga = (unsigned)((kx * 2 + lhalf) ^ (row & 7));
            ldsm_x4(Qhf[mi], sb + AK_QH + row * 128 + ga * 16);
            ldsm_x4(Qlf[mi], sb + AK_QL + row * 128 + ga * 16);
        }
        const int srow = kx * 16 + bk_l;
        const unsigned gs2 = (unsigned)((warp_n * 2 + lhalf) ^ (srow & 7));
        ldsm_x4t(Bss, sb + AK_SS + srow * 128 + gs2 * 16);
#pragma unroll
        for (int mi = 0; mi < 2; mi++)
#pragma unroll
            for (int ni = 0; ni < 2; ni++) {
                const unsigned b0 = ni ? Bss.z : Bss.x;
                const unsigned b1 = ni ? Bss.w : Bss.y;
                mma_fp16(a2[mi][ni], Qhf[mi], b0, b1);
                mma_fp16(a2[mi][ni], Qlf[mi], b0, b1);
            }
    }

    // ---- epilogue: divide by dens, store single fp16 -------------------------
    const int b = bh >> 4, h = bh & 15;
#pragma unroll
    for (int mi = 0; mi < 2; mi++) {
#pragma unroll
        for (int ni = 0; ni < 2; ni++) {
            const int col = warp_n * 16 + ni * 8 + (lane & 3) * 2;
#pragma unroll
            for (int hf = 0; hf < 2; hf++) {
                const int rl = warp_m * 32 + mi * 16 + (lane >> 2) + hf * 8;
                const float inv = 1.0f / dens[rl];
                const float o0 = a2[mi][ni][hf * 2] * inv;
                const float o1 = a2[mi][ni][hf * 2 + 1] * inv;
                const size_t row_g = (size_t)b * Tq + c * LCHUNK + r0 + rl;
                const size_t idx = row_g * Cq + h * 64 + col;
                *(unsigned*)&g_yf[idx] = pack2h(o0, o1);
            }
        }
    }
}

// ---------------- launch -----------------------------------------------------
extern "C" void kernel_launch(void* const* d_in, const int* in_sizes, int n_in,
                              void* d_out, int out_size)
{
    const float* x      = (const float*)d_in[0];
    const float* w_attn = (const float*)d_in[1];
    const float* w_proj = (const float*)d_in[2];
    float* out = (float*)d_out;

    cudaFuncSetAttribute(attn_kernel, cudaFuncAttributeMaxDynamicSharedMemorySize, AK_BYTES);
    cudaFuncSetAttribute(mma_gemm<1>, cudaFuncAttributeMaxDynamicSharedMemorySize, GEMM_SMEM);
    cudaFuncSetAttribute(mma_gemm<2>, cudaFuncAttributeMaxDynamicSharedMemorySize, GEMM_SMEM);

    __half *xf, *wa, *wp, *yf;
    cudaGetSymbolAddress((void**)&xf, g_xf);
    cudaGetSymbolAddress((void**)&wa, g_wa);
    cudaGetSymbolAddress((void**)&wp, g_wp);
    cudaGetSymbolAddress((void**)&yf, g_yf);

    prep_kernel<<<N4_TOTAL / 256, 256>>>(x, w_attn, w_proj);

    mma_gemm<1><<<dim3(3 * Cq / 128, Mrows / 128), 256, GEMM_SMEM>>>(
        xf, wa, nullptr, 3 * Cq);
    chunk_sums_kernel<<<dim3(NCHUNK, BHq), 256>>>();
    scan_kernel<<<dim3(BHq, 4), 256>>>();
    attn_kernel<<<dim3(2 * NCHUNK, BHq), 256, AK_BYTES>>>();
    mma_gemm<2><<<dim3(Cq / 128, Mrows / 128), 256, GEMM_SMEM>>>(
        yf, wp, out, Cq);
}

// round 16
// speedup vs baseline: 3.4476x; 1.0026x over previous
#include <cuda_runtime.h>
#include <cuda_fp16.h>
#include <cuda_bf16.h>
#include <math.h>

// Problem constants
#define Bq 2
#define Tq 2048
#define Cq 1024
#define Hq 16
#define Dq 64
#define NCHUNK 16
#define LCHUNK 128
#define BHq (Bq * Hq)       // 32
#define Mrows (Bq * Tq)     // 4096
#define EPSq 1e-6f

// ---------------- scratch (device globals: no allocs allowed) ----------------
__device__ float g_q[(size_t)BHq * Tq * Dq];
__device__ float g_k[(size_t)BHq * Tq * Dq];
__device__ float g_v[(size_t)BHq * Tq * Dq];
__device__ float g_Sc[(size_t)BHq * NCHUNK * Dq * Dq];
__device__ float g_Sp[(size_t)BHq * NCHUNK * Dq * Dq];
__device__ float g_zc[(size_t)BHq * NCHUNK * Dq];
__device__ float g_zp[(size_t)BHq * NCHUNK * Dq];

// fp16 buffers (single precision fp16 operands; fp32 accumulate in MMA).
__device__ __align__(16) __half g_xf[(size_t)Mrows * Cq];
__device__ __align__(16) __half g_wa[(size_t)Cq * 3 * Cq];
__device__ __align__(16) __half g_wp[(size_t)Cq * Cq];
__device__ __align__(16) __half g_yf[(size_t)Mrows * Cq];

// ---------------- fused prep: fp32 -> fp16 casts ------------------------------
#define N4_X  (Mrows * Cq / 4)            // 1048576
#define N4_WA (Cq * 3 * Cq / 4)           // 786432
#define N4_WP (Cq * Cq / 4)               // 262144
#define N4_TOTAL (N4_X + N4_WA + N4_WP)   // 2097152

__global__ __launch_bounds__(256)
void prep_kernel(const float* __restrict__ x, const float* __restrict__ wa,
                 const float* __restrict__ wp)
{
    const int i = blockIdx.x * 256 + threadIdx.x;
    const float4* src;
    __half* dst;
    int j;
    if (i < N4_X) { src = (const float4*)x; dst = g_xf; j = i; }
    else if (i < N4_X + N4_WA) { src = (const float4*)wa; dst = g_wa; j = i - N4_X; }
    else if (i < N4_TOTAL) { src = (const float4*)wp; dst = g_wp; j = i - N4_X - N4_WA; }
    else return;
    float4 v = src[j];
    __half h0 = __float2half(v.x), h1 = __float2half(v.y);
    __half h2 = __float2half(v.z), h3 = __float2half(v.w);
    uint2 uh;
    uh.x = ((unsigned)__half_as_ushort(h1) << 16) | __half_as_ushort(h0);
    uh.y = ((unsigned)__half_as_ushort(h3) << 16) | __half_as_ushort(h2);
    ((uint2*)dst)[j] = uh;
}

// ---------------- MMA helpers ------------------------------------------------
__device__ __forceinline__ void ldsm_x4(uint4& r, unsigned addr) {
    asm volatile("ldmatrix.sync.aligned.m8n8.x4.shared.b16 {%0,%1,%2,%3}, [%4];"
                 : "=r"(r.x), "=r"(r.y), "=r"(r.z), "=r"(r.w) : "r"(addr));
}
__device__ __forceinline__ void ldsm_x4t(uint4& r, unsigned addr) {
    asm volatile("ldmatrix.sync.aligned.m8n8.x4.trans.shared.b16 {%0,%1,%2,%3}, [%4];"
                 : "=r"(r.x), "=r"(r.y), "=r"(r.z), "=r"(r.w) : "r"(addr));
}
__device__ __forceinline__ void mma_fp16(float c[4], const uint4& a, unsigned b0, unsigned b1) {
    asm volatile("mma.sync.aligned.m16n8k16.row.col.f32.f16.f16.f32 "
                 "{%0,%1,%2,%3},{%4,%5,%6,%7},{%8,%9},{%0,%1,%2,%3};"
                 : "+f"(c[0]), "+f"(c[1]), "+f"(c[2]), "+f"(c[3])
                 : "r"(a.x), "r"(a.y), "r"(a.z), "r"(a.w), "r"(b0), "r"(b1));
}
__device__ __forceinline__ void cp16(unsigned s, const void* g) {
    asm volatile("cp.async.cg.shared.global [%0], [%1], 16;\n" :: "r"(s), "l"(g));
}
__device__ __forceinline__ unsigned pack2h(float a, float b) {
    return ((unsigned)__half_as_ushort(__float2half(b)) << 16)
         | (unsigned)__half_as_ushort(__float2half(a));
}

// ---------------- fp16 tensor-core GEMM, K-step 64 ---------------------------
#define STAGE_BYTES 32768
#define GEMM_SMEM   (2 * STAGE_BYTES)

template <int MODE>
__global__ __launch_bounds__(256)
void mma_gemm(const __half* __restrict__ Am, const __half* __restrict__ Bm,
              float* __restrict__ Cout, int N)
{
    constexpr int K = 1024;
    constexpr int KSTEP = 64;
    constexpr int NITER = K / KSTEP;     // 16
    extern __shared__ char smem[];
    const unsigned sbase = (unsigned)__cvta_generic_to_shared(smem);

    const int tid = threadIdx.x;
    const int lane = tid & 31, wid = tid >> 5;
    const int warp_m = wid >> 2, warp_n = wid & 3;
    const int bm = blockIdx.y * 128, bn = blockIdx.x * 128;

    int sA[4], sB[4], gAr[4], gAc[4], gBr[4], gBc[4];
#pragma unroll
    for (int j = 0; j < 4; j++) {
        const int f = tid + j * 256;          // 0..1023
        const int ar = f >> 3, ac = f & 7;
        sA[j] = (ar * 8 + (ac ^ (ar & 7))) * 16;
        gAr[j] = ar; gAc[j] = ac * 8;
        const int br = f >> 4, bg = f & 15;
        sB[j] = (br * 16 + ((bg & 8) | ((bg & 7) ^ (br & 7)))) * 16;
        gBr[j] = br; gBc[j] = bg * 8;
    }

    const int arow_l = warp_m * 64 + (lane & 15);
    const int aghalf = (lane >> 4) & 1;
    int aOff[4][4];
#pragma unroll
    for (int mi = 0; mi < 4; mi++) {
        const int row = arow_l + mi * 16;
        const int rsw = row & 7;
#pragma unroll
        for (int kx = 0; kx < 4; kx++) {
            const int c = kx * 2 + aghalf;
            aOff[mi][kx] = (row * 8 + (c ^ rsw)) * 16;
        }
    }
    const int bk_l = (lane & 7) + ((lane >> 3) & 1) * 8;
    const int gadd = lane >> 4;
    const int klow = bk_l & 7;
    int bOff[4][2];
#pragma unroll
    for (int kx = 0; kx < 4; kx++) {
        const int k = kx * 16 + bk_l;
#pragma unroll
        for (int np = 0; np < 2; np++) {
            const int g = warp_n * 4 + np * 2 + gadd;
            bOff[kx][np] = (k * 16 + ((g & 8) | ((g & 7) ^ klow))) * 16;
        }
    }

    float acc[4][4][4];
#pragma unroll
    for (int mi = 0; mi < 4; mi++)
#pragma unroll
        for (int ni = 0; ni < 4; ni++)
#pragma unroll
            for (int r = 0; r < 4; r++) acc[mi][ni][r] = 0.f;

    auto issue = [&](int stage, int k0) {
        const unsigned st = sbase + stage * STAGE_BYTES;
#pragma unroll
        for (int j = 0; j < 4; j++) {
            const size_t aoff = (size_t)(bm + gAr[j]) * K + k0 + gAc[j];
            const size_t boff = (size_t)(k0 + gBr[j]) * N + bn + gBc[j];
            cp16(st + sA[j],         Am + aoff);
            cp16(st + 16384 + sB[j], Bm + boff);
        }
        asm volatile("cp.async.commit_group;");
    };

    issue(0, 0);
    issue(1, KSTEP);

    for (int it = 0; it < NITER; it++) {
        asm volatile("cp.async.wait_group 1;");
        __syncthreads();
        const unsigned st = sbase + (it & 1) * STAGE_BYTES;
#pragma unroll
        for (int kx = 0; kx < 4; kx++) {
            uint4 Af[4], Bf[2];
#pragma unroll
            for (int mi = 0; mi < 4; mi++)
                ldsm_x4(Af[mi], st + aOff[mi][kx]);
#pragma unroll
            for (int np = 0; np < 2; np++)
                ldsm_x4t(Bf[np], st + 16384 + bOff[kx][np]);
#pragma unroll
            for (int mi = 0; mi < 4; mi++)
#pragma unroll
                for (int ni = 0; ni < 4; ni++) {
                    const int np = ni >> 1;
                    const unsigned b0 = (ni & 1) ? Bf[np].z : Bf[np].x;
                    const unsigned b1 = (ni & 1) ? Bf[np].w : Bf[np].y;
                    mma_fp16(acc[mi][ni], Af[mi], b0, b1);
                }
        }
        __syncthreads();
        if (it + 2 < NITER) issue(it & 1, (it + 2) * KSTEP);
        else asm volatile("cp.async.commit_group;");
    }

    const int rbase = bm + warp_m * 64 + (lane >> 2);
    const int cbase = bn + warp_n * 32 + (lane & 3) * 2;
#pragma unroll
    for (int ni = 0; ni < 4; ni++) {
        const int c = cbase + ni * 8;
        if (MODE == 2) {
#pragma unroll
            for (int mi = 0; mi < 4; mi++) {
#pragma unroll
                for (int half = 0; half < 2; half++) {
                    const int r = rbase + mi * 16 + half * 8;
                    *(float2*)&Cout[(size_t)r * N + c] =
                        make_float2(acc[mi][ni][half * 2], acc[mi][ni][half * 2 + 1]);
                }
            }
        } else {
            const int seg = c >> 10;
            const int cc = c & 1023;
            const int h = cc >> 6, d0 = cc & 63;
            float* dstb = (seg == 0) ? g_q : (seg == 1) ? g_k : g_v;
#pragma unroll
            for (int mi = 0; mi < 4; mi++) {
#pragma unroll
                for (int half = 0; half < 2; half++) {
                    const int r = rbase + mi * 16 + half * 8;
                    const int b = r >> 11, t = r & 2047;
                    float v0 = acc[mi][ni][half * 2], v1 = acc[mi][ni][half * 2 + 1];
                    if (seg < 2) {
                        v0 = (v0 > 0.f) ? (v0 + 1.f) : expf(v0);
                        v1 = (v1 > 0.f) ? (v1 + 1.f) : expf(v1);
                    }
                    const size_t idx = ((size_t)(b * Hq + h) * Tq + t) * Dq + d0;
                    *(float2*)&dstb[idx] = make_float2(v0, v1);
                }
            }
        }
    }
}

// ---------------- per-chunk K^T V sums + k sums (single-stage smem) ----------
#define CS_BYTES (2 * LCHUNK * Dq * 4)    // 65536

__global__ __launch_bounds__(256)
void chunk_sums_kernel()
{
    extern __shared__ float csm[];
    float* ks = csm;                       // [128][64]
    float* vs = csm + LCHUNK * Dq;         // [128][64]

    const int c  = blockIdx.x;
    const int bh = blockIdx.y;
    const int tid = threadIdx.x;
    const int i0 = (tid >> 4) << 2;
    const int j0 = (tid & 15) << 2;
    const bool zowner = ((tid & 15) == 0);

    const float* kb = g_k + ((size_t)bh * Tq + c * LCHUNK) * Dq;
    const float* vb = g_v + ((size_t)bh * Tq + c * LCHUNK) * Dq;

#pragma unroll
    for (int j = 0; j < 8; j++) {
        const int f = tid + j * 256;       // 0..2047 float4s
        *(float4*)&ks[f * 4] = *(const float4*)(kb + (size_t)f * 4);
        *(float4*)&vs[f * 4] = *(const float4*)(vb + (size_t)f * 4);
    }
    __syncthreads();

    float s[4][4];
#pragma unroll
    for (int a = 0; a < 4; a++)
#pragma unroll
        for (int b = 0; b < 4; b++) s[a][b] = 0.f;
    float z[4] = {0.f, 0.f, 0.f, 0.f};

#pragma unroll 8
    for (int tt = 0; tt < LCHUNK; tt++) {
        float kr[4], vr[4];
        *(float4*)kr = *(const float4*)&ks[tt * 64 + i0];
        *(float4*)vr = *(const float4*)&vs[tt * 64 + j0];
#pragma unroll
        for (int a = 0; a < 4; a++)
#pragma unroll
            for (int b = 0; b < 4; b++)
                s[a][b] = fmaf(kr[a], vr[b], s[a][b]);
        if (zowner) {
#pragma unroll
            for (int a = 0; a < 4; a++) z[a] += kr[a];
        }
    }

    float* Sp = g_Sc + ((size_t)bh * NCHUNK + c) * (Dq * Dq);
#pragma unroll
    for (int a = 0; a < 4; a++)
        *(float4*)&Sp[(i0 + a) * Dq + j0] = make_float4(s[a][0], s[a][1], s[a][2], s[a][3]);
    if (zowner) {
        float* zp = g_zc + ((size_t)bh * NCHUNK + c) * Dq;
#pragma unroll
        for (int a = 0; a < 4; a++) zp[i0 + a] = z[a];
    }
}

// ---------------- exclusive scan over chunks (element-parallel) --------------
__global__ __launch_bounds__(256)
void scan_kernel()
{
    const int bh = blockIdx.x;
    const int e4 = blockIdx.y * 256 + threadIdx.x;    // 0..1023 float4 groups
    const size_t base = (size_t)bh * NCHUNK * (Dq * Dq) + (size_t)e4 * 4;

    float4 run = make_float4(0.f, 0.f, 0.f, 0.f);
#pragma unroll
    for (int c = 0; c < NCHUNK; c++) {
        const size_t off = base + (size_t)c * (Dq * Dq);
        float4 sc = *(const float4*)&g_Sc[off];
        *(float4*)&g_Sp[off] = run;
        run.x += sc.x; run.y += sc.y; run.z += sc.z; run.w += sc.w;
    }

    if (blockIdx.y == 0 && threadIdx.x < Dq) {
        const size_t zb = (size_t)bh * NCHUNK * Dq + threadIdx.x;
        float zrun = 0.f;
#pragma unroll
        for (int c = 0; c < NCHUNK; c++) {
            const size_t off = zb + (size_t)c * Dq;
            float zc = g_zc[off];
            g_zp[off] = zrun;
            zrun += zc;
        }
    }
}

// ---------------- per-chunk attention: fp16 MMA version ----------------------
#define AK_QH 0
#define AK_QL 8192
#define AK_KS 16384
#define AK_VS 32768
#define AK_AS 49152
#define AK_SS 65536
#define AK_ZS 73728
#define AK_DN 73984
#define AK_BYTES 74240

__global__ __launch_bounds__(256)
void attn_kernel()
{
    extern __shared__ char smc[];
    const unsigned sb = (unsigned)__cvta_generic_to_shared(smc);
    float* zs   = (float*)(smc + AK_ZS);
    float* dens = (float*)(smc + AK_DN);

    const int c    = blockIdx.x >> 1;
    const int half = blockIdx.x & 1;
    const int bh   = blockIdx.y;
    const int tid  = threadIdx.x;
    const int lane = tid & 31, wid = tid >> 5;
    const int warp_m = wid >> 2, warp_n = wid & 3;   // 2 x 4
    const int r0   = half << 6;
    const int kvrows = half ? 128 : 64;              // K/V rows needed
    const size_t coff = ((size_t)bh * Tq + c * LCHUNK) * Dq;
    const size_t qoff = coff + (size_t)r0 * Dq;
    const size_t soff = ((size_t)bh * NCHUNK + c) * (Dq * Dq);

    // ---- load/convert phase --------------------------------------------------
#pragma unroll
    for (int j = 0; j < 2; j++) {
        const int gi = tid + j * 256, row = gi >> 3, g = gi & 7;
        const float* s = g_q + qoff + row * 64 + g * 8;
        float4 f0 = *(const float4*)s, f1 = *(const float4*)(s + 4);
        float fs[8] = {f0.x, f0.y, f0.z, f0.w, f1.x, f1.y, f1.z, f1.w};
        unsigned hw[4], lw[4];
#pragma unroll
        for (int p = 0; p < 4; p++) {
            __half ha = __float2half(fs[2*p]), hb = __float2half(fs[2*p+1]);
            float la = fs[2*p] - __half2float(ha);
            float lb = fs[2*p+1] - __half2float(hb);
            hw[p] = ((unsigned)__half_as_ushort(hb) << 16) | __half_as_ushort(ha);
            lw[p] = pack2h(la, lb);
        }
        const unsigned off = row * 128 + ((g ^ (row & 7)) * 16);
        *(uint4*)(smc + AK_QH + off) = make_uint4(hw[0], hw[1], hw[2], hw[3]);
        *(uint4*)(smc + AK_QL + off) = make_uint4(lw[0], lw[1], lw[2], lw[3]);
    }
#pragma unroll
    for (int j = 0; j < 4; j++) {
        const int gi = tid + j * 256, row = gi >> 3, g = gi & 7;
        if (row < kvrows) {
            const float* s = g_k + coff + row * 64 + g * 8;
            float4 f0 = *(const float4*)s, f1 = *(const float4*)(s + 4);
            unsigned hw0 = pack2h(f0.x, f0.y), hw1 = pack2h(f0.z, f0.w);
            unsigned hw2 = pack2h(f1.x, f1.y), hw3 = pack2h(f1.z, f1.w);
            *(uint4*)(smc + AK_KS + row * 128 + ((g ^ (row & 7)) * 16)) =
                make_uint4(hw0, hw1, hw2, hw3);
        }
    }
#pragma unroll
    for (int j = 0; j < 4; j++) {
        const int gi = tid + j * 256, row = gi >> 3, g = gi & 7;
        if (row < kvrows) {
            const float* s = g_v + coff + row * 64 + g * 8;
            float4 f0 = *(const float4*)s, f1 = *(const float4*)(s + 4);
            unsigned hw0 = pack2h(f0.x, f0.y), hw1 = pack2h(f0.z, f0.w);
            unsigned hw2 = pack2h(f1.x, f1.y), hw3 = pack2h(f1.z, f1.w);
            *(uint4*)(smc + AK_VS + row * 128 + ((g ^ (row & 7)) * 16)) =
                make_uint4(hw0, hw1, hw2, hw3);
        }
    }
#pragma unroll
    for (int j = 0; j < 2; j++) {
        const int gi = tid + j * 256, row = gi >> 3, g = gi & 7;
        const float* s = g_Sp + soff + row * 64 + g * 8;
        float4 f0 = *(const float4*)s, f1 = *(const float4*)(s + 4);
        unsigned hw0 = pack2h(f0.x, f0.y), hw1 = pack2h(f0.z, f0.w);
        unsigned hw2 = pack2h(f1.x, f1.y), hw3 = pack2h(f1.z, f1.w);
        *(uint4*)(smc + AK_SS + row * 128 + ((g ^ (row & 7)) * 16)) =
            make_uint4(hw0, hw1, hw2, hw3);
    }
    if (tid < Dq) {
        zs[tid] = g_zp[((size_t)bh * NCHUNK + c) * Dq + tid];
        dens[tid] = EPSq;
    }
    __syncthreads();

    // ---- dens init: eps + q . z ----------------------------------------------
    {
        const int row = tid >> 2, part = tid & 3;
        float s = 0.f;
#pragma unroll
        for (int d = part * 16; d < part * 16 + 16; d++) {
            const unsigned off = row * 128 + (((d >> 3) ^ (row & 7)) * 16) + (d & 7) * 2;
            float qv = __half2float(*(__half*)(smc + AK_QH + off))
                     + __half2float(*(__half*)(smc + AK_QL + off));
            s += qv * zs[d];
        }
        atomicAdd(&dens[row], s);
    }

    // ---- stage 1: A = Q @ K^T (half-0: only s<64 -> warp_n<2) ----------------
    const int lrow = lane & 15, lhalf = lane >> 4;
    if (half || warp_n < 2) {
        float acc[2][4][4];
#pragma unroll
        for (int mi = 0; mi < 2; mi++)
#pragma unroll
            for (int ni = 0; ni < 4; ni++)
#pragma unroll
                for (int r = 0; r < 4; r++) acc[mi][ni][r] = 0.f;

#pragma unroll
        for (int kx = 0; kx < 4; kx++) {
            uint4 Ahf[2], Alf[2], Bs2[2];
#pragma unroll
            for (int mi = 0; mi < 2; mi++) {
                const int row = warp_m * 32 + mi * 16 + lrow;
                const unsigned ga = (unsigned)((kx * 2 + lhalf) ^ (row & 7));
                ldsm_x4(Ahf[mi], sb + AK_QH + row * 128 + ga * 16);
                ldsm_x4(Alf[mi], sb + AK_QL + row * 128 + ga * 16);
            }
#pragma unroll
            for (int jn = 0; jn < 2; jn++) {
                const int srow = warp_n * 32 + jn * 16 + lrow;
                const unsigned gb = (unsigned)((kx * 2 + lhalf) ^ (srow & 7));
                ldsm_x4(Bs2[jn], sb + AK_KS + srow * 128 + gb * 16);
            }
#pragma unroll
            for (int mi = 0; mi < 2; mi++)
#pragma unroll
                for (int ni = 0; ni < 4; ni++) {
                    const int jn = ni >> 1;
                    const unsigned b0 = (ni & 1) ? Bs2[jn].y : Bs2[jn].x;
                    const unsigned b1 = (ni & 1) ? Bs2[jn].w : Bs2[jn].z;
                    mma_fp16(acc[mi][ni], Ahf[mi], b0, b1);
                    mma_fp16(acc[mi][ni], Alf[mi], b0, b1);
                }
        }

        // ---- mask + rowsum + store A (fp16) ----------------------------------
#pragma unroll
        for (int mi = 0; mi < 2; mi++) {
            const int ra = warp_m * 32 + mi * 16 + (lane >> 2);
            const int rb = ra + 8;
            float rs0 = 0.f, rs1 = 0.f;
#pragma unroll
            for (int ni = 0; ni < 4; ni++) {
                const int c0 = warp_n * 32 + ni * 8 + (lane & 3) * 2;
                const float v0 = (c0     <= r0 + ra) ? acc[mi][ni][0] : 0.f;
                const float v1 = (c0 + 1 <= r0 + ra) ? acc[mi][ni][1] : 0.f;
                const float v2 = (c0     <= r0 + rb) ? acc[mi][ni][2] : 0.f;
                const float v3 = (c0 + 1 <= r0 + rb) ? acc[mi][ni][3] : 0.f;
                rs0 += v0 + v1; rs1 += v2 + v3;
                const unsigned g = (unsigned)(c0 >> 3), go = (unsigned)((c0 & 7) * 2);
                const unsigned sw0 = (g & 8) | ((g & 7) ^ (ra & 7));
                const unsigned sw1 = (g & 8) | ((g & 7) ^ (rb & 7));
                *(unsigned*)(smc + AK_AS + ra * 256 + sw0 * 16 + go) = pack2h(v0, v1);
                *(unsigned*)(smc + AK_AS + rb * 256 + sw1 * 16 + go) = pack2h(v2, v3);
            }
            atomicAdd(&dens[ra], rs0);
            atomicAdd(&dens[rb], rs1);
        }
    }
    __syncthreads();

    // ---- stage 2: y = A @ V + Q @ S ------------------------------------------
    const int bk_l = (lane & 7) + ((lane >> 3) & 1) * 8;
    float a2[2][2][4];
#pragma unroll
    for (int mi = 0; mi < 2; mi++)
#pragma unroll
        for (int ni = 0; ni < 2; ni++)
#pragma unroll
            for (int r = 0; r < 4; r++) a2[mi][ni][r] = 0.f;

    const int kxend = half ? 8 : 4;
#pragma unroll
    for (int kx = 0; kx < 8; kx++) {
        if (kx >= kxend) break;
        uint4 Af[2], Bv;
#pragma unroll
        for (int mi = 0; mi < 2; mi++) {
            const int row = warp_m * 32 + mi * 16 + lrow;
            const unsigned g = (unsigned)(kx * 2 + lhalf);
            const unsigned gs = (g & 8) | ((g & 7) ^ (row & 7));
            ldsm_x4(Af[mi], sb + AK_AS + row * 256 + gs * 16);
        }
        const int srow = kx * 16 + bk_l;
        const unsigned gv = (unsigned)((warp_n * 2 + lhalf) ^ (srow & 7));
        ldsm_x4t(Bv, sb + AK_VS + srow * 128 + gv * 16);
#pragma unroll
        for (int mi = 0; mi < 2; mi++)
#pragma unroll
            for (int ni = 0; ni < 2; ni++) {
                const unsigned b0 = ni ? Bv.z : Bv.x;
                const unsigned b1 = ni ? Bv.w : Bv.y;
                mma_fp16(a2[mi][ni], Af[mi], b0, b1);
            }
    }
#pragma unroll
    for (int kx = 0; kx < 4; kx++) {
        uint4 Qhf[2], Qlf[2], Bss;
#pragma unroll
        for (int mi = 0; mi < 2; mi++) {
            const int row = warp_m * 32 + mi * 16 + lrow;
            const unsigned ga = (unsigned)((kx * 2 + lhalf) ^ (row & 7));
            ldsm_x4(Qhf[mi], sb + AK_QH + row * 128 + ga * 16);
            ldsm_x4(Qlf[mi], sb + AK_QL + row * 128 + ga * 16);
        }
        const int srow = kx * 16 + bk_l;
        const unsigned gs2 = (unsigned)((warp_n * 2 + lhalf) ^ (srow & 7));
        ldsm_x4t(Bss, sb + AK_SS + srow * 128 + gs2 * 16);
#pragma unroll
        for (int mi = 0; mi < 2; mi++)
#pragma unroll
            for (int ni = 0; ni < 2; ni++) {
                const unsigned b0 = ni ? Bss.z : Bss.x;
                const unsigned b1 = ni ? Bss.w : Bss.y;
                mma_fp16(a2[mi][ni], Qhf[mi], b0, b1);
                mma_fp16(a2[mi][ni], Qlf[mi], b0, b1);
            }
    }

    // ---- epilogue: divide by dens, store single fp16 -------------------------
    const int b = bh >> 4, h = bh & 15;
#pragma unroll
    for (int mi = 0; mi < 2; mi++) {
#pragma unroll
        for (int ni = 0; ni < 2; ni++) {
            const int col = warp_n * 16 + ni * 8 + (lane & 3) * 2;
#pragma unroll
            for (int hf = 0; hf < 2; hf++) {
                const int rl = warp_m * 32 + mi * 16 + (lane >> 2) + hf * 8;
                const float inv = 1.0f / dens[rl];
                const float o0 = a2[mi][ni][hf * 2] * inv;
                const float o1 = a2[mi][ni][hf * 2 + 1] * inv;
                const size_t row_g = (size_t)b * Tq + c * LCHUNK + r0 + rl;
                const size_t idx = row_g * Cq + h * 64 + col;
                *(unsigned*)&g_yf[idx] = pack2h(o0, o1);
            }
        }
    }
}

// ---------------- launch -----------------------------------------------------
extern "C" void kernel_launch(void* const* d_in, const int* in_sizes, int n_in,
                              void* d_out, int out_size)
{
    const float* x      = (const float*)d_in[0];
    const float* w_attn = (const float*)d_in[1];
    const float* w_proj = (const float*)d_in[2];
    float* out = (float*)d_out;

    cudaFuncSetAttribute(attn_kernel, cudaFuncAttributeMaxDynamicSharedMemorySize, AK_BYTES);
    cudaFuncSetAttribute(chunk_sums_kernel, cudaFuncAttributeMaxDynamicSharedMemorySize, CS_BYTES);
    cudaFuncSetAttribute(mma_gemm<1>, cudaFuncAttributeMaxDynamicSharedMemorySize, GEMM_SMEM);
    cudaFuncSetAttribute(mma_gemm<2>, cudaFuncAttributeMaxDynamicSharedMemorySize, GEMM_SMEM);

    __half *xf, *wa, *wp, *yf;
    cudaGetSymbolAddress((void**)&xf, g_xf);
    cudaGetSymbolAddress((void**)&wa, g_wa);
    cudaGetSymbolAddress((void**)&wp, g_wp);
    cudaGetSymbolAddress((void**)&yf, g_yf);

    prep_kernel<<<N4_TOTAL / 256, 256>>>(x, w_attn, w_proj);

    mma_gemm<1><<<dim3(3 * Cq / 128, Mrows / 128), 256, GEMM_SMEM>>>(
        xf, wa, nullptr, 3 * Cq);
    chunk_sums_kernel<<<dim3(NCHUNK, BHq), 256, CS_BYTES>>>();
    scan_kernel<<<dim3(BHq, 4), 256>>>();
    attn_kernel<<<dim3(2 * NCHUNK, BHq), 256, AK_BYTES>>>();
    mma_gemm<2><<<dim3(Cq / 128, Mrows / 128), 256, GEMM_SMEM>>>(
        yf, wp, out, Cq);
}

// round 17
// speedup vs baseline: 3.6201x; 1.0500x over previous
#include <cuda_runtime.h>
#include <cuda_fp16.h>
#include <cuda_bf16.h>
#include <math.h>

// Problem constants
#define Bq 2
#define Tq 2048
#define Cq 1024
#define Hq 16
#define Dq 64
#define NCHUNK 16
#define LCHUNK 128
#define BHq (Bq * Hq)       // 32
#define Mrows (Bq * Tq)     // 4096
#define EPSq 1e-6f

// ---------------- scratch (device globals: no allocs allowed) ----------------
__device__ float g_q[(size_t)BHq * Tq * Dq];
__device__ float g_k[(size_t)BHq * Tq * Dq];
__device__ float g_v[(size_t)BHq * Tq * Dq];
__device__ float g_Sc[(size_t)BHq * NCHUNK * Dq * Dq];
__device__ float g_Sp[(size_t)BHq * NCHUNK * Dq * Dq];
__device__ float g_zc[(size_t)BHq * NCHUNK * Dq];
__device__ float g_zp[(size_t)BHq * NCHUNK * Dq];

// fp16 buffers (single precision fp16 operands; fp32 accumulate in MMA).
__device__ __align__(16) __half g_xf[(size_t)Mrows * Cq];
__device__ __align__(16) __half g_wa[(size_t)Cq * 3 * Cq];
__device__ __align__(16) __half g_wp[(size_t)Cq * Cq];
__device__ __align__(16) __half g_yf[(size_t)Mrows * Cq];

// ---------------- fused prep: fp32 -> fp16 casts ------------------------------
#define N4_X  (Mrows * Cq / 4)            // 1048576
#define N4_WA (Cq * 3 * Cq / 4)           // 786432
#define N4_WP (Cq * Cq / 4)               // 262144
#define N4_TOTAL (N4_X + N4_WA + N4_WP)   // 2097152

__global__ __launch_bounds__(256)
void prep_kernel(const float* __restrict__ x, const float* __restrict__ wa,
                 const float* __restrict__ wp)
{
    const int i = blockIdx.x * 256 + threadIdx.x;
    const float4* src;
    __half* dst;
    int j;
    if (i < N4_X) { src = (const float4*)x; dst = g_xf; j = i; }
    else if (i < N4_X + N4_WA) { src = (const float4*)wa; dst = g_wa; j = i - N4_X; }
    else if (i < N4_TOTAL) { src = (const float4*)wp; dst = g_wp; j = i - N4_X - N4_WA; }
    else return;
    float4 v = src[j];
    __half h0 = __float2half(v.x), h1 = __float2half(v.y);
    __half h2 = __float2half(v.z), h3 = __float2half(v.w);
    uint2 uh;
    uh.x = ((unsigned)__half_as_ushort(h1) << 16) | __half_as_ushort(h0);
    uh.y = ((unsigned)__half_as_ushort(h3) << 16) | __half_as_ushort(h2);
    ((uint2*)dst)[j] = uh;
}

// ---------------- MMA helpers ------------------------------------------------
__device__ __forceinline__ void ldsm_x4(uint4& r, unsigned addr) {
    asm volatile("ldmatrix.sync.aligned.m8n8.x4.shared.b16 {%0,%1,%2,%3}, [%4];"
                 : "=r"(r.x), "=r"(r.y), "=r"(r.z), "=r"(r.w) : "r"(addr));
}
__device__ __forceinline__ void ldsm_x4t(uint4& r, unsigned addr) {
    asm volatile("ldmatrix.sync.aligned.m8n8.x4.trans.shared.b16 {%0,%1,%2,%3}, [%4];"
                 : "=r"(r.x), "=r"(r.y), "=r"(r.z), "=r"(r.w) : "r"(addr));
}
__device__ __forceinline__ void mma_fp16(float c[4], const uint4& a, unsigned b0, unsigned b1) {
    asm volatile("mma.sync.aligned.m16n8k16.row.col.f32.f16.f16.f32 "
                 "{%0,%1,%2,%3},{%4,%5,%6,%7},{%8,%9},{%0,%1,%2,%3};"
                 : "+f"(c[0]), "+f"(c[1]), "+f"(c[2]), "+f"(c[3])
                 : "r"(a.x), "r"(a.y), "r"(a.z), "r"(a.w), "r"(b0), "r"(b1));
}
__device__ __forceinline__ void cp16(unsigned s, const void* g) {
    asm volatile("cp.async.cg.shared.global [%0], [%1], 16;\n" :: "r"(s), "l"(g));
}
__device__ __forceinline__ unsigned pack2h(float a, float b) {
    return ((unsigned)__half_as_ushort(__float2half(b)) << 16)
         | (unsigned)__half_as_ushort(__float2half(a));
}

// ---------------- fp16 tensor-core GEMM, K-step 64, 3-stage unrolled ---------
#define STAGE_BYTES 32768
#define GEMM_SMEM   (3 * STAGE_BYTES)

template <int MODE>
__global__ __launch_bounds__(256, 2)
void mma_gemm(const __half* __restrict__ Am, const __half* __restrict__ Bm,
              float* __restrict__ Cout, int N)
{
    constexpr int K = 1024;
    constexpr int KSTEP = 64;
    constexpr int NITER = K / KSTEP;     // 16
    extern __shared__ char smem[];
    const unsigned sbase = (unsigned)__cvta_generic_to_shared(smem);

    const int tid = threadIdx.x;
    const int lane = tid & 31, wid = tid >> 5;
    const int warp_m = wid >> 2, warp_n = wid & 3;
    const int bm = blockIdx.y * 128, bn = blockIdx.x * 128;

    int sA[4], sB[4], gAr[4], gAc[4], gBr[4], gBc[4];
#pragma unroll
    for (int j = 0; j < 4; j++) {
        const int f = tid + j * 256;          // 0..1023
        const int ar = f >> 3, ac = f & 7;
        sA[j] = (ar * 8 + (ac ^ (ar & 7))) * 16;
        gAr[j] = ar; gAc[j] = ac * 8;
        const int br = f >> 4, bg = f & 15;
        sB[j] = (br * 16 + ((bg & 8) | ((bg & 7) ^ (br & 7)))) * 16;
        gBr[j] = br; gBc[j] = bg * 8;
    }

    const int arow_l = warp_m * 64 + (lane & 15);
    const int aghalf = (lane >> 4) & 1;
    int aOff[4][4];
#pragma unroll
    for (int mi = 0; mi < 4; mi++) {
        const int row = arow_l + mi * 16;
        const int rsw = row & 7;
#pragma unroll
        for (int kx = 0; kx < 4; kx++) {
            const int c = kx * 2 + aghalf;
            aOff[mi][kx] = (row * 8 + (c ^ rsw)) * 16;
        }
    }
    const int bk_l = (lane & 7) + ((lane >> 3) & 1) * 8;
    const int gadd = lane >> 4;
    const int klow = bk_l & 7;
    int bOff[4][2];
#pragma unroll
    for (int kx = 0; kx < 4; kx++) {
        const int k = kx * 16 + bk_l;
#pragma unroll
        for (int np = 0; np < 2; np++) {
            const int g = warp_n * 4 + np * 2 + gadd;
            bOff[kx][np] = (k * 16 + ((g & 8) | ((g & 7) ^ klow))) * 16;
        }
    }

    float acc[4][4][4];
#pragma unroll
    for (int mi = 0; mi < 4; mi++)
#pragma unroll
        for (int ni = 0; ni < 4; ni++)
#pragma unroll
            for (int r = 0; r < 4; r++) acc[mi][ni][r] = 0.f;

    auto issue = [&](int stage, int k0) {
        const unsigned st = sbase + stage * STAGE_BYTES;
#pragma unroll
        for (int j = 0; j < 4; j++) {
            const size_t aoff = (size_t)(bm + gAr[j]) * K + k0 + gAc[j];
            const size_t boff = (size_t)(k0 + gBr[j]) * N + bn + gBc[j];
            cp16(st + sA[j],         Am + aoff);
            cp16(st + 16384 + sB[j], Bm + boff);
        }
        asm volatile("cp.async.commit_group;");
    };

    issue(0, 0);
    issue(1, KSTEP);

#pragma unroll
    for (int it = 0; it < NITER; it++) {
        asm volatile("cp.async.wait_group 1;");
        __syncthreads();
        if (it + 2 < NITER) issue((it + 2) % 3, (it + 2) * KSTEP);
        else asm volatile("cp.async.commit_group;");
        const unsigned st = sbase + (it % 3) * STAGE_BYTES;
#pragma unroll
        for (int kx = 0; kx < 4; kx++) {
            uint4 Af[4], Bf[2];
#pragma unroll
            for (int mi = 0; mi < 4; mi++)
                ldsm_x4(Af[mi], st + aOff[mi][kx]);
#pragma unroll
            for (int np = 0; np < 2; np++)
                ldsm_x4t(Bf[np], st + 16384 + bOff[kx][np]);
#pragma unroll
            for (int mi = 0; mi < 4; mi++)
#pragma unroll
                for (int ni = 0; ni < 4; ni++) {
                    const int np = ni >> 1;
                    const unsigned b0 = (ni & 1) ? Bf[np].z : Bf[np].x;
                    const unsigned b1 = (ni & 1) ? Bf[np].w : Bf[np].y;
                    mma_fp16(acc[mi][ni], Af[mi], b0, b1);
                }
        }
    }

    const int rbase = bm + warp_m * 64 + (lane >> 2);
    const int cbase = bn + warp_n * 32 + (lane & 3) * 2;
#pragma unroll
    for (int ni = 0; ni < 4; ni++) {
        const int c = cbase + ni * 8;
        if (MODE == 2) {
#pragma unroll
            for (int mi = 0; mi < 4; mi++) {
#pragma unroll
                for (int half = 0; half < 2; half++) {
                    const int r = rbase + mi * 16 + half * 8;
                    *(float2*)&Cout[(size_t)r * N + c] =
                        make_float2(acc[mi][ni][half * 2], acc[mi][ni][half * 2 + 1]);
                }
            }
        } else {
            const int seg = c >> 10;
            const int cc = c & 1023;
            const int h = cc >> 6, d0 = cc & 63;
            float* dstb = (seg == 0) ? g_q : (seg == 1) ? g_k : g_v;
#pragma unroll
            for (int mi = 0; mi < 4; mi++) {
#pragma unroll
                for (int half = 0; half < 2; half++) {
                    const int r = rbase + mi * 16 + half * 8;
                    const int b = r >> 11, t = r & 2047;
                    float v0 = acc[mi][ni][half * 2], v1 = acc[mi][ni][half * 2 + 1];
                    if (seg < 2) {
                        v0 = (v0 > 0.f) ? (v0 + 1.f) : expf(v0);
                        v1 = (v1 > 0.f) ? (v1 + 1.f) : expf(v1);
                    }
                    const size_t idx = ((size_t)(b * Hq + h) * Tq + t) * Dq + d0;
                    *(float2*)&dstb[idx] = make_float2(v0, v1);
                }
            }
        }
    }
}

// ---------------- per-chunk K^T V sums + k sums (single-stage smem) ----------
#define CS_BYTES (2 * LCHUNK * Dq * 4)    // 65536

__global__ __launch_bounds__(256)
void chunk_sums_kernel()
{
    extern __shared__ float csm[];
    float* ks = csm;                       // [128][64]
    float* vs = csm + LCHUNK * Dq;         // [128][64]

    const int c  = blockIdx.x;
    const int bh = blockIdx.y;
    const int tid = threadIdx.x;
    const int i0 = (tid >> 4) << 2;
    const int j0 = (tid & 15) << 2;
    const bool zowner = ((tid & 15) == 0);

    const float* kb = g_k + ((size_t)bh * Tq + c * LCHUNK) * Dq;
    const float* vb = g_v + ((size_t)bh * Tq + c * LCHUNK) * Dq;

#pragma unroll
    for (int j = 0; j < 8; j++) {
        const int f = tid + j * 256;       // 0..2047 float4s
        *(float4*)&ks[f * 4] = *(const float4*)(kb + (size_t)f * 4);
        *(float4*)&vs[f * 4] = *(const float4*)(vb + (size_t)f * 4);
    }
    __syncthreads();

    float s[4][4];
#pragma unroll
    for (int a = 0; a < 4; a++)
#pragma unroll
        for (int b = 0; b < 4; b++) s[a][b] = 0.f;
    float z[4] = {0.f, 0.f, 0.f, 0.f};

#pragma unroll 8
    for (int tt = 0; tt < LCHUNK; tt++) {
        float kr[4], vr[4];
        *(float4*)kr = *(const float4*)&ks[tt * 64 + i0];
        *(float4*)vr = *(const float4*)&vs[tt * 64 + j0];
#pragma unroll
        for (int a = 0; a < 4; a++)
#pragma unroll
            for (int b = 0; b < 4; b++)
                s[a][b] = fmaf(kr[a], vr[b], s[a][b]);
        if (zowner) {
#pragma unroll
            for (int a = 0; a < 4; a++) z[a] += kr[a];
        }
    }

    float* Sp = g_Sc + ((size_t)bh * NCHUNK + c) * (Dq * Dq);
#pragma unroll
    for (int a = 0; a < 4; a++)
        *(float4*)&Sp[(i0 + a) * Dq + j0] = make_float4(s[a][0], s[a][1], s[a][2], s[a][3]);
    if (zowner) {
        float* zp = g_zc + ((size_t)bh * NCHUNK + c) * Dq;
#pragma unroll
        for (int a = 0; a < 4; a++) zp[i0 + a] = z[a];
    }
}

// ---------------- exclusive scan over chunks (element-parallel, float2) ------
// grid (BHq, 8), 256 threads; each thread owns one float2 of the 64x64 state.
__global__ __launch_bounds__(256)
void scan_kernel()
{
    const int bh = blockIdx.x;
    const int e2 = blockIdx.y * 256 + threadIdx.x;    // 0..2047 float2 groups
    const size_t base = (size_t)bh * NCHUNK * (Dq * Dq) + (size_t)e2 * 2;

    float2 run = make_float2(0.f, 0.f);
#pragma unroll
    for (int c = 0; c < NCHUNK; c++) {
        const size_t off = base + (size_t)c * (Dq * Dq);
        float2 sc = *(const float2*)&g_Sc[off];
        *(float2*)&g_Sp[off] = run;
        run.x += sc.x; run.y += sc.y;
    }

    if (blockIdx.y == 0 && threadIdx.x < Dq) {
        const size_t zb = (size_t)bh * NCHUNK * Dq + threadIdx.x;
        float zrun = 0.f;
#pragma unroll
        for (int c = 0; c < NCHUNK; c++) {
            const size_t off = zb + (size_t)c * Dq;
            float zc = g_zc[off];
            g_zp[off] = zrun;
            zrun += zc;
        }
    }
}

// ---------------- per-chunk attention: fp16 MMA version ----------------------
#define AK_QH 0
#define AK_QL 8192
#define AK_KS 16384
#define AK_VS 32768
#define AK_AS 49152
#define AK_SS 65536
#define AK_ZS 73728
#define AK_DN 73984
#define AK_BYTES 74240

__global__ __launch_bounds__(256)
void attn_kernel()
{
    extern __shared__ char smc[];
    const unsigned sb = (unsigned)__cvta_generic_to_shared(smc);
    float* zs   = (float*)(smc + AK_ZS);
    float* dens = (float*)(smc + AK_DN);

    const int c    = blockIdx.x >> 1;
    const int half = blockIdx.x & 1;
    const int bh   = blockIdx.y;
    const int tid  = threadIdx.x;
    const int lane = tid & 31, wid = tid >> 5;
    const int warp_m = wid >> 2, warp_n = wid & 3;   // 2 x 4
    const int r0   = half << 6;
    const int kvrows = half ? 128 : 64;
    const size_t coff = ((size_t)bh * Tq + c * LCHUNK) * Dq;
    const size_t qoff = coff + (size_t)r0 * Dq;
    const size_t soff = ((size_t)bh * NCHUNK + c) * (Dq * Dq);

#pragma unroll
    for (int j = 0; j < 2; j++) {
        const int gi = tid + j * 256, row = gi >> 3, g = gi & 7;
        const float* s = g_q + qoff + row * 64 + g * 8;
        float4 f0 = *(const float4*)s, f1 = *(const float4*)(s + 4);
        float fs[8] = {f0.x, f0.y, f0.z, f0.w, f1.x, f1.y, f1.z, f1.w};
        unsigned hw[4], lw[4];
#pragma unroll
        for (int p = 0; p < 4; p++) {
            __half ha = __float2half(fs[2*p]), hb = __float2half(fs[2*p+1]);
            float la = fs[2*p] - __half2float(ha);
            float lb = fs[2*p+1] - __half2float(hb);
            hw[p] = ((unsigned)__half_as_ushort(hb) << 16) | __half_as_ushort(ha);
            lw[p] = pack2h(la, lb);
        }
        const unsigned off = row * 128 + ((g ^ (row & 7)) * 16);
        *(uint4*)(smc + AK_QH + off) = make_uint4(hw[0], hw[1], hw[2], hw[3]);
        *(uint4*)(smc + AK_QL + off) = make_uint4(lw[0], lw[1], lw[2], lw[3]);
    }
#pragma unroll
    for (int j = 0; j < 4; j++) {
        const int gi = tid + j * 256, row = gi >> 3, g = gi & 7;
        if (row < kvrows) {
            const float* s = g_k + coff + row * 64 + g * 8;
            float4 f0 = *(const float4*)s, f1 = *(const float4*)(s + 4);
            unsigned hw0 = pack2h(f0.x, f0.y), hw1 = pack2h(f0.z, f0.w);
            unsigned hw2 = pack2h(f1.x, f1.y), hw3 = pack2h(f1.z, f1.w);
            *(uint4*)(smc + AK_KS + row * 128 + ((g ^ (row & 7)) * 16)) =
                make_uint4(hw0, hw1, hw2, hw3);
        }
    }
#pragma unroll
    for (int j = 0; j < 4; j++) {
        const int gi = tid + j * 256, row = gi >> 3, g = gi & 7;
        if (row < kvrows) {
            const float* s = g_v + coff + row * 64 + g * 8;
            float4 f0 = *(const float4*)s, f1 = *(const float4*)(s + 4);
            unsigned hw0 = pack2h(f0.x, f0.y), hw1 = pack2h(f0.z, f0.w);
            unsigned hw2 = pack2h(f1.x, f1.y), hw3 = pack2h(f1.z, f1.w);
            *(uint4*)(smc + AK_VS + row * 128 + ((g ^ (row & 7)) * 16)) =
                make_uint4(hw0, hw1, hw2, hw3);
        }
    }
#pragma unroll
    for (int j = 0; j < 2; j++) {
        const int gi = tid + j * 256, row = gi >> 3, g = gi & 7;
        const float* s = g_Sp + soff + row * 64 + g * 8;
        float4 f0 = *(const float4*)s, f1 = *(const float4*)(s + 4);
        unsigned hw0 = pack2h(f0.x, f0.y), hw1 = pack2h(f0.z, f0.w);
        unsigned hw2 = pack2h(f1.x, f1.y), hw3 = pack2h(f1.z, f1.w);
        *(uint4*)(smc + AK_SS + row * 128 + ((g ^ (row & 7)) * 16)) =
            make_uint4(hw0, hw1, hw2, hw3);
    }
    if (tid < Dq) {
        zs[tid] = g_zp[((size_t)bh * NCHUNK + c) * Dq + tid];
        dens[tid] = EPSq;
    }
    __syncthreads();

    {
        const int row = tid >> 2, part = tid & 3;
        float s = 0.f;
#pragma unroll
        for (int d = part * 16; d < part * 16 + 16; d++) {
            const unsigned off = row * 128 + (((d >> 3) ^ (row & 7)) * 16) + (d & 7) * 2;
            float qv = __half2float(*(__half*)(smc + AK_QH + off))
                     + __half2float(*(__half*)(smc + AK_QL + off));
            s += qv * zs[d];
        }
        atomicAdd(&dens[row], s);
    }

    const int lrow = lane & 15, lhalf = lane >> 4;
    if (half || warp_n < 2) {
        float acc[2][4][4];
#pragma unroll
        for (int mi = 0; mi < 2; mi++)
#pragma unroll
            for (int ni = 0; ni < 4; ni++)
#pragma unroll
                for (int r = 0; r < 4; r++) acc[mi][ni][r] = 0.f;

#pragma unroll
        for (int kx = 0; kx < 4; kx++) {
            uint4 Ahf[2], Alf[2], Bs2[2];
#pragma unroll
            for (int mi = 0; mi < 2; mi++) {
                const int row = warp_m * 32 + mi * 16 + lrow;
                const unsigned ga = (unsigned)((kx * 2 + lhalf) ^ (row & 7));
                ldsm_x4(Ahf[mi], sb + AK_QH + row * 128 + ga * 16);
                ldsm_x4(Alf[mi], sb + AK_QL + row * 128 + ga * 16);
            }
#pragma unroll
            for (int jn = 0; jn < 2; jn++) {
                const int srow = warp_n * 32 + jn * 16 + lrow;
                const unsigned gb = (unsigned)((kx * 2 + lhalf) ^ (srow & 7));
                ldsm_x4(Bs2[jn], sb + AK_KS + srow * 128 + gb * 16);
            }
#pragma unroll
            for (int mi = 0; mi < 2; mi++)
#pragma unroll
                for (int ni = 0; ni < 4; ni++) {
                    const int jn = ni >> 1;
                    const unsigned b0 = (ni & 1) ? Bs2[jn].y : Bs2[jn].x;
                    const unsigned b1 = (ni & 1) ? Bs2[jn].w : Bs2[jn].z;
                    mma_fp16(acc[mi][ni], Ahf[mi], b0, b1);
                    mma_fp16(acc[mi][ni], Alf[mi], b0, b1);
                }
        }

#pragma unroll
        for (int mi = 0; mi < 2; mi++) {
            const int ra = warp_m * 32 + mi * 16 + (lane >> 2);
            const int rb = ra + 8;
            float rs0 = 0.f, rs1 = 0.f;
#pragma unroll
            for (int ni = 0; ni < 4; ni++) {
                const int c0 = warp_n * 32 + ni * 8 + (lane & 3) * 2;
                const float v0 = (c0     <= r0 + ra) ? acc[mi][ni][0] : 0.f;
                const float v1 = (c0 + 1 <= r0 + ra) ? acc[mi][ni][1] : 0.f;
                const float v2 = (c0     <= r0 + rb) ? acc[mi][ni][2] : 0.f;
                const float v3 = (c0 + 1 <= r0 + rb) ? acc[mi][ni][3] : 0.f;
                rs0 += v0 + v1; rs1 += v2 + v3;
                const unsigned g = (unsigned)(c0 >> 3), go = (unsigned)((c0 & 7) * 2);
                const unsigned sw0 = (g & 8) | ((g & 7) ^ (ra & 7));
                const unsigned sw1 = (g & 8) | ((g & 7) ^ (rb & 7));
                *(unsigned*)(smc + AK_AS + ra * 256 + sw0 * 16 + go) = pack2h(v0, v1);
                *(unsigned*)(smc + AK_AS + rb * 256 + sw1 * 16 + go) = pack2h(v2, v3);
            }
            atomicAdd(&dens[ra], rs0);
            atomicAdd(&dens[rb], rs1);
        }
    }
    __syncthreads();

    const int bk_l = (lane & 7) + ((lane >> 3) & 1) * 8;
    float a2[2][2][4];
#pragma unroll
    for (int mi = 0; mi < 2; mi++)
#pragma unroll
        for (int ni = 0; ni < 2; ni++)
#pragma unroll
            for (int r = 0; r < 4; r++) a2[mi][ni][r] = 0.f;

    const int kxend = half ? 8 : 4;
#pragma unroll
    for (int kx = 0; kx < 8; kx++) {
        if (kx >= kxend) break;
        uint4 Af[2], Bv;
#pragma unroll
        for (int mi = 0; mi < 2; mi++) {
            const int row = warp_m * 32 + mi * 16 + lrow;
            const unsigned g = (unsigned)(kx * 2 + lhalf);
            const unsigned gs = (g & 8) | ((g & 7) ^ (row & 7));
            ldsm_x4(Af[mi], sb + AK_AS + row * 256 + gs * 16);
        }
        const int srow = kx * 16 + bk_l;
        const unsigned gv = (unsigned)((warp_n * 2 + lhalf) ^ (srow & 7));
        ldsm_x4t(Bv, sb + AK_VS + srow * 128 + gv * 16);
#pragma unroll
        for (int mi = 0; mi < 2; mi++)
#pragma unroll
            for (int ni = 0; ni < 2; ni++) {
                const unsigned b0 = ni ? Bv.z : Bv.x;
                const unsigned b1 = ni ? Bv.w : Bv.y;
                mma_fp16(a2[mi][ni], Af[mi], b0, b1);
            }
    }
#pragma unroll
    for (int kx = 0; kx < 4; kx++) {
        uint4 Qhf[2], Qlf[2], Bss;
#pragma unroll
        for (int mi = 0; mi < 2; mi++) {
            const int row = warp_m * 32 + mi * 16 + lrow;
            const unsigned ga = (unsigned)((kx * 2 + lhalf) ^ (row & 7));
            ldsm_x4(Qhf[mi], sb + AK_QH + row * 128 + ga * 16);
            ldsm_x4(Qlf[mi], sb + AK_QL + row * 128 + ga * 16);
        }
        const int srow = kx * 16 + bk_l;
        const unsigned gs2 = (unsigned)((warp_n * 2 + lhalf) ^ (srow & 7));
        ldsm_x4t(Bss, sb + AK_SS + srow * 128 + gs2 * 16);
#pragma unroll
        for (int mi = 0; mi < 2; mi++)
#pragma unroll
            for (int ni = 0; ni < 2; ni++) {
                const unsigned b0 = ni ? Bss.z : Bss.x;
                const unsigned b1 = ni ? Bss.w : Bss.y;
                mma_fp16(a2[mi][ni], Qhf[mi], b0, b1);
                mma_fp16(a2[mi][ni], Qlf[mi], b0, b1);
            }
    }

    const int b = bh >> 4, h = bh & 15;
#pragma unroll
    for (int mi = 0; mi < 2; mi++) {
#pragma unroll
        for (int ni = 0; ni < 2; ni++) {
            const int col = warp_n * 16 + ni * 8 + (lane & 3) * 2;
#pragma unroll
            for (int hf = 0; hf < 2; hf++) {
                const int rl = warp_m * 32 + mi * 16 + (lane >> 2) + hf * 8;
                const float inv = 1.0f / dens[rl];
                const float o0 = a2[mi][ni][hf * 2] * inv;
                const float o1 = a2[mi][ni][hf * 2 + 1] * inv;
                const size_t row_g = (size_t)b * Tq + c * LCHUNK + r0 + rl;
                const size_t idx = row_g * Cq + h * 64 + col;
                *(unsigned*)&g_yf[idx] = pack2h(o0, o1);
            }
        }
    }
}

// ---------------- launch -----------------------------------------------------
extern "C" void kernel_launch(void* const* d_in, const int* in_sizes, int n_in,
                              void* d_out, int out_size)
{
    const float* x      = (const float*)d_in[0];
    const float* w_attn = (const float*)d_in[1];
    const float* w_proj = (const float*)d_in[2];
    float* out = (float*)d_out;

    cudaFuncSetAttribute(attn_kernel, cudaFuncAttributeMaxDynamicSharedMemorySize, AK_BYTES);
    cudaFuncSetAttribute(chunk_sums_kernel, cudaFuncAttributeMaxDynamicSharedMemorySize, CS_BYTES);
    cudaFuncSetAttribute(mma_gemm<1>, cudaFuncAttributeMaxDynamicSharedMemorySize, GEMM_SMEM);
    cudaFuncSetAttribute(mma_gemm<2>, cudaFuncAttributeMaxDynamicSharedMemorySize, GEMM_SMEM);

    __half *xf, *wa, *wp, *yf;
    cudaGetSymbolAddress((void**)&xf, g_xf);
    cudaGetSymbolAddress((void**)&wa, g_wa);
    cudaGetSymbolAddress((void**)&wp, g_wp);
    cudaGetSymbolAddress((void**)&yf, g_yf);

    prep_kernel<<<N4_TOTAL / 256, 256>>>(x, w_attn, w_proj);

    mma_gemm<1><<<dim3(3 * Cq / 128, Mrows / 128), 256, GEMM_SMEM>>>(
        xf, wa, nullptr, 3 * Cq);
    chunk_sums_kernel<<<dim3(NCHUNK, BHq), 256, CS_BYTES>>>();
    scan_kernel<<<dim3(BHq, 8), 256>>>();
    attn_kernel<<<dim3(2 * NCHUNK, BHq), 256, AK_BYTES>>>();
    mma_gemm<2><<<dim3(Cq / 128, Mrows / 128), 256, GEMM_SMEM>>>(
        yf, wp, out, Cq);
}